// round 1
// baseline (speedup 1.0000x reference)
#include <cuda_runtime.h>
#include <math.h>

// ---------------- problem dims ----------------
constexpr int B_ = 32, L_ = 512, D_ = 256, H_ = 8, V_ = 4096, KC_ = 128;
constexpr int HD_ = D_ / H_;                 // 32
constexpr int BL_ = B_ * L_;                 // 16384
constexpr long long BLD_ = (long long)BL_ * D_;   // 4194304
constexpr long long BLV_ = (long long)BL_ * V_;   // 67108864

// ---------------- scratch (static device memory; no allocs) ----------------
// layout (floats):
constexpr long long OFF_X     = 0;
constexpr long long OFF_QR    = 1 * BLD_;
constexpr long long OFF_QI    = 2 * BLD_;
constexpr long long OFF_KR    = 3 * BLD_;
constexpr long long OFF_KI    = 4 * BLD_;
constexpr long long OFF_VR    = 5 * BLD_;
constexpr long long OFF_VI    = 6 * BLD_;
constexpr long long OFF_AR    = 7 * BLD_;
constexpr long long OFF_AI    = 8 * BLD_;
constexpr long long OFF_ZR    = 9 * BLD_;
constexpr long long OFF_ZI    = 10 * BLD_;
constexpr long long OFF_GATED = 11 * BLD_;
constexpr long long OFF_Y     = 12 * BLD_;
constexpr long long OFF_DOT   = 13 * BLD_;                      // BL*KC = 2097152
constexpr long long OFF_G     = OFF_DOT + (long long)BL_ * KC_; // 32768
constexpr long long OFF_CG    = OFF_G + (long long)KC_ * D_;    // 8192
constexpr long long OFF_WEV   = OFF_CG + (long long)B_ * D_;    // 65536
constexpr long long OFF_WCT   = OFF_WEV + (long long)D_ * D_;   // 65536
constexpr long long OFF_STK   = OFF_WCT + (long long)D_ * D_;   // 8192
constexpr long long OFF_BM    = OFF_STK + (long long)B_ * D_;   // 1024
constexpr long long OFF_BP    = OFF_BM + 4 * D_;                // 1024
constexpr long long OFF_EN    = OFF_BP + 4 * D_;                // 128
constexpr long long OFF_PART  = OFF_EN + KC_;                   // 16384
constexpr long long SCRATCH_N = OFF_PART + BL_ + 64;

__device__ float d_scratch[SCRATCH_N];
__device__ int   d_idxbuf[BL_];

// ---------------- generic SGEMM: C = SIGN * A(MxK) @ W(NxK)^T (+bias)(+C) ----------------
template<int SIGN, bool ACC, bool BIAS>
__global__ __launch_bounds__(256)
void gemm_nt(const float* __restrict__ A, const float* __restrict__ W,
             const float* __restrict__ bias, float* __restrict__ C,
             int M, int N, int K) {
    __shared__ float As[8][129];
    __shared__ float Ws[8][129];
    const int tid = threadIdx.x;
    const int tx = tid & 15, ty = tid >> 4;
    const int m0 = blockIdx.y * 128, n0 = blockIdx.x * 128;
    const int lm = tid >> 1;   // 0..127
    const int lh = tid & 1;    // which float4 within 8-wide k slab

    float acc[8][8];
#pragma unroll
    for (int i = 0; i < 8; i++)
#pragma unroll
        for (int j = 0; j < 8; j++) acc[i][j] = 0.f;

    for (int k0 = 0; k0 < K; k0 += 8) {
        float4 av = make_float4(0.f, 0.f, 0.f, 0.f);
        float4 wv = make_float4(0.f, 0.f, 0.f, 0.f);
        int gm = m0 + lm;
        if (gm < M) av = *reinterpret_cast<const float4*>(A + (long long)gm * K + k0 + lh * 4);
        int gn = n0 + lm;
        if (gn < N) wv = *reinterpret_cast<const float4*>(W + (long long)gn * K + k0 + lh * 4);
        __syncthreads();
        As[lh * 4 + 0][lm] = av.x; As[lh * 4 + 1][lm] = av.y;
        As[lh * 4 + 2][lm] = av.z; As[lh * 4 + 3][lm] = av.w;
        Ws[lh * 4 + 0][lm] = wv.x; Ws[lh * 4 + 1][lm] = wv.y;
        Ws[lh * 4 + 2][lm] = wv.z; Ws[lh * 4 + 3][lm] = wv.w;
        __syncthreads();
#pragma unroll
        for (int kk = 0; kk < 8; kk++) {
            float ra[8], rw[8];
#pragma unroll
            for (int i = 0; i < 8; i++) ra[i] = As[kk][ty + 16 * i];
#pragma unroll
            for (int j = 0; j < 8; j++) rw[j] = Ws[kk][tx + 16 * j];
#pragma unroll
            for (int i = 0; i < 8; i++)
#pragma unroll
                for (int j = 0; j < 8; j++)
                    acc[i][j] += ra[i] * rw[j];
        }
    }
#pragma unroll
    for (int i = 0; i < 8; i++) {
        int gm = m0 + ty + 16 * i;
        if (gm >= M) continue;
#pragma unroll
        for (int j = 0; j < 8; j++) {
            int gn = n0 + tx + 16 * j;
            if (gn >= N) continue;
            float v = (SIGN > 0) ? acc[i][j] : -acc[i][j];
            if (BIAS) v += bias[gn];
            if (ACC) v += C[(long long)gm * N + gn];
            C[(long long)gm * N + gn] = v;
        }
    }
}

// ---------------- small prep kernels ----------------
__global__ void embed_k(const int* __restrict__ tok, const float* __restrict__ emb,
                        float* __restrict__ x) {
    long long t = (long long)blockIdx.x * blockDim.x + threadIdx.x;
    if (t >= BLD_) return;
    int token = (int)(t >> 8);           // /D
    int d = (int)(t & 255);
    x[t] = emb[(long long)tok[token] * D_ + d];
}

__global__ void bias_comb_k(const float* __restrict__ br, const float* __restrict__ bi,
                            float* __restrict__ bm, float* __restrict__ bp) {
    int t = blockIdx.x * blockDim.x + threadIdx.x;
    if (t < 4 * D_) { bm[t] = br[t] - bi[t]; bp[t] = br[t] + bi[t]; }
}

__global__ void pack_w_k(const float* __restrict__ gw, float* __restrict__ wev,
                         float* __restrict__ wct) {
    int t = blockIdx.x * blockDim.x + threadIdx.x;
    if (t >= D_ * D_) return;
    int d = t >> 8, j = t & 255;
    wev[t] = gw[d * 3 * D_ + 2 * j];
    wct[t] = gw[d * 3 * D_ + 2 * D_ + j];
}

__global__ void enorm_k(const float* __restrict__ E, float* __restrict__ en) {
    int k = threadIdx.x;
    if (k >= KC_) return;
    float a = 0.f;
    for (int d = 0; d < D_; d++) { float e = E[k * D_ + d]; a += e * e; }
    en[k] = a;
}

// ---------------- fused attention ----------------
// grid: B*H*(L/8) blocks, 256 threads. Per block: 8 query rows, full 512-key softmax.
constexpr int QR_ = 8;
constexpr int ST_ = 32;
__global__ __launch_bounds__(256)
void attention_k(const float* __restrict__ qr_, const float* __restrict__ qi_,
                 const float* __restrict__ kr_, const float* __restrict__ ki_,
                 const float* __restrict__ vr_, const float* __restrict__ vi_,
                 float* __restrict__ ar_, float* __restrict__ ai_) {
    __shared__ float sQr[QR_][33], sQi[QR_][33];
    __shared__ float sKr[ST_][33], sKi[ST_][33];
    __shared__ float sVr[ST_][33], sVi[ST_][33];
    __shared__ float sS[QR_][L_];

    int bid = blockIdx.x;
    int qc = bid & 63;              // L/QR = 64
    int h  = (bid >> 6) & 7;
    int b  = bid >> 9;
    int t = threadIdx.x;
    const long long base = (long long)b * L_ * D_ + h * HD_;
    const int q0 = qc * QR_;

    { // load Q chunk (8x32 r+i)
        int r = t >> 5, d = t & 31;
        sQr[r][d] = qr_[base + (long long)(q0 + r) * D_ + d];
        sQi[r][d] = qi_[base + (long long)(q0 + r) * D_ + d];
    }

    const float scale = 0.17677669529663687f; // 1/sqrt(32)
    for (int kt = 0; kt < L_ / ST_; kt++) {
        __syncthreads();
#pragma unroll
        for (int i = 0; i < 4; i++) {
            int idx = t + i * 256;
            int s = idx >> 5, d = idx & 31;
            sKr[s][d] = kr_[base + (long long)(kt * ST_ + s) * D_ + d];
            sKi[s][d] = ki_[base + (long long)(kt * ST_ + s) * D_ + d];
        }
        __syncthreads();
        int r = t >> 5, s = t & 31;
        float acc = 0.f;
#pragma unroll
        for (int d = 0; d < HD_; d++)
            acc += sQr[r][d] * sKr[s][d] + sQi[r][d] * sKi[s][d];
        sS[r][kt * ST_ + s] = acc * scale;
    }
    __syncthreads();

    { // softmax: one warp per query row, 16 elems/lane
        int w = t >> 5, lane = t & 31;
        float vals[16];
        float m = -3.4e38f;
#pragma unroll
        for (int i = 0; i < 16; i++) { vals[i] = sS[w][lane + 32 * i]; m = fmaxf(m, vals[i]); }
#pragma unroll
        for (int off = 16; off > 0; off >>= 1) m = fmaxf(m, __shfl_xor_sync(0xffffffffu, m, off));
        float sum = 0.f;
#pragma unroll
        for (int i = 0; i < 16; i++) { vals[i] = expf(vals[i] - m); sum += vals[i]; }
#pragma unroll
        for (int off = 16; off > 0; off >>= 1) sum += __shfl_xor_sync(0xffffffffu, sum, off);
        float inv = 1.f / sum;
#pragma unroll
        for (int i = 0; i < 16; i++) sS[w][lane + 32 * i] = vals[i] * inv;
    }
    __syncthreads();

    int r = t >> 5, d = t & 31;
    float o_r = 0.f, o_i = 0.f;
    for (int vt = 0; vt < L_ / ST_; vt++) {
#pragma unroll
        for (int i = 0; i < 4; i++) {
            int idx = t + i * 256;
            int s = idx >> 5, dd = idx & 31;
            sVr[s][dd] = vr_[base + (long long)(vt * ST_ + s) * D_ + dd];
            sVi[s][dd] = vi_[base + (long long)(vt * ST_ + s) * D_ + dd];
        }
        __syncthreads();
#pragma unroll
        for (int s = 0; s < ST_; s++) {
            float p = sS[r][vt * ST_ + s];
            o_r += p * sVr[s][d];
            o_i += p * sVi[s][d];
        }
        __syncthreads();
    }
    ar_[base + (long long)(q0 + r) * D_ + d] = o_r;
    ai_[base + (long long)(q0 + r) * D_ + d] = o_i;
}

// ---------------- VQ argmin + per-token loss partial ----------------
__global__ void vq_argmin_k(const float* __restrict__ dot, const float* __restrict__ en,
                            const float* __restrict__ zr, const float* __restrict__ zi,
                            const float* __restrict__ E, int* __restrict__ idx_out,
                            float* __restrict__ part) {
    int tkn = blockIdx.x;
    int k = threadIdx.x;             // 128
    __shared__ float sv[128];
    __shared__ int si[128];
    float v = en[k] - 2.f * dot[(long long)tkn * KC_ + k];
    sv[k] = v; si[k] = k;
    __syncthreads();
    for (int s = 64; s > 0; s >>= 1) {
        if (k < s) {
            float a = sv[k], b2 = sv[k + s];
            if (b2 < a || (b2 == a && si[k + s] < si[k])) { sv[k] = b2; si[k] = si[k + s]; }
        }
        __syncthreads();
    }
    int best = si[0];
    if (k == 0) idx_out[tkn] = best;
    __syncthreads();
    float acc = 0.f;
    for (int d = k; d < D_; d += 128) {
        float diff = E[(long long)best * D_ + d] - zr[(long long)tkn * D_ + d];
        float ziv = zi[(long long)tkn * D_ + d];
        acc += diff * diff + ziv * ziv;
    }
    sv[k] = acc;
    __syncthreads();
    for (int s = 64; s > 0; s >>= 1) {
        if (k < s) sv[k] += sv[k + s];
        __syncthreads();
    }
    if (k == 0) part[tkn] = sv[0];
}

__global__ void vq_reduce_k(const float* __restrict__ part, float* __restrict__ out_loss) {
    __shared__ float s[256];
    float a = 0.f;
    for (int i = threadIdx.x; i < BL_; i += 256) a += part[i];
    s[threadIdx.x] = a;
    __syncthreads();
    for (int st = 128; st > 0; st >>= 1) {
        if (threadIdx.x < st) s[threadIdx.x] += s[threadIdx.x + st];
        __syncthreads();
    }
    if (threadIdx.x == 0) out_loss[0] = 2.f * s[0] / (float)BLD_;
}

// ---------------- gate / stack / layernorm+modrelu ----------------
__global__ void gate_k(const float* __restrict__ G, const float* __restrict__ Cg,
                       const int* __restrict__ idx, float* __restrict__ gated) {
    long long t = (long long)blockIdx.x * blockDim.x + threadIdx.x;
    if (t >= BLD_) return;
    int d = (int)(t & 255);
    int tkn = (int)(t >> 8);
    int b = tkn >> 9;                      // /L
    float x = G[(long long)idx[tkn] * D_ + d] + Cg[b * D_ + d];
    gated[t] = 1.f / (1.f + expf(-x));
}

__global__ void stack_k(const float* __restrict__ gated, float* __restrict__ stk,
                        float* __restrict__ out_stk) {
    int b = blockIdx.x, d = threadIdx.x;
    float s = 0.f;
    for (int l = 0; l < L_; l++) s += gated[((long long)b * L_ + l) * D_ + d];
    stk[b * D_ + d] = s;
    out_stk[b * D_ + d] = s;
}

__global__ void ln_modrelu_k(const float* __restrict__ gated, const float* __restrict__ stk,
                             const float* __restrict__ lg, const float* __restrict__ lb,
                             const float* __restrict__ ib, const float* __restrict__ mb,
                             float* __restrict__ Y) {
    int tkn = blockIdx.x;
    int b = tkn >> 9;
    int d = threadIdx.x;
    __shared__ float red[256];
    float x = gated[(long long)tkn * D_ + d] + stk[b * D_ + d];
    red[d] = x;
    __syncthreads();
    for (int s = 128; s > 0; s >>= 1) {
        if (d < s) red[d] += red[d + s];
        __syncthreads();
    }
    float mu = red[0] * (1.f / 256.f);
    __syncthreads();
    float diff = x - mu;
    red[d] = diff * diff;
    __syncthreads();
    for (int s = 128; s > 0; s >>= 1) {
        if (d < s) red[d] += red[d + s];
        __syncthreads();
    }
    float var = red[0] * (1.f / 256.f);
    float nr = diff * (1.f / sqrtf(var + 1e-5f)) * lg[d] + lb[d];
    float ni = ib[d];
    float mag = sqrtf(nr * nr + ni * ni);
    float sc = fmaxf(mag + mb[d], 0.f) / (mag + 1e-6f);
    Y[(long long)tkn * D_ + d] = nr * sc;
}

// ---------------- host launch ----------------
static inline dim3 gemm_grid(int M, int N) {
    return dim3((N + 127) / 128, (M + 127) / 128);
}

extern "C" void kernel_launch(void* const* d_in, const int* in_sizes, int n_in,
                              void* d_out, int out_size) {
    const int*   tokens = (const int*)d_in[0];
    const float* context = (const float*)d_in[1];
    const float* emb = (const float*)d_in[2];
    const float* awr = (const float*)d_in[3];
    const float* awi = (const float*)d_in[4];
    const float* abr = (const float*)d_in[5];
    const float* abi = (const float*)d_in[6];
    const float* vqe = (const float*)d_in[7];
    const float* gw  = (const float*)d_in[8];
    const float* gb  = (const float*)d_in[9];
    const float* lrg = (const float*)d_in[10];
    const float* lrb = (const float*)d_in[11];
    // d_in[12] = ln_i_g : mathematically unused (multiplies exact zeros)
    const float* lib = (const float*)d_in[13];
    const float* mrb = (const float*)d_in[14];
    const float* hw  = (const float*)d_in[15];
    const float* hb  = (const float*)d_in[16];
    float* out = (float*)d_out;

    float* S; cudaGetSymbolAddress((void**)&S, d_scratch);
    int* idxb; cudaGetSymbolAddress((void**)&idxb, d_idxbuf);

    float* x    = S + OFF_X;
    float* qr   = S + OFF_QR;  float* qi = S + OFF_QI;
    float* kr   = S + OFF_KR;  float* ki = S + OFF_KI;
    float* vr   = S + OFF_VR;  float* vi = S + OFF_VI;
    float* ar   = S + OFF_AR;  float* ai = S + OFF_AI;
    float* zr   = S + OFF_ZR;  float* zi = S + OFF_ZI;
    float* gated = S + OFF_GATED;
    float* Y    = S + OFF_Y;
    float* dotb = S + OFF_DOT;
    float* G    = S + OFF_G;
    float* Cg   = S + OFF_CG;
    float* wev  = S + OFF_WEV;
    float* wct  = S + OFF_WCT;
    float* stk  = S + OFF_STK;
    float* bm   = S + OFF_BM;
    float* bp   = S + OFF_BP;
    float* en   = S + OFF_EN;
    float* part = S + OFF_PART;

    const int DD = D_ * D_;

    // prep
    bias_comb_k<<<(4 * D_ + 255) / 256, 256>>>(abr, abi, bm, bp);
    pack_w_k<<<(DD + 255) / 256, 256>>>(gw, wev, wct);
    enorm_k<<<1, 128>>>(vqe, en);
    embed_k<<<(int)((BLD_ + 255) / 256), 256>>>(tokens, emb, x);

    // QKV (clinear with zi = 0)
    gemm_nt<1, false, true><<<gemm_grid(BL_, D_), 256>>>(x, awr + 0 * DD, bm + 0 * D_, qr, BL_, D_, D_);
    gemm_nt<1, false, true><<<gemm_grid(BL_, D_), 256>>>(x, awi + 0 * DD, bp + 0 * D_, qi, BL_, D_, D_);
    gemm_nt<1, false, true><<<gemm_grid(BL_, D_), 256>>>(x, awr + 1 * DD, bm + 1 * D_, kr, BL_, D_, D_);
    gemm_nt<1, false, true><<<gemm_grid(BL_, D_), 256>>>(x, awi + 1 * DD, bp + 1 * D_, ki, BL_, D_, D_);
    gemm_nt<1, false, true><<<gemm_grid(BL_, D_), 256>>>(x, awr + 2 * DD, bm + 2 * D_, vr, BL_, D_, D_);
    gemm_nt<1, false, true><<<gemm_grid(BL_, D_), 256>>>(x, awi + 2 * DD, bp + 2 * D_, vi, BL_, D_, D_);

    // attention
    attention_k<<<B_ * H_ * (L_ / QR_), 256>>>(qr, qi, kr, ki, vr, vi, ar, ai);

    // output clinear
    gemm_nt<1, false, true><<<gemm_grid(BL_, D_), 256>>>(ar, awr + 3 * DD, bm + 3 * D_, zr, BL_, D_, D_);
    gemm_nt<-1, true, false><<<gemm_grid(BL_, D_), 256>>>(ai, awi + 3 * DD, nullptr, zr, BL_, D_, D_);
    gemm_nt<1, false, true><<<gemm_grid(BL_, D_), 256>>>(ai, awr + 3 * DD, bp + 3 * D_, zi, BL_, D_, D_);
    gemm_nt<1, true, false><<<gemm_grid(BL_, D_), 256>>>(ar, awi + 3 * DD, nullptr, zi, BL_, D_, D_);

    // VQ: Dot = zr @ E^T, then argmin + loss
    gemm_nt<1, false, false><<<gemm_grid(BL_, KC_), 256>>>(zr, vqe, nullptr, dotb, BL_, KC_, D_);
    vq_argmin_k<<<BL_, 128>>>(dotb, en, zr, zi, vqe, idxb, part);
    vq_reduce_k<<<1, 256>>>(part, out + BLV_);

    // gate tables: G = vq_emb @ Weven^T ; Cg = context @ Wctx^T + gate_b
    gemm_nt<1, false, false><<<gemm_grid(KC_, D_), 256>>>(vqe, wev, nullptr, G, KC_, D_, D_);
    gemm_nt<1, false, true><<<gemm_grid(B_, D_), 256>>>(context, wct, gb, Cg, B_, D_, D_);

    // gated, stack (also writes stack_top output), layernorm+modrelu
    gate_k<<<(int)((BLD_ + 255) / 256), 256>>>(G, Cg, idxb, gated);
    stack_k<<<B_, D_>>>(gated, stk, out + BLV_ + 1);
    ln_modrelu_k<<<BL_, D_>>>(gated, stk, lrg, lrb, lib, mrb, Y);

    // head: logits = Y @ head_w^T + head_b  -> d_out[0 : B*L*V]
    gemm_nt<1, false, true><<<gemm_grid(BL_, V_), 256>>>(Y, hw, hb, out, BL_, V_, D_);
}

// round 3
// speedup vs baseline: 1.3772x; 1.3772x over previous
#include <cuda_runtime.h>
#include <cuda_bf16.h>
#include <cstdint>
#include <math.h>

// ---------------- problem dims ----------------
constexpr int B_ = 32, L_ = 512, D_ = 256, H_ = 8, V_ = 4096, KC_ = 128;
constexpr int HD_ = D_ / H_;                 // 32
constexpr int BL_ = B_ * L_;                 // 16384
constexpr long long BLD_ = (long long)BL_ * D_;   // 4194304
constexpr long long BLV_ = (long long)BL_ * V_;   // 67108864

// ---------------- fp32 scratch offsets ----------------
constexpr long long OFF_X     = 0;                               // BLD
constexpr long long OFF_QKV   = OFF_X + BLD_;                    // BL*1536
constexpr long long OFF_AP    = OFF_QKV + (long long)BL_ * 1536; // BL*512
constexpr long long OFF_Z     = OFF_AP + (long long)BL_ * 512;   // BL*512
constexpr long long OFF_DOT   = OFF_Z + (long long)BL_ * 512;    // BL*128
constexpr long long OFF_GATED = OFF_DOT + (long long)BL_ * KC_;  // BLD
constexpr long long OFF_Y     = OFF_GATED + BLD_;                // BLD
constexpr long long OFF_G     = OFF_Y + BLD_;                    // 128*256
constexpr long long OFF_CG    = OFF_G + (long long)KC_ * D_;     // 32*256
constexpr long long OFF_WEV   = OFF_CG + (long long)B_ * D_;     // 256*256
constexpr long long OFF_WCT   = OFF_WEV + (long long)D_ * D_;    // 256*256
constexpr long long OFF_STK   = OFF_WCT + (long long)D_ * D_;    // 32*256
constexpr long long OFF_EN    = OFF_STK + (long long)B_ * D_;    // 128
constexpr long long OFF_PART  = OFF_EN + KC_;                    // BL
constexpr long long OFF_BQKV  = OFF_PART + BL_;                  // 1536
constexpr long long OFF_BZ    = OFF_BQKV + 1536;                 // 512
constexpr long long SCRATCH_N = OFF_BZ + 512 + 64;

__device__ float d_scratch[SCRATCH_N];
__device__ int   d_idxbuf[BL_];

// ---------------- bf16 scratch offsets ----------------
constexpr long long BF_XH  = 0;
constexpr long long BF_XL  = BF_XH + BLD_;
constexpr long long BF_WQH = BF_XL + BLD_;                     // 1536*256
constexpr long long BF_WQL = BF_WQH + 1536LL * 256;
constexpr long long BF_APH = BF_WQL + 1536LL * 256;            // BL*512
constexpr long long BF_APL = BF_APH + (long long)BL_ * 512;
constexpr long long BF_WZH = BF_APL + (long long)BL_ * 512;    // 512*512
constexpr long long BF_WZL = BF_WZH + 512LL * 512;
constexpr long long BF_ZRH = BF_WZL + 512LL * 512;             // BLD
constexpr long long BF_ZRL = BF_ZRH + BLD_;
constexpr long long BF_VQH = BF_ZRL + BLD_;                    // 128*256
constexpr long long BF_VQL = BF_VQH + (long long)KC_ * D_;
constexpr long long BF_YH  = BF_VQL + (long long)KC_ * D_;     // BLD
constexpr long long BF_YL  = BF_YH + BLD_;
constexpr long long BF_HWH = BF_YL + BLD_;                     // 4096*256
constexpr long long BF_HWL = BF_HWH + (long long)V_ * D_;
constexpr long long BF_N   = BF_HWL + (long long)V_ * D_ + 64;

__device__ __nv_bfloat16 d_bf[BF_N];

// ==================== PTX helpers (sm_80+ path: HMMA / ldmatrix / cp.async) ====================
__device__ __forceinline__ uint32_t smem_u32(const void* p) {
    uint32_t a;
    asm("{ .reg .u64 t; cvta.to.shared.u64 t, %1; cvt.u32.u64 %0, t; }" : "=r"(a) : "l"(p));
    return a;
}

#define CP_ASYNC16(dst, src) \
    asm volatile("cp.async.cg.shared.global [%0], [%1], 16;" :: "r"(dst), "l"(src))
#define CP_COMMIT() asm volatile("cp.async.commit_group;" ::: "memory")
#define CP_WAIT(n)  asm volatile("cp.async.wait_group %0;" :: "n"(n) : "memory")

#define LDSM_X4(r, addr) \
    asm volatile("ldmatrix.sync.aligned.m8n8.x4.shared.b16 {%0,%1,%2,%3}, [%4];" \
                 : "=r"((r)[0]), "=r"((r)[1]), "=r"((r)[2]), "=r"((r)[3]) : "r"(addr))

#define MMA_BF16(d, a, b) \
    asm volatile("mma.sync.aligned.m16n8k16.row.col.f32.bf16.bf16.f32 " \
                 "{%0,%1,%2,%3}, {%4,%5,%6,%7}, {%8,%9}, {%0,%1,%2,%3};" \
                 : "+f"((d)[0]), "+f"((d)[1]), "+f"((d)[2]), "+f"((d)[3]) \
                 : "r"((a)[0]), "r"((a)[1]), "r"((a)[2]), "r"((a)[3]), \
                   "r"((b)[0]), "r"((b)[1]))

// ==================== HMMA bf16-split GEMM ====================
// C[M,N] = (AH+AL)[M,K] @ (BH+BL)[N,K]^T (+bias), fp32 accum.
// CTA tile 128x128, 8 warps (2M x 4N), warp tile 64x32, K-slab 32, 2 stages.
constexpr int LDT = 40;                               // padded row stride (bf16)
constexpr int TILE_BYTES2 = 128 * LDT * 2;            // 10240
constexpr int STAGE_BYTES = 4 * TILE_BYTES2;          // AH, AL, BH, BL = 40960
constexpr int GM_SMEM = 2 * STAGE_BYTES;              // 81920

template<bool BIAS>
__global__ __launch_bounds__(256, 1)
void gemm_mma(const __nv_bfloat16* __restrict__ AH, const __nv_bfloat16* __restrict__ AL,
              const __nv_bfloat16* __restrict__ BH, const __nv_bfloat16* __restrict__ BL,
              const float* __restrict__ bias, float* __restrict__ C,
              int N, int K) {
    extern __shared__ char smem[];
    const uint32_t sb = smem_u32(smem);
    const int tid = threadIdx.x, wid = tid >> 5, lane = tid & 31;
    const int m0 = blockIdx.y * 128, n0 = blockIdx.x * 128;
    const int warpM = wid & 1, warpN = wid >> 1;      // 2 x 4
    const int mW = warpM * 64, nW = warpN * 32;

    float acc[4][4][4];
#pragma unroll
    for (int i = 0; i < 4; i++)
#pragma unroll
        for (int j = 0; j < 4; j++)
#pragma unroll
            for (int c = 0; c < 4; c++) acc[i][j][c] = 0.f;

    const __nv_bfloat16* srcs[4] = {AH, AL, BH, BL};

    auto load_stage = [&](int buf, int k0) {
#pragma unroll
        for (int mtx = 0; mtx < 4; mtx++) {
            const __nv_bfloat16* src = srcs[mtx];
            const int rbase = (mtx < 2) ? m0 : n0;
            uint32_t dst = sb + buf * STAGE_BYTES + mtx * TILE_BYTES2;
#pragma unroll
            for (int it = 0; it < 2; it++) {
                int c = it * 256 + tid;               // 0..511
                int row = c >> 2, cc = c & 3;
                uint32_t daddr = dst + (uint32_t)(row * LDT + cc * 8) * 2;
                const void* gaddr = src + (size_t)(rbase + row) * K + k0 + cc * 8;
                CP_ASYNC16(daddr, gaddr);
            }
        }
        CP_COMMIT();
    };

    // fragment address helpers
    auto a_addr = [&](uint32_t base, int mBase, int k0) -> uint32_t {
        int t = lane >> 3;
        int r = mBase + ((t & 1) << 3) + (lane & 7);
        int c = k0 + ((t >> 1) << 3);
        return base + (uint32_t)(r * LDT + c) * 2;
    };
    auto b_addr = [&](uint32_t base, int nBase, int k0) -> uint32_t {
        int t = lane >> 3;
        int n = nBase + ((t >> 1) << 3) + (lane & 7);
        int c = k0 + ((t & 1) << 3);
        return base + (uint32_t)(n * LDT + c) * 2;
    };

    const int S = K >> 5;
    load_stage(0, 0);

    for (int s = 0; s < S; s++) {
        const int b = s & 1;
        if (s + 1 < S) {
            load_stage(b ^ 1, (s + 1) << 5);
            CP_WAIT(1);
        } else {
            CP_WAIT(0);
        }
        __syncthreads();

        const uint32_t aH = sb + b * STAGE_BYTES;
        const uint32_t aL = aH + TILE_BYTES2;
        const uint32_t bH = aH + 2 * TILE_BYTES2;
        const uint32_t bL = aH + 3 * TILE_BYTES2;

#pragma unroll
        for (int kk = 0; kk < 2; kk++) {
            const int k0 = kk * 16;
            uint32_t ah[4][4], al[4][4];
#pragma unroll
            for (int mf = 0; mf < 4; mf++) {
                LDSM_X4(ah[mf], a_addr(aH, mW + mf * 16, k0));
                LDSM_X4(al[mf], a_addr(aL, mW + mf * 16, k0));
            }
            uint32_t bh[4][2], bl[4][2];
#pragma unroll
            for (int nf2 = 0; nf2 < 2; nf2++) {
                uint32_t r[4];
                LDSM_X4(r, b_addr(bH, nW + nf2 * 16, k0));
                bh[nf2 * 2][0] = r[0]; bh[nf2 * 2][1] = r[1];
                bh[nf2 * 2 + 1][0] = r[2]; bh[nf2 * 2 + 1][1] = r[3];
                LDSM_X4(r, b_addr(bL, nW + nf2 * 16, k0));
                bl[nf2 * 2][0] = r[0]; bl[nf2 * 2][1] = r[1];
                bl[nf2 * 2 + 1][0] = r[2]; bl[nf2 * 2 + 1][1] = r[3];
            }
#pragma unroll
            for (int mf = 0; mf < 4; mf++)
#pragma unroll
                for (int nf = 0; nf < 4; nf++) {
                    MMA_BF16(acc[mf][nf], ah[mf], bh[nf]);
                    MMA_BF16(acc[mf][nf], ah[mf], bl[nf]);
                    MMA_BF16(acc[mf][nf], al[mf], bh[nf]);
                }
        }
        __syncthreads();
    }

    // epilogue
    const int lr = lane >> 2, lc = (lane & 3) * 2;
#pragma unroll
    for (int mf = 0; mf < 4; mf++) {
        int row0 = m0 + mW + mf * 16 + lr;
#pragma unroll
        for (int nf = 0; nf < 4; nf++) {
            int col = n0 + nW + nf * 8 + lc;
            float b0 = 0.f, b1 = 0.f;
            if (BIAS) { b0 = bias[col]; b1 = bias[col + 1]; }
            float2 v0 = make_float2(acc[mf][nf][0] + b0, acc[mf][nf][1] + b1);
            float2 v1 = make_float2(acc[mf][nf][2] + b0, acc[mf][nf][3] + b1);
            *reinterpret_cast<float2*>(C + (size_t)row0 * N + col) = v0;
            *reinterpret_cast<float2*>(C + (size_t)(row0 + 8) * N + col) = v1;
        }
    }
}

// ---------------- fp32 SGEMM (small matrices only) ----------------
template<bool BIAS>
__global__ __launch_bounds__(256)
void gemm_nt(const float* __restrict__ A, const float* __restrict__ W,
             const float* __restrict__ bias, float* __restrict__ C,
             int M, int N, int K) {
    __shared__ float As[8][129];
    __shared__ float Ws[8][129];
    const int tid = threadIdx.x;
    const int tx = tid & 15, ty = tid >> 4;
    const int m0 = blockIdx.y * 128, n0 = blockIdx.x * 128;
    const int lm = tid >> 1;
    const int lh = tid & 1;

    float acc[8][8];
#pragma unroll
    for (int i = 0; i < 8; i++)
#pragma unroll
        for (int j = 0; j < 8; j++) acc[i][j] = 0.f;

    for (int k0 = 0; k0 < K; k0 += 8) {
        float4 av = make_float4(0.f, 0.f, 0.f, 0.f);
        float4 wv = make_float4(0.f, 0.f, 0.f, 0.f);
        int gm = m0 + lm;
        if (gm < M) av = *reinterpret_cast<const float4*>(A + (long long)gm * K + k0 + lh * 4);
        int gn = n0 + lm;
        if (gn < N) wv = *reinterpret_cast<const float4*>(W + (long long)gn * K + k0 + lh * 4);
        __syncthreads();
        As[lh * 4 + 0][lm] = av.x; As[lh * 4 + 1][lm] = av.y;
        As[lh * 4 + 2][lm] = av.z; As[lh * 4 + 3][lm] = av.w;
        Ws[lh * 4 + 0][lm] = wv.x; Ws[lh * 4 + 1][lm] = wv.y;
        Ws[lh * 4 + 2][lm] = wv.z; Ws[lh * 4 + 3][lm] = wv.w;
        __syncthreads();
#pragma unroll
        for (int kk = 0; kk < 8; kk++) {
            float ra[8], rw[8];
#pragma unroll
            for (int i = 0; i < 8; i++) ra[i] = As[kk][ty + 16 * i];
#pragma unroll
            for (int j = 0; j < 8; j++) rw[j] = Ws[kk][tx + 16 * j];
#pragma unroll
            for (int i = 0; i < 8; i++)
#pragma unroll
                for (int j = 0; j < 8; j++)
                    acc[i][j] += ra[i] * rw[j];
        }
    }
#pragma unroll
    for (int i = 0; i < 8; i++) {
        int gm = m0 + ty + 16 * i;
        if (gm >= M) continue;
#pragma unroll
        for (int j = 0; j < 8; j++) {
            int gn = n0 + tx + 16 * j;
            if (gn >= N) continue;
            float v = acc[i][j];
            if (BIAS) v += bias[gn];
            C[(long long)gm * N + gn] = v;
        }
    }
}

// ---------------- prep / convert kernels ----------------
__global__ void embed_k(const int* __restrict__ tok, const float* __restrict__ emb,
                        float* __restrict__ x) {
    long long t = (long long)blockIdx.x * blockDim.x + threadIdx.x;
    if (t >= BLD_) return;
    int token = (int)(t >> 8);
    int d = (int)(t & 255);
    x[t] = emb[(long long)tok[token] * D_ + d];
}

__global__ void split_k(const float* __restrict__ x, __nv_bfloat16* __restrict__ hi,
                        __nv_bfloat16* __restrict__ lo, long long n) {
    long long t = (long long)blockIdx.x * blockDim.x + threadIdx.x;
    if (t >= n) return;
    float v = x[t];
    __nv_bfloat16 h = __float2bfloat16(v);
    hi[t] = h;
    lo[t] = __float2bfloat16(v - __bfloat162float(h));
}

// extract zr (cols 0..255 of packed Z) and split
__global__ void split_zr_k(const float* __restrict__ Z, __nv_bfloat16* __restrict__ hi,
                           __nv_bfloat16* __restrict__ lo) {
    long long t = (long long)blockIdx.x * blockDim.x + threadIdx.x;
    if (t >= BLD_) return;
    long long m = t >> 8; int d = (int)(t & 255);
    float v = Z[m * 512 + d];
    __nv_bfloat16 h = __float2bfloat16(v);
    hi[t] = h;
    lo[t] = __float2bfloat16(v - __bfloat162float(h));
}

// WQKV rows: [qr(awr0), qi(awi0), kr(awr1), ki(awi1), vr(awr2), vi(awi2)]
__global__ void build_wqkv_k(const float* __restrict__ awr, const float* __restrict__ awi,
                             __nv_bfloat16* __restrict__ hi, __nv_bfloat16* __restrict__ lo) {
    long long t = (long long)blockIdx.x * blockDim.x + threadIdx.x;
    if (t >= 1536LL * 256) return;
    int n = (int)(t >> 8), k = (int)(t & 255);
    int seg = n >> 8, j = n & 255, proj = seg >> 1;
    float v = ((seg & 1) == 0) ? awr[((long long)proj * 256 + j) * 256 + k]
                               : awi[((long long)proj * 256 + j) * 256 + k];
    __nv_bfloat16 h = __float2bfloat16(v);
    hi[t] = h;
    lo[t] = __float2bfloat16(v - __bfloat162float(h));
}

__global__ void build_bqkv_k(const float* __restrict__ abr, const float* __restrict__ abi,
                             float* __restrict__ bq) {
    int t = blockIdx.x * blockDim.x + threadIdx.x;
    if (t >= 1536) return;
    int seg = t >> 8, j = t & 255, proj = seg >> 1;
    float r = abr[proj * 256 + j], i2 = abi[proj * 256 + j];
    bq[t] = ((seg & 1) == 0) ? (r - i2) : (r + i2);
}

// WZ (512x512): n<256: [Wr3 | -Wi3]; n>=256: [Wi3 | Wr3]
__global__ void build_wz_k(const float* __restrict__ awr, const float* __restrict__ awi,
                           __nv_bfloat16* __restrict__ hi, __nv_bfloat16* __restrict__ lo) {
    long long t = (long long)blockIdx.x * blockDim.x + threadIdx.x;
    if (t >= 512LL * 512) return;
    int n = (int)(t >> 9), k = (int)(t & 511);
    float v;
    if (n < 256) {
        v = (k < 256) ? awr[(768LL + n) * 256 + k] : -awi[(768LL + n) * 256 + (k - 256)];
    } else {
        int n2 = n - 256;
        v = (k < 256) ? awi[(768LL + n2) * 256 + k] : awr[(768LL + n2) * 256 + (k - 256)];
    }
    __nv_bfloat16 h = __float2bfloat16(v);
    hi[t] = h;
    lo[t] = __float2bfloat16(v - __bfloat162float(h));
}

__global__ void build_bz_k(const float* __restrict__ abr, const float* __restrict__ abi,
                           float* __restrict__ bz) {
    int t = blockIdx.x * blockDim.x + threadIdx.x;
    if (t >= 512) return;
    if (t < 256) bz[t] = abr[768 + t] - abi[768 + t];
    else         bz[t] = abr[768 + t - 256] + abi[768 + t - 256];
}

__global__ void pack_w_k(const float* __restrict__ gw, float* __restrict__ wev,
                         float* __restrict__ wct) {
    int t = blockIdx.x * blockDim.x + threadIdx.x;
    if (t >= D_ * D_) return;
    int d = t >> 8, j = t & 255;
    wev[t] = gw[d * 3 * D_ + 2 * j];
    wct[t] = gw[d * 3 * D_ + 2 * D_ + j];
}

__global__ void enorm_k(const float* __restrict__ E, float* __restrict__ en) {
    int k = threadIdx.x;
    if (k >= KC_) return;
    float a = 0.f;
    for (int d = 0; d < D_; d++) { float e = E[k * D_ + d]; a += e * e; }
    en[k] = a;
}

// ---------------- fused attention (fp32, packed QKV in / packed AP out) ----------------
constexpr int QR_ = 8;
constexpr int ST_ = 32;
__global__ __launch_bounds__(256)
void attention_k(const float* __restrict__ qkv, float* __restrict__ ap) {
    __shared__ float sQr[QR_][33], sQi[QR_][33];
    __shared__ float sKr[ST_][33], sKi[ST_][33];
    __shared__ float sVr[ST_][33], sVi[ST_][33];
    __shared__ float sS[QR_][L_];

    int bid = blockIdx.x;
    int qc = bid & 63;
    int h  = (bid >> 6) & 7;
    int b  = bid >> 9;
    int t = threadIdx.x;
    const size_t tok0 = (size_t)b * L_;
    const int hd0 = h * HD_;
    const int q0 = qc * QR_;

    {   // load Q chunk
        int r = t >> 5, d = t & 31;
        const float* qrow = qkv + (tok0 + q0 + r) * 1536 + hd0 + d;
        sQr[r][d] = qrow[0];
        sQi[r][d] = qrow[256];
    }

    const float scale = 0.17677669529663687f; // 1/sqrt(32)
    for (int kt = 0; kt < L_ / ST_; kt++) {
        __syncthreads();
#pragma unroll
        for (int i = 0; i < 4; i++) {
            int idx = t + i * 256;
            int s = idx >> 5, d = idx & 31;
            const float* krow = qkv + (tok0 + kt * ST_ + s) * 1536 + hd0 + d;
            sKr[s][d] = krow[512];
            sKi[s][d] = krow[768];
        }
        __syncthreads();
        int r = t >> 5, s = t & 31;
        float acc = 0.f;
#pragma unroll
        for (int d = 0; d < HD_; d++)
            acc += sQr[r][d] * sKr[s][d] + sQi[r][d] * sKi[s][d];
        sS[r][kt * ST_ + s] = acc * scale;
    }
    __syncthreads();

    {   // softmax: one warp per query row
        int w = t >> 5, lane = t & 31;
        float vals[16];
        float m = -3.4e38f;
#pragma unroll
        for (int i = 0; i < 16; i++) { vals[i] = sS[w][lane + 32 * i]; m = fmaxf(m, vals[i]); }
#pragma unroll
        for (int off = 16; off > 0; off >>= 1) m = fmaxf(m, __shfl_xor_sync(0xffffffffu, m, off));
        float sum = 0.f;
#pragma unroll
        for (int i = 0; i < 16; i++) { vals[i] = expf(vals[i] - m); sum += vals[i]; }
#pragma unroll
        for (int off = 16; off > 0; off >>= 1) sum += __shfl_xor_sync(0xffffffffu, sum, off);
        float inv = 1.f / sum;
#pragma unroll
        for (int i = 0; i < 16; i++) sS[w][lane + 32 * i] = vals[i] * inv;
    }
    __syncthreads();

    int r = t >> 5, d = t & 31;
    float o_r = 0.f, o_i = 0.f;
    for (int vt = 0; vt < L_ / ST_; vt++) {
#pragma unroll
        for (int i = 0; i < 4; i++) {
            int idx = t + i * 256;
            int s = idx >> 5, dd = idx & 31;
            const float* vrow = qkv + (tok0 + vt * ST_ + s) * 1536 + hd0 + dd;
            sVr[s][dd] = vrow[1024];
            sVi[s][dd] = vrow[1280];
        }
        __syncthreads();
#pragma unroll
        for (int s = 0; s < ST_; s++) {
            float p = sS[r][vt * ST_ + s];
            o_r += p * sVr[s][d];
            o_i += p * sVi[s][d];
        }
        __syncthreads();
    }
    float* orow = ap + (tok0 + q0 + r) * 512 + hd0 + d;
    orow[0]   = o_r;
    orow[256] = o_i;
}

// ---------------- VQ argmin + loss ----------------
__global__ void vq_argmin_k(const float* __restrict__ dot, const float* __restrict__ en,
                            const float* __restrict__ Z, const float* __restrict__ E,
                            int* __restrict__ idx_out, float* __restrict__ part) {
    int tkn = blockIdx.x;
    int k = threadIdx.x;
    __shared__ float sv[128];
    __shared__ int si[128];
    float v = en[k] - 2.f * dot[(long long)tkn * KC_ + k];
    sv[k] = v; si[k] = k;
    __syncthreads();
    for (int s = 64; s > 0; s >>= 1) {
        if (k < s) {
            float a = sv[k], b2 = sv[k + s];
            if (b2 < a || (b2 == a && si[k + s] < si[k])) { sv[k] = b2; si[k] = si[k + s]; }
        }
        __syncthreads();
    }
    int best = si[0];
    if (k == 0) idx_out[tkn] = best;
    __syncthreads();
    float acc = 0.f;
    for (int d = k; d < D_; d += 128) {
        float diff = E[(long long)best * D_ + d] - Z[(long long)tkn * 512 + d];
        float ziv = Z[(long long)tkn * 512 + 256 + d];
        acc += diff * diff + ziv * ziv;
    }
    sv[k] = acc;
    __syncthreads();
    for (int s = 64; s > 0; s >>= 1) {
        if (k < s) sv[k] += sv[k + s];
        __syncthreads();
    }
    if (k == 0) part[tkn] = sv[0];
}

__global__ void vq_reduce_k(const float* __restrict__ part, float* __restrict__ out_loss) {
    __shared__ float s[256];
    float a = 0.f;
    for (int i = threadIdx.x; i < BL_; i += 256) a += part[i];
    s[threadIdx.x] = a;
    __syncthreads();
    for (int st = 128; st > 0; st >>= 1) {
        if (threadIdx.x < st) s[threadIdx.x] += s[threadIdx.x + st];
        __syncthreads();
    }
    if (threadIdx.x == 0) out_loss[0] = 2.f * s[0] / (float)BLD_;
}

// ---------------- gate / stack / layernorm+modrelu ----------------
__global__ void gate_k(const float* __restrict__ G, const float* __restrict__ Cg,
                       const int* __restrict__ idx, float* __restrict__ gated) {
    long long t = (long long)blockIdx.x * blockDim.x + threadIdx.x;
    if (t >= BLD_) return;
    int d = (int)(t & 255);
    int tkn = (int)(t >> 8);
    int b = tkn >> 9;
    float x = G[(long long)idx[tkn] * D_ + d] + Cg[b * D_ + d];
    gated[t] = 1.f / (1.f + expf(-x));
}

__global__ void stack_k(const float* __restrict__ gated, float* __restrict__ stk,
                        float* __restrict__ out_stk) {
    int b = blockIdx.x, d = threadIdx.x;
    float s = 0.f;
    for (int l = 0; l < L_; l++) s += gated[((long long)b * L_ + l) * D_ + d];
    stk[b * D_ + d] = s;
    out_stk[b * D_ + d] = s;
}

__global__ void ln_modrelu_k(const float* __restrict__ gated, const float* __restrict__ stk,
                             const float* __restrict__ lg, const float* __restrict__ lb,
                             const float* __restrict__ ib, const float* __restrict__ mb,
                             float* __restrict__ Y) {
    int tkn = blockIdx.x;
    int b = tkn >> 9;
    int d = threadIdx.x;
    __shared__ float red[256];
    float x = gated[(long long)tkn * D_ + d] + stk[b * D_ + d];
    red[d] = x;
    __syncthreads();
    for (int s = 128; s > 0; s >>= 1) {
        if (d < s) red[d] += red[d + s];
        __syncthreads();
    }
    float mu = red[0] * (1.f / 256.f);
    __syncthreads();
    float diff = x - mu;
    red[d] = diff * diff;
    __syncthreads();
    for (int s = 128; s > 0; s >>= 1) {
        if (d < s) red[d] += red[d + s];
        __syncthreads();
    }
    float var = red[0] * (1.f / 256.f);
    float nr = diff * (1.f / sqrtf(var + 1e-5f)) * lg[d] + lb[d];
    float ni = ib[d];
    float mag = sqrtf(nr * nr + ni * ni);
    float sc = fmaxf(mag + mb[d], 0.f) / (mag + 1e-6f);
    Y[(long long)tkn * D_ + d] = nr * sc;
}

// ---------------- host launch ----------------
extern "C" void kernel_launch(void* const* d_in, const int* in_sizes, int n_in,
                              void* d_out, int out_size) {
    const int*   tokens = (const int*)d_in[0];
    const float* context = (const float*)d_in[1];
    const float* emb = (const float*)d_in[2];
    const float* awr = (const float*)d_in[3];
    const float* awi = (const float*)d_in[4];
    const float* abr = (const float*)d_in[5];
    const float* abi = (const float*)d_in[6];
    const float* vqe = (const float*)d_in[7];
    const float* gw  = (const float*)d_in[8];
    const float* gb  = (const float*)d_in[9];
    const float* lrg = (const float*)d_in[10];
    const float* lrb = (const float*)d_in[11];
    const float* lib = (const float*)d_in[13];
    const float* mrb = (const float*)d_in[14];
    const float* hw  = (const float*)d_in[15];
    const float* hb  = (const float*)d_in[16];
    float* out = (float*)d_out;

    float* S; cudaGetSymbolAddress((void**)&S, d_scratch);
    __nv_bfloat16* BF; cudaGetSymbolAddress((void**)&BF, d_bf);
    int* idxb; cudaGetSymbolAddress((void**)&idxb, d_idxbuf);

    cudaFuncSetAttribute(gemm_mma<true>,  cudaFuncAttributeMaxDynamicSharedMemorySize, GM_SMEM);
    cudaFuncSetAttribute(gemm_mma<false>, cudaFuncAttributeMaxDynamicSharedMemorySize, GM_SMEM);

    float* X    = S + OFF_X;
    float* QKV  = S + OFF_QKV;
    float* AP   = S + OFF_AP;
    float* Z    = S + OFF_Z;
    float* DOT  = S + OFF_DOT;
    float* GT   = S + OFF_GATED;
    float* Y    = S + OFF_Y;
    float* G    = S + OFF_G;
    float* Cg   = S + OFF_CG;
    float* wev  = S + OFF_WEV;
    float* wct  = S + OFF_WCT;
    float* stk  = S + OFF_STK;
    float* en   = S + OFF_EN;
    float* part = S + OFF_PART;
    float* bqkv = S + OFF_BQKV;
    float* bz   = S + OFF_BZ;

    __nv_bfloat16* XH  = BF + BF_XH;  __nv_bfloat16* XL  = BF + BF_XL;
    __nv_bfloat16* WQH = BF + BF_WQH; __nv_bfloat16* WQL = BF + BF_WQL;
    __nv_bfloat16* APH = BF + BF_APH; __nv_bfloat16* APL = BF + BF_APL;
    __nv_bfloat16* WZH = BF + BF_WZH; __nv_bfloat16* WZL = BF + BF_WZL;
    __nv_bfloat16* ZRH = BF + BF_ZRH; __nv_bfloat16* ZRL = BF + BF_ZRL;
    __nv_bfloat16* VQH = BF + BF_VQH; __nv_bfloat16* VQL = BF + BF_VQL;
    __nv_bfloat16* YH  = BF + BF_YH;  __nv_bfloat16* YL  = BF + BF_YL;
    __nv_bfloat16* HWH = BF + BF_HWH; __nv_bfloat16* HWL = BF + BF_HWL;

    // prep: weights / biases / tables
    build_bqkv_k<<<6, 256>>>(abr, abi, bqkv);
    build_bz_k<<<2, 256>>>(abr, abi, bz);
    build_wqkv_k<<<(int)((1536LL * 256 + 255) / 256), 256>>>(awr, awi, WQH, WQL);
    build_wz_k<<<(int)((512LL * 512 + 255) / 256), 256>>>(awr, awi, WZH, WZL);
    split_k<<<(int)(((long long)KC_ * D_ + 255) / 256), 256>>>(vqe, VQH, VQL, (long long)KC_ * D_);
    split_k<<<(int)(((long long)V_ * D_ + 255) / 256), 256>>>(hw, HWH, HWL, (long long)V_ * D_);
    pack_w_k<<<(D_ * D_ + 255) / 256, 256>>>(gw, wev, wct);
    enorm_k<<<1, 128>>>(vqe, en);

    // embed + split
    embed_k<<<(int)((BLD_ + 255) / 256), 256>>>(tokens, emb, X);
    split_k<<<(int)((BLD_ + 255) / 256), 256>>>(X, XH, XL, BLD_);

    // QKV fused GEMM: (16384 x 1536) = X @ WQKV^T + bqkv
    gemm_mma<true><<<dim3(1536 / 128, BL_ / 128), 256, GM_SMEM>>>(
        XH, XL, WQH, WQL, bqkv, QKV, 1536, 256);

    // attention (packed in/out)
    attention_k<<<B_ * H_ * (L_ / QR_), 256>>>(QKV, AP);

    // out clinear fused: Z(16384x512) = AP @ WZ^T + bz
    split_k<<<(int)((BLD_ * 2 + 255) / 256), 256>>>(AP, APH, APL, BLD_ * 2);
    gemm_mma<true><<<dim3(512 / 128, BL_ / 128), 256, GM_SMEM>>>(
        APH, APL, WZH, WZL, bz, Z, 512, 512);

    // VQ: DOT = zr @ vqe^T ; argmin + loss
    split_zr_k<<<(int)((BLD_ + 255) / 256), 256>>>(Z, ZRH, ZRL);
    gemm_mma<false><<<dim3(KC_ / 128, BL_ / 128), 256, GM_SMEM>>>(
        ZRH, ZRL, VQH, VQL, nullptr, DOT, KC_, 256);
    vq_argmin_k<<<BL_, 128>>>(DOT, en, Z, vqe, idxb, part);
    vq_reduce_k<<<1, 256>>>(part, out + BLV_);

    // gate tables (small fp32 GEMMs)
    gemm_nt<false><<<dim3(2, 1), 256>>>(vqe, wev, nullptr, G, KC_, D_, D_);
    gemm_nt<true><<<dim3(2, 1), 256>>>(context, wct, gb, Cg, B_, D_, D_);

    // gate, stack, layernorm+modrelu
    gate_k<<<(int)((BLD_ + 255) / 256), 256>>>(G, Cg, idxb, GT);
    stack_k<<<B_, D_>>>(GT, stk, out + BLV_ + 1);
    ln_modrelu_k<<<BL_, D_>>>(GT, stk, lrg, lrb, lib, mrb, Y);

    // head GEMM: logits = Y @ head_w^T + head_b
    split_k<<<(int)((BLD_ + 255) / 256), 256>>>(Y, YH, YL, BLD_);
    gemm_mma<true><<<dim3(V_ / 128, BL_ / 128), 256, GM_SMEM>>>(
        YH, YL, HWH, HWL, hb, out, V_, 256);
}

// round 4
// speedup vs baseline: 4.5423x; 3.2982x over previous
#include <cuda_runtime.h>
#include <cuda_bf16.h>
#include <cstdint>
#include <math.h>

// ---------------- problem dims ----------------
constexpr int B_ = 32, L_ = 512, D_ = 256, H_ = 8, V_ = 4096, KC_ = 128;
constexpr int BL_ = B_ * L_;                 // 16384
constexpr long long BLD_ = (long long)BL_ * D_;   // 4194304
constexpr long long BLV_ = (long long)BL_ * V_;   // 67108864

// ---------------- fp32 scratch ----------------
constexpr long long OFF_Z     = 0;                               // BL*256
constexpr long long OFF_DOT   = OFF_Z + (long long)BL_ * 256;    // BL*128
constexpr long long OFF_GATED = OFF_DOT + (long long)BL_ * KC_;  // BLD
constexpr long long OFF_G     = OFF_GATED + BLD_;                // 128*256
constexpr long long OFF_CG    = OFF_G + (long long)KC_ * D_;     // 32*256
constexpr long long OFF_WEV   = OFF_CG + (long long)B_ * D_;
constexpr long long OFF_WCT   = OFF_WEV + (long long)D_ * D_;
constexpr long long OFF_STK   = OFF_WCT + (long long)D_ * D_;
constexpr long long OFF_EN    = OFF_STK + (long long)B_ * D_;
constexpr long long OFF_PART  = OFF_EN + KC_;
constexpr long long OFF_BQKV  = OFF_PART + BL_;
constexpr long long OFF_BZR   = OFF_BQKV + 1536;
constexpr long long SCRATCH_N = OFF_BZR + 256 + 64;

__device__ float d_scratch[SCRATCH_N];
__device__ int   d_idxbuf[BL_];

// ---------------- bf16 scratch ----------------
constexpr long long BF_X    = 0;                                // BLD
constexpr long long BF_WQ   = BF_X + BLD_;                      // 1536*256
constexpr long long BF_QKV  = BF_WQ + 1536LL * 256;             // BL*1536
constexpr long long BF_AP   = BF_QKV + (long long)BL_ * 1536;   // BL*512
constexpr long long BF_WZ   = BF_AP + (long long)BL_ * 512;     // 256*512
constexpr long long BF_ZH   = BF_WZ + 256LL * 512;              // BLD
constexpr long long BF_ZL   = BF_ZH + BLD_;
constexpr long long BF_VQH  = BF_ZL + BLD_;                     // 128*256
constexpr long long BF_VQL  = BF_VQH + (long long)KC_ * D_;
constexpr long long BF_YH   = BF_VQL + (long long)KC_ * D_;     // BLD
constexpr long long BF_YL   = BF_YH + BLD_;
constexpr long long BF_HWH  = BF_YL + BLD_;                     // V*D
constexpr long long BF_HWL  = BF_HWH + (long long)V_ * D_;
constexpr long long BF_N    = BF_HWL + (long long)V_ * D_ + 64;

__device__ __nv_bfloat16 d_bf[BF_N];

// ==================== PTX helpers ====================
__device__ __forceinline__ uint32_t smem_u32(const void* p) {
    uint32_t a;
    asm("{ .reg .u64 t; cvta.to.shared.u64 t, %1; cvt.u32.u64 %0, t; }" : "=r"(a) : "l"(p));
    return a;
}
#define CP_ASYNC16(dst, src) \
    asm volatile("cp.async.cg.shared.global [%0], [%1], 16;" :: "r"(dst), "l"(src))
#define CP_COMMIT() asm volatile("cp.async.commit_group;" ::: "memory")
#define CP_WAIT(n)  asm volatile("cp.async.wait_group %0;" :: "n"(n) : "memory")
#define LDSM_X4(r, addr) \
    asm volatile("ldmatrix.sync.aligned.m8n8.x4.shared.b16 {%0,%1,%2,%3}, [%4];" \
                 : "=r"((r)[0]), "=r"((r)[1]), "=r"((r)[2]), "=r"((r)[3]) : "r"(addr))
#define MMA_BF16(d, a, b) \
    asm volatile("mma.sync.aligned.m16n8k16.row.col.f32.bf16.bf16.f32 " \
                 "{%0,%1,%2,%3}, {%4,%5,%6,%7}, {%8,%9}, {%0,%1,%2,%3};" \
                 : "+f"((d)[0]), "+f"((d)[1]), "+f"((d)[2]), "+f"((d)[3]) \
                 : "r"((a)[0]), "r"((a)[1]), "r"((a)[2]), "r"((a)[3]), \
                   "r"((b)[0]), "r"((b)[1]))
// d.lo = lo, d.hi = hi
#define PACK_BF16X2(d, lo, hi) \
    asm("cvt.rn.bf16x2.f32 %0, %1, %2;" : "=r"(d) : "f"(hi), "f"(lo))

// ==================== 3-term split HMMA GEMM (precision-critical) ====================
constexpr int LDT = 40;
constexpr int TILE_B3 = 128 * LDT * 2;            // 10240
constexpr int STAGE_B3 = 4 * TILE_B3;             // 40960
constexpr int G3_SMEM = 3 * STAGE_B3;             // 122880

template<bool BIAS>
__global__ __launch_bounds__(256, 1)
void gemm3(const __nv_bfloat16* __restrict__ AH, const __nv_bfloat16* __restrict__ AL,
           const __nv_bfloat16* __restrict__ BH, const __nv_bfloat16* __restrict__ BL,
           const float* __restrict__ bias, float* __restrict__ C,
           int N, int K) {
    extern __shared__ char smem[];
    const uint32_t sb = smem_u32(smem);
    const int tid = threadIdx.x, wid = tid >> 5, lane = tid & 31;
    const int m0 = blockIdx.y * 128, n0 = blockIdx.x * 128;
    const int warpM = wid & 1, warpN = wid >> 1;
    const int mW = warpM * 64, nW = warpN * 32;

    float acc[4][4][4];
#pragma unroll
    for (int i = 0; i < 4; i++)
#pragma unroll
        for (int j = 0; j < 4; j++)
#pragma unroll
            for (int c = 0; c < 4; c++) acc[i][j][c] = 0.f;

    const __nv_bfloat16* srcs[4] = {AH, AL, BH, BL};

    auto load_stage = [&](int buf, int k0) {
#pragma unroll
        for (int mtx = 0; mtx < 4; mtx++) {
            const __nv_bfloat16* src = srcs[mtx];
            const int rbase = (mtx < 2) ? m0 : n0;
            uint32_t dst = sb + buf * STAGE_B3 + mtx * TILE_B3;
#pragma unroll
            for (int it = 0; it < 2; it++) {
                int c = it * 256 + tid;
                int row = c >> 2, cc = c & 3;
                CP_ASYNC16(dst + (uint32_t)(row * LDT + cc * 8) * 2,
                           src + (size_t)(rbase + row) * K + k0 + cc * 8);
            }
        }
        CP_COMMIT();
    };

    auto a_addr = [&](uint32_t base, int mBase, int k0) -> uint32_t {
        int t = lane >> 3;
        int r = mBase + ((t & 1) << 3) + (lane & 7);
        int c = k0 + ((t >> 1) << 3);
        return base + (uint32_t)(r * LDT + c) * 2;
    };
    auto b_addr = [&](uint32_t base, int nBase, int k0) -> uint32_t {
        int t = lane >> 3;
        int n = nBase + ((t >> 1) << 3) + (lane & 7);
        int c = k0 + ((t & 1) << 3);
        return base + (uint32_t)(n * LDT + c) * 2;
    };

    const int S = K >> 5;
    load_stage(0, 0);
    load_stage(1, 32);

    for (int s = 0; s < S; s++) {
        const int buf = s % 3;
        if (s + 2 < S) { load_stage((s + 2) % 3, (s + 2) << 5); CP_WAIT(2); }
        else if (s + 1 < S) { CP_WAIT(1); }
        else { CP_WAIT(0); }
        __syncthreads();

        const uint32_t aH = sb + buf * STAGE_B3;
        const uint32_t aL = aH + TILE_B3;
        const uint32_t bH = aH + 2 * TILE_B3;
        const uint32_t bL = aH + 3 * TILE_B3;

#pragma unroll
        for (int kk = 0; kk < 2; kk++) {
            const int k0 = kk * 16;
            uint32_t ah[4][4], al[4][4];
#pragma unroll
            for (int mf = 0; mf < 4; mf++) {
                LDSM_X4(ah[mf], a_addr(aH, mW + mf * 16, k0));
                LDSM_X4(al[mf], a_addr(aL, mW + mf * 16, k0));
            }
            uint32_t bh[4][2], bl[4][2];
#pragma unroll
            for (int nf2 = 0; nf2 < 2; nf2++) {
                uint32_t r[4];
                LDSM_X4(r, b_addr(bH, nW + nf2 * 16, k0));
                bh[nf2 * 2][0] = r[0]; bh[nf2 * 2][1] = r[1];
                bh[nf2 * 2 + 1][0] = r[2]; bh[nf2 * 2 + 1][1] = r[3];
                LDSM_X4(r, b_addr(bL, nW + nf2 * 16, k0));
                bl[nf2 * 2][0] = r[0]; bl[nf2 * 2][1] = r[1];
                bl[nf2 * 2 + 1][0] = r[2]; bl[nf2 * 2 + 1][1] = r[3];
            }
#pragma unroll
            for (int mf = 0; mf < 4; mf++)
#pragma unroll
                for (int nf = 0; nf < 4; nf++) {
                    MMA_BF16(acc[mf][nf], ah[mf], bh[nf]);
                    MMA_BF16(acc[mf][nf], ah[mf], bl[nf]);
                    MMA_BF16(acc[mf][nf], al[mf], bh[nf]);
                }
        }
        __syncthreads();
    }

    const int lr = lane >> 2, lc = (lane & 3) * 2;
#pragma unroll
    for (int mf = 0; mf < 4; mf++) {
        int row0 = m0 + mW + mf * 16 + lr;
#pragma unroll
        for (int nf = 0; nf < 4; nf++) {
            int col = n0 + nW + nf * 8 + lc;
            float b0 = 0.f, b1 = 0.f;
            if (BIAS) { b0 = bias[col]; b1 = bias[col + 1]; }
            *reinterpret_cast<float2*>(C + (size_t)row0 * N + col) =
                make_float2(acc[mf][nf][0] + b0, acc[mf][nf][1] + b1);
            *reinterpret_cast<float2*>(C + (size_t)(row0 + 8) * N + col) =
                make_float2(acc[mf][nf][2] + b0, acc[mf][nf][3] + b1);
        }
    }
}

// ==================== single-bf16 HMMA GEMM ====================
// OUTM 0: bf16 out (+bias) into Ch.  OUTM 1: fp32 Cf + split Ch/Cl (+bias).
constexpr int STAGE_B1 = 2 * TILE_B3;             // 20480
constexpr int G1_SMEM = 3 * STAGE_B1;             // 61440

template<int OUTM>
__global__ __launch_bounds__(256, 1)
void gemm1(const __nv_bfloat16* __restrict__ A, const __nv_bfloat16* __restrict__ B,
           const float* __restrict__ bias, float* __restrict__ Cf,
           __nv_bfloat16* __restrict__ Ch, __nv_bfloat16* __restrict__ Cl,
           int N, int K) {
    extern __shared__ char smem[];
    const uint32_t sb = smem_u32(smem);
    const int tid = threadIdx.x, wid = tid >> 5, lane = tid & 31;
    const int m0 = blockIdx.y * 128, n0 = blockIdx.x * 128;
    const int warpM = wid & 1, warpN = wid >> 1;
    const int mW = warpM * 64, nW = warpN * 32;

    float acc[4][4][4];
#pragma unroll
    for (int i = 0; i < 4; i++)
#pragma unroll
        for (int j = 0; j < 4; j++)
#pragma unroll
            for (int c = 0; c < 4; c++) acc[i][j][c] = 0.f;

    auto load_stage = [&](int buf, int k0) {
#pragma unroll
        for (int mtx = 0; mtx < 2; mtx++) {
            const __nv_bfloat16* src = (mtx == 0) ? A : B;
            const int rbase = (mtx == 0) ? m0 : n0;
            uint32_t dst = sb + buf * STAGE_B1 + mtx * TILE_B3;
#pragma unroll
            for (int it = 0; it < 2; it++) {
                int c = it * 256 + tid;
                int row = c >> 2, cc = c & 3;
                CP_ASYNC16(dst + (uint32_t)(row * LDT + cc * 8) * 2,
                           src + (size_t)(rbase + row) * K + k0 + cc * 8);
            }
        }
        CP_COMMIT();
    };

    auto a_addr = [&](uint32_t base, int mBase, int k0) -> uint32_t {
        int t = lane >> 3;
        int r = mBase + ((t & 1) << 3) + (lane & 7);
        int c = k0 + ((t >> 1) << 3);
        return base + (uint32_t)(r * LDT + c) * 2;
    };
    auto b_addr = [&](uint32_t base, int nBase, int k0) -> uint32_t {
        int t = lane >> 3;
        int n = nBase + ((t >> 1) << 3) + (lane & 7);
        int c = k0 + ((t & 1) << 3);
        return base + (uint32_t)(n * LDT + c) * 2;
    };

    const int S = K >> 5;
    load_stage(0, 0);
    load_stage(1, 32);

    for (int s = 0; s < S; s++) {
        const int buf = s % 3;
        if (s + 2 < S) { load_stage((s + 2) % 3, (s + 2) << 5); CP_WAIT(2); }
        else if (s + 1 < S) { CP_WAIT(1); }
        else { CP_WAIT(0); }
        __syncthreads();

        const uint32_t aB = sb + buf * STAGE_B1;
        const uint32_t bB = aB + TILE_B3;

#pragma unroll
        for (int kk = 0; kk < 2; kk++) {
            const int k0 = kk * 16;
            uint32_t af[4][4];
#pragma unroll
            for (int mf = 0; mf < 4; mf++) LDSM_X4(af[mf], a_addr(aB, mW + mf * 16, k0));
            uint32_t bf[4][2];
#pragma unroll
            for (int nf2 = 0; nf2 < 2; nf2++) {
                uint32_t r[4];
                LDSM_X4(r, b_addr(bB, nW + nf2 * 16, k0));
                bf[nf2 * 2][0] = r[0]; bf[nf2 * 2][1] = r[1];
                bf[nf2 * 2 + 1][0] = r[2]; bf[nf2 * 2 + 1][1] = r[3];
            }
#pragma unroll
            for (int mf = 0; mf < 4; mf++)
#pragma unroll
                for (int nf = 0; nf < 4; nf++)
                    MMA_BF16(acc[mf][nf], af[mf], bf[nf]);
        }
        __syncthreads();
    }

    const int lr = lane >> 2, lc = (lane & 3) * 2;
#pragma unroll
    for (int mf = 0; mf < 4; mf++) {
        int row0 = m0 + mW + mf * 16 + lr;
#pragma unroll
        for (int nf = 0; nf < 4; nf++) {
            int col = n0 + nW + nf * 8 + lc;
            float b0 = bias ? bias[col] : 0.f;
            float b1 = bias ? bias[col + 1] : 0.f;
#pragma unroll
            for (int half = 0; half < 2; half++) {
                size_t row = (size_t)(row0 + half * 8);
                float v0 = acc[mf][nf][half * 2] + b0;
                float v1 = acc[mf][nf][half * 2 + 1] + b1;
                if (OUTM == 0) {
                    uint32_t p; PACK_BF16X2(p, v0, v1);
                    *reinterpret_cast<uint32_t*>(Ch + row * N + col) = p;
                } else {
                    *reinterpret_cast<float2*>(Cf + row * N + col) = make_float2(v0, v1);
                    __nv_bfloat16 h0 = __float2bfloat16(v0), h1 = __float2bfloat16(v1);
                    uint32_t ph; PACK_BF16X2(ph, __bfloat162float(h0), __bfloat162float(h1));
                    *reinterpret_cast<uint32_t*>(Ch + row * N + col) = ph;
                    uint32_t pl;
                    PACK_BF16X2(pl, v0 - __bfloat162float(h0), v1 - __bfloat162float(h1));
                    *reinterpret_cast<uint32_t*>(Cl + row * N + col) = pl;
                }
            }
        }
    }
}

// ==================== bf16 HMMA flash attention ====================
// grid = B*H*4; 256 thr (8 warps x 16 q-rows). Q tile 128x64 (r||i),
// K chunks 128x64, V transposed in smem [64][128].
constexpr int ALDQ = 72, ALDK = 72, ALDVT = 136;
constexpr int SQ_OFF = 0;
constexpr int SK_OFF = 128 * ALDQ * 2;
constexpr int SV_OFF = SK_OFF + 128 * ALDK * 2;
constexpr int ATT_SMEM = SV_OFF + 64 * ALDVT * 2;   // 54272

__global__ __launch_bounds__(256, 1)
void attn_mma(const __nv_bfloat16* __restrict__ qkv, __nv_bfloat16* __restrict__ ap) {
    extern __shared__ char smem[];
    __nv_bfloat16* sQ = reinterpret_cast<__nv_bfloat16*>(smem + SQ_OFF);
    __nv_bfloat16* sK = reinterpret_cast<__nv_bfloat16*>(smem + SK_OFF);
    __nv_bfloat16* sVt = reinterpret_cast<__nv_bfloat16*>(smem + SV_OFF);
    const uint32_t sQb = smem_u32(sQ), sKb = smem_u32(sK), sVb = smem_u32(sVt);

    const int bid = blockIdx.x;
    const int qt = bid & 3, h = (bid >> 2) & 7, b = bid >> 5;
    const int tid = threadIdx.x, wid = tid >> 5, lane = tid & 31;
    const size_t tok0 = (size_t)b * L_;
    const int q0 = qt * 128;
    const int hoff = h * 32;

    // load Q tile (rows: 128 q, cols 0..31 = qr, 32..63 = qi)
#pragma unroll
    for (int i = 0; i < 4; i++) {
        int c = i * 256 + tid;
        int row = c >> 3, u = c & 7, seg = u >> 2, j = u & 3;
        uint4 v = *reinterpret_cast<const uint4*>(
            qkv + (tok0 + q0 + row) * 1536 + hoff + seg * 256 + j * 8);
        *reinterpret_cast<uint4*>(sQ + row * ALDQ + seg * 32 + j * 8) = v;
    }
    __syncthreads();

    auto a_addr = [&](uint32_t base, int mBase, int k0, int ld) -> uint32_t {
        int t = lane >> 3;
        int r = mBase + ((t & 1) << 3) + (lane & 7);
        int c = k0 + ((t >> 1) << 3);
        return base + (uint32_t)(r * ld + c) * 2;
    };
    auto b_addr = [&](uint32_t base, int nBase, int k0, int ld) -> uint32_t {
        int t = lane >> 3;
        int n = nBase + ((t >> 1) << 3) + (lane & 7);
        int c = k0 + ((t & 1) << 3);
        return base + (uint32_t)(n * ld + c) * 2;
    };

    // persistent Q fragments (warp's 16 rows x 64 feat)
    uint32_t aQ[4][4];
#pragma unroll
    for (int kf = 0; kf < 4; kf++) LDSM_X4(aQ[kf], a_addr(sQb, wid * 16, kf * 16, ALDQ));

    float O[8][4];
#pragma unroll
    for (int i = 0; i < 8; i++)
#pragma unroll
        for (int c = 0; c < 4; c++) O[i][c] = 0.f;
    float m0r = -1e30f, m1r = -1e30f, l0 = 0.f, l1 = 0.f;
    const float scale = 0.17677669529663687f;

    for (int kc = 0; kc < 4; kc++) {
        __syncthreads();
        // K chunk (kr||ki)
#pragma unroll
        for (int i = 0; i < 4; i++) {
            int c = i * 256 + tid;
            int row = c >> 3, u = c & 7, seg = u >> 2, j = u & 3;
            uint4 v = *reinterpret_cast<const uint4*>(
                qkv + (tok0 + kc * 128 + row) * 1536 + hoff + 512 + seg * 256 + j * 8);
            *reinterpret_cast<uint4*>(sK + row * ALDK + seg * 32 + j * 8) = v;
        }
        // V chunk transposed: sVt[vcol][key]
#pragma unroll
        for (int i = 0; i < 4; i++) {
            int c = i * 256 + tid;
            int s = c >> 3, u = c & 7, seg = u >> 2, j = u & 3;
            uint4 v = *reinterpret_cast<const uint4*>(
                qkv + (tok0 + kc * 128 + s) * 1536 + hoff + 1024 + seg * 256 + j * 8);
            const __nv_bfloat16* pb = reinterpret_cast<const __nv_bfloat16*>(&v);
            int c0 = seg * 32 + j * 8;
#pragma unroll
            for (int jj = 0; jj < 8; jj++) sVt[(c0 + jj) * ALDVT + s] = pb[jj];
        }
        __syncthreads();

        // scores: S (16 rows x 128 keys per warp)
        float S[16][4];
#pragma unroll
        for (int nf = 0; nf < 16; nf++)
#pragma unroll
            for (int c = 0; c < 4; c++) S[nf][c] = 0.f;
#pragma unroll
        for (int kf = 0; kf < 4; kf++) {
#pragma unroll
            for (int nf2 = 0; nf2 < 8; nf2++) {
                uint32_t r[4];
                LDSM_X4(r, b_addr(sKb, nf2 * 16, kf * 16, ALDK));
                uint32_t b01[2] = {r[0], r[1]}, b23[2] = {r[2], r[3]};
                MMA_BF16(S[nf2 * 2], aQ[kf], b01);
                MMA_BF16(S[nf2 * 2 + 1], aQ[kf], b23);
            }
        }
        // online softmax
        float mx0 = -1e30f, mx1 = -1e30f;
#pragma unroll
        for (int nf = 0; nf < 16; nf++) {
#pragma unroll
            for (int c = 0; c < 4; c++) S[nf][c] *= scale;
            mx0 = fmaxf(mx0, fmaxf(S[nf][0], S[nf][1]));
            mx1 = fmaxf(mx1, fmaxf(S[nf][2], S[nf][3]));
        }
        mx0 = fmaxf(mx0, __shfl_xor_sync(0xffffffffu, mx0, 1));
        mx0 = fmaxf(mx0, __shfl_xor_sync(0xffffffffu, mx0, 2));
        mx1 = fmaxf(mx1, __shfl_xor_sync(0xffffffffu, mx1, 1));
        mx1 = fmaxf(mx1, __shfl_xor_sync(0xffffffffu, mx1, 2));
        float mn0 = fmaxf(m0r, mx0), mn1 = fmaxf(m1r, mx1);
        float al0 = __expf(m0r - mn0), al1 = __expf(m1r - mn1);
        m0r = mn0; m1r = mn1;
        float rs0 = 0.f, rs1 = 0.f;
#pragma unroll
        for (int nf = 0; nf < 16; nf++) {
            S[nf][0] = __expf(S[nf][0] - mn0);
            S[nf][1] = __expf(S[nf][1] - mn0);
            S[nf][2] = __expf(S[nf][2] - mn1);
            S[nf][3] = __expf(S[nf][3] - mn1);
            rs0 += S[nf][0] + S[nf][1];
            rs1 += S[nf][2] + S[nf][3];
        }
        rs0 += __shfl_xor_sync(0xffffffffu, rs0, 1);
        rs0 += __shfl_xor_sync(0xffffffffu, rs0, 2);
        rs1 += __shfl_xor_sync(0xffffffffu, rs1, 1);
        rs1 += __shfl_xor_sync(0xffffffffu, rs1, 2);
        l0 = l0 * al0 + rs0;
        l1 = l1 * al1 + rs1;
#pragma unroll
        for (int i = 0; i < 8; i++) {
            O[i][0] *= al0; O[i][1] *= al0; O[i][2] *= al1; O[i][3] *= al1;
        }
        // PV: O += P @ V
#pragma unroll
        for (int t = 0; t < 8; t++) {
            uint32_t pa[4];
            PACK_BF16X2(pa[0], S[2 * t][0], S[2 * t][1]);
            PACK_BF16X2(pa[1], S[2 * t][2], S[2 * t][3]);
            PACK_BF16X2(pa[2], S[2 * t + 1][0], S[2 * t + 1][1]);
            PACK_BF16X2(pa[3], S[2 * t + 1][2], S[2 * t + 1][3]);
#pragma unroll
            for (int vn2 = 0; vn2 < 4; vn2++) {
                uint32_t r[4];
                LDSM_X4(r, b_addr(sVb, vn2 * 16, t * 16, ALDVT));
                uint32_t b01[2] = {r[0], r[1]}, b23[2] = {r[2], r[3]};
                MMA_BF16(O[vn2 * 2], pa, b01);
                MMA_BF16(O[vn2 * 2 + 1], pa, b23);
            }
        }
    }

    // epilogue: write ar -> ap[tok][hoff + c], ai -> ap[tok][256 + hoff + c-32]
    float i0 = 1.f / l0, i1 = 1.f / l1;
    const int r = lane >> 2, cq = (lane & 3) * 2;
#pragma unroll
    for (int onf = 0; onf < 8; onf++) {
        int vc = onf * 8 + cq;
        int off = (vc < 32) ? (hoff + vc) : (256 + hoff + vc - 32);
#pragma unroll
        for (int half = 0; half < 2; half++) {
            size_t token = tok0 + q0 + wid * 16 + r + half * 8;
            float inv = half ? i1 : i0;
            uint32_t p;
            PACK_BF16X2(p, O[onf][half * 2] * inv, O[onf][half * 2 + 1] * inv);
            *reinterpret_cast<uint32_t*>(ap + token * 512 + off) = p;
        }
    }
}

// ---------------- fp32 SGEMM (tiny matrices) ----------------
template<bool BIAS>
__global__ __launch_bounds__(256)
void gemm_nt(const float* __restrict__ A, const float* __restrict__ W,
             const float* __restrict__ bias, float* __restrict__ C,
             int M, int N, int K) {
    __shared__ float As[8][129];
    __shared__ float Ws[8][129];
    const int tid = threadIdx.x;
    const int tx = tid & 15, ty = tid >> 4;
    const int m0 = blockIdx.y * 128, n0 = blockIdx.x * 128;
    const int lm = tid >> 1, lh = tid & 1;

    float acc[8][8];
#pragma unroll
    for (int i = 0; i < 8; i++)
#pragma unroll
        for (int j = 0; j < 8; j++) acc[i][j] = 0.f;

    for (int k0 = 0; k0 < K; k0 += 8) {
        float4 av = make_float4(0.f, 0.f, 0.f, 0.f);
        float4 wv = make_float4(0.f, 0.f, 0.f, 0.f);
        int gm = m0 + lm;
        if (gm < M) av = *reinterpret_cast<const float4*>(A + (long long)gm * K + k0 + lh * 4);
        int gn = n0 + lm;
        if (gn < N) wv = *reinterpret_cast<const float4*>(W + (long long)gn * K + k0 + lh * 4);
        __syncthreads();
        As[lh * 4 + 0][lm] = av.x; As[lh * 4 + 1][lm] = av.y;
        As[lh * 4 + 2][lm] = av.z; As[lh * 4 + 3][lm] = av.w;
        Ws[lh * 4 + 0][lm] = wv.x; Ws[lh * 4 + 1][lm] = wv.y;
        Ws[lh * 4 + 2][lm] = wv.z; Ws[lh * 4 + 3][lm] = wv.w;
        __syncthreads();
#pragma unroll
        for (int kk = 0; kk < 8; kk++) {
            float ra[8], rw[8];
#pragma unroll
            for (int i = 0; i < 8; i++) ra[i] = As[kk][ty + 16 * i];
#pragma unroll
            for (int j = 0; j < 8; j++) rw[j] = Ws[kk][tx + 16 * j];
#pragma unroll
            for (int i = 0; i < 8; i++)
#pragma unroll
                for (int j = 0; j < 8; j++) acc[i][j] += ra[i] * rw[j];
        }
    }
#pragma unroll
    for (int i = 0; i < 8; i++) {
        int gm = m0 + ty + 16 * i;
        if (gm >= M) continue;
#pragma unroll
        for (int j = 0; j < 8; j++) {
            int gn = n0 + tx + 16 * j;
            if (gn >= N) continue;
            float v = acc[i][j];
            if (BIAS) v += bias[gn];
            C[(long long)gm * N + gn] = v;
        }
    }
}

// ---------------- prep kernels ----------------
__global__ void embed_bf_k(const int* __restrict__ tok, const float* __restrict__ emb,
                           __nv_bfloat16* __restrict__ x) {
    long long t = (long long)blockIdx.x * blockDim.x + threadIdx.x;
    if (t >= BLD_) return;
    int token = (int)(t >> 8), d = (int)(t & 255);
    x[t] = __float2bfloat16(emb[(long long)tok[token] * D_ + d]);
}

__global__ void split_k(const float* __restrict__ x, __nv_bfloat16* __restrict__ hi,
                        __nv_bfloat16* __restrict__ lo, long long n) {
    long long t = (long long)blockIdx.x * blockDim.x + threadIdx.x;
    if (t >= n) return;
    float v = x[t];
    __nv_bfloat16 h = __float2bfloat16(v);
    hi[t] = h;
    lo[t] = __float2bfloat16(v - __bfloat162float(h));
}

__global__ void build_wq_bf_k(const float* __restrict__ awr, const float* __restrict__ awi,
                              __nv_bfloat16* __restrict__ w) {
    long long t = (long long)blockIdx.x * blockDim.x + threadIdx.x;
    if (t >= 1536LL * 256) return;
    int n = (int)(t >> 8), k = (int)(t & 255);
    int seg = n >> 8, j = n & 255, proj = seg >> 1;
    float v = ((seg & 1) == 0) ? awr[((long long)proj * 256 + j) * 256 + k]
                               : awi[((long long)proj * 256 + j) * 256 + k];
    w[t] = __float2bfloat16(v);
}

__global__ void build_bqkv_k(const float* __restrict__ abr, const float* __restrict__ abi,
                             float* __restrict__ bq) {
    int t = blockIdx.x * blockDim.x + threadIdx.x;
    if (t >= 1536) return;
    int seg = t >> 8, j = t & 255, proj = seg >> 1;
    float r = abr[proj * 256 + j], i2 = abi[proj * 256 + j];
    bq[t] = ((seg & 1) == 0) ? (r - i2) : (r + i2);
}

// WZ (256x512): row n: [Wr3[n][:], -Wi3[n][:]]
__global__ void build_wz_bf_k(const float* __restrict__ awr, const float* __restrict__ awi,
                              __nv_bfloat16* __restrict__ w) {
    long long t = (long long)blockIdx.x * blockDim.x + threadIdx.x;
    if (t >= 256LL * 512) return;
    int n = (int)(t >> 9), k = (int)(t & 511);
    float v = (k < 256) ? awr[(768LL + n) * 256 + k] : -awi[(768LL + n) * 256 + (k - 256)];
    w[t] = __float2bfloat16(v);
}

__global__ void build_bzr_k(const float* __restrict__ abr, const float* __restrict__ abi,
                            float* __restrict__ bz) {
    int t = blockIdx.x * blockDim.x + threadIdx.x;
    if (t < 256) bz[t] = abr[768 + t] - abi[768 + t];
}

__global__ void pack_w_k(const float* __restrict__ gw, float* __restrict__ wev,
                         float* __restrict__ wct) {
    int t = blockIdx.x * blockDim.x + threadIdx.x;
    if (t >= D_ * D_) return;
    int d = t >> 8, j = t & 255;
    wev[t] = gw[d * 3 * D_ + 2 * j];
    wct[t] = gw[d * 3 * D_ + 2 * D_ + j];
}

__global__ void enorm_k(const float* __restrict__ E, float* __restrict__ en) {
    int k = threadIdx.x;
    if (k >= KC_) return;
    float a = 0.f;
    for (int d = 0; d < D_; d++) { float e = E[k * D_ + d]; a += e * e; }
    en[k] = a;
}

// ---------------- VQ argmin + loss ----------------
__global__ void vq_argmin_k(const float* __restrict__ dot, const float* __restrict__ en,
                            const float* __restrict__ Z, const float* __restrict__ E,
                            int* __restrict__ idx_out, float* __restrict__ part) {
    int tkn = blockIdx.x;
    int k = threadIdx.x;
    __shared__ float sv[128];
    __shared__ int si[128];
    float v = en[k] - 2.f * dot[(long long)tkn * KC_ + k];
    sv[k] = v; si[k] = k;
    __syncthreads();
    for (int s = 64; s > 0; s >>= 1) {
        if (k < s) {
            float a = sv[k], b2 = sv[k + s];
            if (b2 < a || (b2 == a && si[k + s] < si[k])) { sv[k] = b2; si[k] = si[k + s]; }
        }
        __syncthreads();
    }
    int best = si[0];
    if (k == 0) idx_out[tkn] = best;
    __syncthreads();
    float acc = 0.f;
    for (int d = k; d < D_; d += 128) {
        float diff = E[(long long)best * D_ + d] - Z[(long long)tkn * 256 + d];
        acc += diff * diff;
    }
    sv[k] = acc;
    __syncthreads();
    for (int s = 64; s > 0; s >>= 1) {
        if (k < s) sv[k] += sv[k + s];
        __syncthreads();
    }
    if (k == 0) part[tkn] = sv[0];
}

__global__ void vq_reduce_k(const float* __restrict__ part, float* __restrict__ out_loss) {
    __shared__ float s[256];
    float a = 0.f;
    for (int i = threadIdx.x; i < BL_; i += 256) a += part[i];
    s[threadIdx.x] = a;
    __syncthreads();
    for (int st = 128; st > 0; st >>= 1) {
        if (threadIdx.x < st) s[threadIdx.x] += s[threadIdx.x + st];
        __syncthreads();
    }
    if (threadIdx.x == 0) out_loss[0] = 2.f * s[0] / (float)BLD_;
}

// ---------------- gate / stack / layernorm+modrelu ----------------
__global__ void gate_k(const float* __restrict__ G, const float* __restrict__ Cg,
                       const int* __restrict__ idx, float* __restrict__ gated) {
    long long t = (long long)blockIdx.x * blockDim.x + threadIdx.x;
    if (t >= BLD_) return;
    int d = (int)(t & 255);
    int tkn = (int)(t >> 8);
    int b = tkn >> 9;
    float x = G[(long long)idx[tkn] * D_ + d] + Cg[b * D_ + d];
    gated[t] = 1.f / (1.f + expf(-x));
}

__global__ void stack_k(const float* __restrict__ gated, float* __restrict__ stk,
                        float* __restrict__ out_stk) {
    int b = blockIdx.x, d = threadIdx.x;
    float s = 0.f;
    for (int l = 0; l < L_; l++) s += gated[((long long)b * L_ + l) * D_ + d];
    stk[b * D_ + d] = s;
    out_stk[b * D_ + d] = s;
}

__global__ void ln_modrelu_k(const float* __restrict__ gated, const float* __restrict__ stk,
                             const float* __restrict__ lg, const float* __restrict__ lb,
                             const float* __restrict__ ib, const float* __restrict__ mb,
                             __nv_bfloat16* __restrict__ YH, __nv_bfloat16* __restrict__ YL) {
    int tkn = blockIdx.x;
    int b = tkn >> 9;
    int d = threadIdx.x;
    __shared__ float red[256];
    float x = gated[(long long)tkn * D_ + d] + stk[b * D_ + d];
    red[d] = x;
    __syncthreads();
    for (int s = 128; s > 0; s >>= 1) {
        if (d < s) red[d] += red[d + s];
        __syncthreads();
    }
    float mu = red[0] * (1.f / 256.f);
    __syncthreads();
    float diff = x - mu;
    red[d] = diff * diff;
    __syncthreads();
    for (int s = 128; s > 0; s >>= 1) {
        if (d < s) red[d] += red[d + s];
        __syncthreads();
    }
    float var = red[0] * (1.f / 256.f);
    float nr = diff * (1.f / sqrtf(var + 1e-5f)) * lg[d] + lb[d];
    float ni = ib[d];
    float mag = sqrtf(nr * nr + ni * ni);
    float sc = fmaxf(mag + mb[d], 0.f) / (mag + 1e-6f);
    float y = nr * sc;
    __nv_bfloat16 h = __float2bfloat16(y);
    YH[(long long)tkn * D_ + d] = h;
    YL[(long long)tkn * D_ + d] = __float2bfloat16(y - __bfloat162float(h));
}

// ---------------- host launch ----------------
extern "C" void kernel_launch(void* const* d_in, const int* in_sizes, int n_in,
                              void* d_out, int out_size) {
    const int*   tokens = (const int*)d_in[0];
    const float* context = (const float*)d_in[1];
    const float* emb = (const float*)d_in[2];
    const float* awr = (const float*)d_in[3];
    const float* awi = (const float*)d_in[4];
    const float* abr = (const float*)d_in[5];
    const float* abi = (const float*)d_in[6];
    const float* vqe = (const float*)d_in[7];
    const float* gw  = (const float*)d_in[8];
    const float* gb  = (const float*)d_in[9];
    const float* lrg = (const float*)d_in[10];
    const float* lrb = (const float*)d_in[11];
    const float* lib = (const float*)d_in[13];
    const float* mrb = (const float*)d_in[14];
    const float* hw  = (const float*)d_in[15];
    const float* hb  = (const float*)d_in[16];
    float* out = (float*)d_out;

    float* S; cudaGetSymbolAddress((void**)&S, d_scratch);
    __nv_bfloat16* BF; cudaGetSymbolAddress((void**)&BF, d_bf);
    int* idxb; cudaGetSymbolAddress((void**)&idxb, d_idxbuf);

    cudaFuncSetAttribute(gemm3<true>,  cudaFuncAttributeMaxDynamicSharedMemorySize, G3_SMEM);
    cudaFuncSetAttribute(gemm3<false>, cudaFuncAttributeMaxDynamicSharedMemorySize, G3_SMEM);
    cudaFuncSetAttribute(gemm1<0>, cudaFuncAttributeMaxDynamicSharedMemorySize, G1_SMEM);
    cudaFuncSetAttribute(gemm1<1>, cudaFuncAttributeMaxDynamicSharedMemorySize, G1_SMEM);
    cudaFuncSetAttribute(attn_mma, cudaFuncAttributeMaxDynamicSharedMemorySize, ATT_SMEM);

    float* Z    = S + OFF_Z;
    float* DOT  = S + OFF_DOT;
    float* GT   = S + OFF_GATED;
    float* G    = S + OFF_G;
    float* Cg   = S + OFF_CG;
    float* wev  = S + OFF_WEV;
    float* wct  = S + OFF_WCT;
    float* stk  = S + OFF_STK;
    float* en   = S + OFF_EN;
    float* part = S + OFF_PART;
    float* bqkv = S + OFF_BQKV;
    float* bzr  = S + OFF_BZR;

    __nv_bfloat16* XBF  = BF + BF_X;
    __nv_bfloat16* WQBF = BF + BF_WQ;
    __nv_bfloat16* QKVB = BF + BF_QKV;
    __nv_bfloat16* APB  = BF + BF_AP;
    __nv_bfloat16* WZBF = BF + BF_WZ;
    __nv_bfloat16* ZH   = BF + BF_ZH;  __nv_bfloat16* ZL  = BF + BF_ZL;
    __nv_bfloat16* VQH  = BF + BF_VQH; __nv_bfloat16* VQL = BF + BF_VQL;
    __nv_bfloat16* YH   = BF + BF_YH;  __nv_bfloat16* YL  = BF + BF_YL;
    __nv_bfloat16* HWH  = BF + BF_HWH; __nv_bfloat16* HWL = BF + BF_HWL;

    // prep
    build_bqkv_k<<<6, 256>>>(abr, abi, bqkv);
    build_bzr_k<<<1, 256>>>(abr, abi, bzr);
    build_wq_bf_k<<<(int)((1536LL * 256 + 255) / 256), 256>>>(awr, awi, WQBF);
    build_wz_bf_k<<<(int)((256LL * 512 + 255) / 256), 256>>>(awr, awi, WZBF);
    split_k<<<(int)(((long long)KC_ * D_ + 255) / 256), 256>>>(vqe, VQH, VQL, (long long)KC_ * D_);
    split_k<<<(int)(((long long)V_ * D_ + 255) / 256), 256>>>(hw, HWH, HWL, (long long)V_ * D_);
    pack_w_k<<<(D_ * D_ + 255) / 256, 256>>>(gw, wev, wct);
    enorm_k<<<1, 128>>>(vqe, en);
    embed_bf_k<<<(int)((BLD_ + 255) / 256), 256>>>(tokens, emb, XBF);

    // QKV GEMM (single bf16) -> bf16 packed QKV
    gemm1<0><<<dim3(1536 / 128, BL_ / 128), 256, G1_SMEM>>>(
        XBF, WQBF, bqkv, nullptr, QKVB, nullptr, 1536, 256);

    // flash attention (bf16 HMMA)
    attn_mma<<<B_ * H_ * 4, 256, ATT_SMEM>>>(QKVB, APB);

    // out clinear (single bf16, real part only): Z fp32 + ZH/ZL split
    gemm1<1><<<dim3(256 / 128, BL_ / 128), 256, G1_SMEM>>>(
        APB, WZBF, bzr, Z, ZH, ZL, 256, 512);

    // VQ dot (split, precision-critical for argmin)
    gemm3<false><<<dim3(1, BL_ / 128), 256, G3_SMEM>>>(
        ZH, ZL, VQH, VQL, nullptr, DOT, KC_, 256);
    vq_argmin_k<<<BL_, 128>>>(DOT, en, Z, vqe, idxb, part);
    vq_reduce_k<<<1, 256>>>(part, out + BLV_);

    // gate tables
    gemm_nt<false><<<dim3(2, 1), 256>>>(vqe, wev, nullptr, G, KC_, D_, D_);
    gemm_nt<true><<<dim3(2, 1), 256>>>(context, wct, gb, Cg, B_, D_, D_);

    // gate, stack, layernorm+modrelu (fused split output)
    gate_k<<<(int)((BLD_ + 255) / 256), 256>>>(G, Cg, idxb, GT);
    stack_k<<<B_, D_>>>(GT, stk, out + BLV_ + 1);
    ln_modrelu_k<<<BL_, D_>>>(GT, stk, lrg, lrb, lib, mrb, YH, YL);

    // head GEMM (split, precision-critical): logits
    gemm3<true><<<dim3(V_ / 128, BL_ / 128), 256, G3_SMEM>>>(
        YH, YL, HWH, HWL, hb, out, V_, 256);
}

// round 5
// speedup vs baseline: 4.9285x; 1.0850x over previous
#include <cuda_runtime.h>
#include <cuda_bf16.h>
#include <cstdint>
#include <math.h>

// ---------------- problem dims ----------------
constexpr int B_ = 32, L_ = 512, D_ = 256, H_ = 8, V_ = 4096, KC_ = 128;
constexpr int BL_ = B_ * L_;                 // 16384
constexpr long long BLD_ = (long long)BL_ * D_;   // 4194304
constexpr long long BLV_ = (long long)BL_ * V_;   // 67108864

// ---------------- fp32 scratch ----------------
constexpr long long OFF_Z     = 0;                               // BL*256
constexpr long long OFF_DOT   = OFF_Z + (long long)BL_ * 256;    // BL*128
constexpr long long OFF_GATED = OFF_DOT + (long long)BL_ * KC_;  // BLD
constexpr long long OFF_G     = OFF_GATED + BLD_;                // 128*256
constexpr long long OFF_CG    = OFF_G + (long long)KC_ * D_;     // 32*256
constexpr long long OFF_WEV   = OFF_CG + (long long)B_ * D_;
constexpr long long OFF_WCT   = OFF_WEV + (long long)D_ * D_;
constexpr long long OFF_STK   = OFF_WCT + (long long)D_ * D_;
constexpr long long OFF_EN    = OFF_STK + (long long)B_ * D_;
constexpr long long OFF_PART  = OFF_EN + KC_;
constexpr long long OFF_BQKV  = OFF_PART + BL_;
constexpr long long OFF_BZR   = OFF_BQKV + 1536;
constexpr long long OFF_PART2 = OFF_BZR + 256;                   // 32*8*256
constexpr long long SCRATCH_N = OFF_PART2 + 32LL * 8 * 256 + 64;

__device__ float d_scratch[SCRATCH_N];
__device__ int   d_idxbuf[BL_];

// ---------------- bf16 scratch ----------------
constexpr long long BF_X    = 0;                                // BLD
constexpr long long BF_WQ   = BF_X + BLD_;                      // 1536*256
constexpr long long BF_QKV  = BF_WQ + 1536LL * 256;             // BL*1536
constexpr long long BF_AP   = BF_QKV + (long long)BL_ * 1536;   // BL*512
constexpr long long BF_WZ   = BF_AP + (long long)BL_ * 512;     // 256*512
constexpr long long BF_ZH   = BF_WZ + 256LL * 512;              // BLD
constexpr long long BF_ZL   = BF_ZH + BLD_;
constexpr long long BF_VQH  = BF_ZL + BLD_;                     // 128*256
constexpr long long BF_VQL  = BF_VQH + (long long)KC_ * D_;
constexpr long long BF_YH   = BF_VQL + (long long)KC_ * D_;     // BLD
constexpr long long BF_YL   = BF_YH + BLD_;
constexpr long long BF_HWH  = BF_YL + BLD_;                     // V*D
constexpr long long BF_HWL  = BF_HWH + (long long)V_ * D_;
constexpr long long BF_N    = BF_HWL + (long long)V_ * D_ + 64;

__device__ __nv_bfloat16 d_bf[BF_N];

// ==================== PTX helpers ====================
__device__ __forceinline__ uint32_t smem_u32(const void* p) {
    uint32_t a;
    asm("{ .reg .u64 t; cvta.to.shared.u64 t, %1; cvt.u32.u64 %0, t; }" : "=r"(a) : "l"(p));
    return a;
}
#define CP_ASYNC16(dst, src) \
    asm volatile("cp.async.cg.shared.global [%0], [%1], 16;" :: "r"(dst), "l"(src))
#define CP_COMMIT() asm volatile("cp.async.commit_group;" ::: "memory")
#define CP_WAIT(n)  asm volatile("cp.async.wait_group %0;" :: "n"(n) : "memory")
#define LDSM_X4(r, addr) \
    asm volatile("ldmatrix.sync.aligned.m8n8.x4.shared.b16 {%0,%1,%2,%3}, [%4];" \
                 : "=r"((r)[0]), "=r"((r)[1]), "=r"((r)[2]), "=r"((r)[3]) : "r"(addr))
#define MMA_BF16(d, a, b) \
    asm volatile("mma.sync.aligned.m16n8k16.row.col.f32.bf16.bf16.f32 " \
                 "{%0,%1,%2,%3}, {%4,%5,%6,%7}, {%8,%9}, {%0,%1,%2,%3};" \
                 : "+f"((d)[0]), "+f"((d)[1]), "+f"((d)[2]), "+f"((d)[3]) \
                 : "r"((a)[0]), "r"((a)[1]), "r"((a)[2]), "r"((a)[3]), \
                   "r"((b)[0]), "r"((b)[1]))
// d.lo = lo, d.hi = hi
#define PACK_BF16X2(d, lo, hi) \
    asm("cvt.rn.bf16x2.f32 %0, %1, %2;" : "=r"(d) : "f"(hi), "f"(lo))

constexpr int LDT = 40;                         // padded row stride (bf16)

// ==================== 3-term split HMMA GEMM, 256x128 CTA tile ====================
// C[M,N] = (AH+AL)[M,K] @ (BH+BL)[N,K]^T (+bias), fp32 accum.
// 8 warps as 4M x 2N (warp tile 64x64), K-slab 32, 3-stage cp.async.
constexpr int T3_A = 256 * LDT * 2;             // 20480
constexpr int T3_B = 128 * LDT * 2;             // 10240
constexpr int STAGE3 = 2 * T3_A + 2 * T3_B;     // 61440: AH, AL, BH, BL
constexpr int G3_SMEM = 3 * STAGE3;             // 184320

template<bool BIAS>
__global__ __launch_bounds__(256, 1)
void gemm3(const __nv_bfloat16* __restrict__ AH, const __nv_bfloat16* __restrict__ AL,
           const __nv_bfloat16* __restrict__ BH, const __nv_bfloat16* __restrict__ BL,
           const float* __restrict__ bias, float* __restrict__ C,
           int N, int K) {
    extern __shared__ char smem[];
    const uint32_t sb = smem_u32(smem);
    const int tid = threadIdx.x, wid = tid >> 5, lane = tid & 31;
    const int m0 = blockIdx.y * 256, n0 = blockIdx.x * 128;
    const int mW = (wid & 3) * 64, nW = (wid >> 2) * 64;

    float acc[4][8][4];
#pragma unroll
    for (int i = 0; i < 4; i++)
#pragma unroll
        for (int j = 0; j < 8; j++)
#pragma unroll
            for (int c = 0; c < 4; c++) acc[i][j][c] = 0.f;

    auto load_stage = [&](int buf, int k0) {
        const uint32_t st = sb + buf * STAGE3;
        // A tiles: 256 rows x 32 cols, AH then AL
#pragma unroll
        for (int half = 0; half < 2; half++) {
            const __nv_bfloat16* src = half ? AL : AH;
            uint32_t dst = st + half * T3_A;
#pragma unroll
            for (int it = 0; it < 4; it++) {
                int c = it * 256 + tid;                // 0..1023
                int row = c >> 2, cc = c & 3;
                CP_ASYNC16(dst + (uint32_t)(row * LDT + cc * 8) * 2,
                           src + (size_t)(m0 + row) * K + k0 + cc * 8);
            }
        }
        // B tiles: 128 rows x 32 cols
#pragma unroll
        for (int half = 0; half < 2; half++) {
            const __nv_bfloat16* src = half ? BL : BH;
            uint32_t dst = st + 2 * T3_A + half * T3_B;
#pragma unroll
            for (int it = 0; it < 2; it++) {
                int c = it * 256 + tid;                // 0..511
                int row = c >> 2, cc = c & 3;
                CP_ASYNC16(dst + (uint32_t)(row * LDT + cc * 8) * 2,
                           src + (size_t)(n0 + row) * K + k0 + cc * 8);
            }
        }
        CP_COMMIT();
    };

    auto a_addr = [&](uint32_t base, int mBase, int k0) -> uint32_t {
        int t = lane >> 3;
        int r = mBase + ((t & 1) << 3) + (lane & 7);
        int c = k0 + ((t >> 1) << 3);
        return base + (uint32_t)(r * LDT + c) * 2;
    };
    auto b_addr = [&](uint32_t base, int nBase, int k0) -> uint32_t {
        int t = lane >> 3;
        int n = nBase + ((t >> 1) << 3) + (lane & 7);
        int c = k0 + ((t & 1) << 3);
        return base + (uint32_t)(n * LDT + c) * 2;
    };

    const int S = K >> 5;
    load_stage(0, 0);
    load_stage(1, 32);

    for (int s = 0; s < S; s++) {
        const int buf = s % 3;
        if (s + 2 < S) { load_stage((s + 2) % 3, (s + 2) << 5); CP_WAIT(2); }
        else if (s + 1 < S) { CP_WAIT(1); }
        else { CP_WAIT(0); }
        __syncthreads();

        const uint32_t aHs = sb + buf * STAGE3;
        const uint32_t aLs = aHs + T3_A;
        const uint32_t bHs = aHs + 2 * T3_A;
        const uint32_t bLs = bHs + T3_B;

#pragma unroll
        for (int kk = 0; kk < 2; kk++) {
            const int k0 = kk * 16;
            uint32_t ah[4][4], al[4][4];
#pragma unroll
            for (int mf = 0; mf < 4; mf++) {
                LDSM_X4(ah[mf], a_addr(aHs, mW + mf * 16, k0));
                LDSM_X4(al[mf], a_addr(aLs, mW + mf * 16, k0));
            }
#pragma unroll
            for (int nf2 = 0; nf2 < 4; nf2++) {
                uint32_t rh[4], rl[4];
                LDSM_X4(rh, b_addr(bHs, nW + nf2 * 16, k0));
                LDSM_X4(rl, b_addr(bLs, nW + nf2 * 16, k0));
                uint32_t bh01[2] = {rh[0], rh[1]}, bh23[2] = {rh[2], rh[3]};
                uint32_t bl01[2] = {rl[0], rl[1]}, bl23[2] = {rl[2], rl[3]};
#pragma unroll
                for (int mf = 0; mf < 4; mf++) {
                    MMA_BF16(acc[mf][nf2 * 2], ah[mf], bh01);
                    MMA_BF16(acc[mf][nf2 * 2 + 1], ah[mf], bh23);
                    MMA_BF16(acc[mf][nf2 * 2], ah[mf], bl01);
                    MMA_BF16(acc[mf][nf2 * 2 + 1], ah[mf], bl23);
                    MMA_BF16(acc[mf][nf2 * 2], al[mf], bh01);
                    MMA_BF16(acc[mf][nf2 * 2 + 1], al[mf], bh23);
                }
            }
        }
        __syncthreads();
    }

    const int lr = lane >> 2, lc = (lane & 3) * 2;
#pragma unroll
    for (int mf = 0; mf < 4; mf++) {
        int row0 = m0 + mW + mf * 16 + lr;
#pragma unroll
        for (int nf = 0; nf < 8; nf++) {
            int col = n0 + nW + nf * 8 + lc;
            float b0 = 0.f, b1 = 0.f;
            if (BIAS) { b0 = bias[col]; b1 = bias[col + 1]; }
            *reinterpret_cast<float2*>(C + (size_t)row0 * N + col) =
                make_float2(acc[mf][nf][0] + b0, acc[mf][nf][1] + b1);
            *reinterpret_cast<float2*>(C + (size_t)(row0 + 8) * N + col) =
                make_float2(acc[mf][nf][2] + b0, acc[mf][nf][3] + b1);
        }
    }
}

// ==================== single-bf16 HMMA GEMM (128x128) ====================
// OUTM 0: bf16 out (+bias) into Ch.  OUTM 1: fp32 Cf + split Ch/Cl (+bias).
constexpr int TILE_B1 = 128 * LDT * 2;            // 10240
constexpr int STAGE_B1 = 2 * TILE_B1;             // 20480
constexpr int G1_SMEM = 3 * STAGE_B1;             // 61440

template<int OUTM>
__global__ __launch_bounds__(256, 1)
void gemm1(const __nv_bfloat16* __restrict__ A, const __nv_bfloat16* __restrict__ B,
           const float* __restrict__ bias, float* __restrict__ Cf,
           __nv_bfloat16* __restrict__ Ch, __nv_bfloat16* __restrict__ Cl,
           int N, int K) {
    extern __shared__ char smem[];
    const uint32_t sb = smem_u32(smem);
    const int tid = threadIdx.x, wid = tid >> 5, lane = tid & 31;
    const int m0 = blockIdx.y * 128, n0 = blockIdx.x * 128;
    const int warpM = wid & 1, warpN = wid >> 1;
    const int mW = warpM * 64, nW = warpN * 32;

    float acc[4][4][4];
#pragma unroll
    for (int i = 0; i < 4; i++)
#pragma unroll
        for (int j = 0; j < 4; j++)
#pragma unroll
            for (int c = 0; c < 4; c++) acc[i][j][c] = 0.f;

    auto load_stage = [&](int buf, int k0) {
#pragma unroll
        for (int mtx = 0; mtx < 2; mtx++) {
            const __nv_bfloat16* src = (mtx == 0) ? A : B;
            const int rbase = (mtx == 0) ? m0 : n0;
            uint32_t dst = sb + buf * STAGE_B1 + mtx * TILE_B1;
#pragma unroll
            for (int it = 0; it < 2; it++) {
                int c = it * 256 + tid;
                int row = c >> 2, cc = c & 3;
                CP_ASYNC16(dst + (uint32_t)(row * LDT + cc * 8) * 2,
                           src + (size_t)(rbase + row) * K + k0 + cc * 8);
            }
        }
        CP_COMMIT();
    };

    auto a_addr = [&](uint32_t base, int mBase, int k0) -> uint32_t {
        int t = lane >> 3;
        int r = mBase + ((t & 1) << 3) + (lane & 7);
        int c = k0 + ((t >> 1) << 3);
        return base + (uint32_t)(r * LDT + c) * 2;
    };
    auto b_addr = [&](uint32_t base, int nBase, int k0) -> uint32_t {
        int t = lane >> 3;
        int n = nBase + ((t >> 1) << 3) + (lane & 7);
        int c = k0 + ((t & 1) << 3);
        return base + (uint32_t)(n * LDT + c) * 2;
    };

    const int S = K >> 5;
    load_stage(0, 0);
    load_stage(1, 32);

    for (int s = 0; s < S; s++) {
        const int buf = s % 3;
        if (s + 2 < S) { load_stage((s + 2) % 3, (s + 2) << 5); CP_WAIT(2); }
        else if (s + 1 < S) { CP_WAIT(1); }
        else { CP_WAIT(0); }
        __syncthreads();

        const uint32_t aB = sb + buf * STAGE_B1;
        const uint32_t bB = aB + TILE_B1;

#pragma unroll
        for (int kk = 0; kk < 2; kk++) {
            const int k0 = kk * 16;
            uint32_t af[4][4];
#pragma unroll
            for (int mf = 0; mf < 4; mf++) LDSM_X4(af[mf], a_addr(aB, mW + mf * 16, k0));
            uint32_t bf[4][2];
#pragma unroll
            for (int nf2 = 0; nf2 < 2; nf2++) {
                uint32_t r[4];
                LDSM_X4(r, b_addr(bB, nW + nf2 * 16, k0));
                bf[nf2 * 2][0] = r[0]; bf[nf2 * 2][1] = r[1];
                bf[nf2 * 2 + 1][0] = r[2]; bf[nf2 * 2 + 1][1] = r[3];
            }
#pragma unroll
            for (int mf = 0; mf < 4; mf++)
#pragma unroll
                for (int nf = 0; nf < 4; nf++)
                    MMA_BF16(acc[mf][nf], af[mf], bf[nf]);
        }
        __syncthreads();
    }

    const int lr = lane >> 2, lc = (lane & 3) * 2;
#pragma unroll
    for (int mf = 0; mf < 4; mf++) {
        int row0 = m0 + mW + mf * 16 + lr;
#pragma unroll
        for (int nf = 0; nf < 4; nf++) {
            int col = n0 + nW + nf * 8 + lc;
            float b0 = bias ? bias[col] : 0.f;
            float b1 = bias ? bias[col + 1] : 0.f;
#pragma unroll
            for (int half = 0; half < 2; half++) {
                size_t row = (size_t)(row0 + half * 8);
                float v0 = acc[mf][nf][half * 2] + b0;
                float v1 = acc[mf][nf][half * 2 + 1] + b1;
                if (OUTM == 0) {
                    uint32_t p; PACK_BF16X2(p, v0, v1);
                    *reinterpret_cast<uint32_t*>(Ch + row * N + col) = p;
                } else {
                    *reinterpret_cast<float2*>(Cf + row * N + col) = make_float2(v0, v1);
                    __nv_bfloat16 h0 = __float2bfloat16(v0), h1 = __float2bfloat16(v1);
                    uint32_t ph; PACK_BF16X2(ph, __bfloat162float(h0), __bfloat162float(h1));
                    *reinterpret_cast<uint32_t*>(Ch + row * N + col) = ph;
                    uint32_t pl;
                    PACK_BF16X2(pl, v0 - __bfloat162float(h0), v1 - __bfloat162float(h1));
                    *reinterpret_cast<uint32_t*>(Cl + row * N + col) = pl;
                }
            }
        }
    }
}

// ==================== bf16 HMMA flash attention ====================
constexpr int ALDQ = 72, ALDK = 72, ALDVT = 136;
constexpr int SQ_OFF = 0;
constexpr int SK_OFF = 128 * ALDQ * 2;
constexpr int SV_OFF = SK_OFF + 128 * ALDK * 2;
constexpr int ATT_SMEM = SV_OFF + 64 * ALDVT * 2;   // 54272

__global__ __launch_bounds__(256, 1)
void attn_mma(const __nv_bfloat16* __restrict__ qkv, __nv_bfloat16* __restrict__ ap) {
    extern __shared__ char smem[];
    __nv_bfloat16* sQ = reinterpret_cast<__nv_bfloat16*>(smem + SQ_OFF);
    __nv_bfloat16* sK = reinterpret_cast<__nv_bfloat16*>(smem + SK_OFF);
    __nv_bfloat16* sVt = reinterpret_cast<__nv_bfloat16*>(smem + SV_OFF);
    const uint32_t sQb = smem_u32(sQ), sKb = smem_u32(sK), sVb = smem_u32(sVt);

    const int bid = blockIdx.x;
    const int qt = bid & 3, h = (bid >> 2) & 7, b = bid >> 5;
    const int tid = threadIdx.x, wid = tid >> 5, lane = tid & 31;
    const size_t tok0 = (size_t)b * L_;
    const int q0 = qt * 128;
    const int hoff = h * 32;

#pragma unroll
    for (int i = 0; i < 4; i++) {
        int c = i * 256 + tid;
        int row = c >> 3, u = c & 7, seg = u >> 2, j = u & 3;
        uint4 v = *reinterpret_cast<const uint4*>(
            qkv + (tok0 + q0 + row) * 1536 + hoff + seg * 256 + j * 8);
        *reinterpret_cast<uint4*>(sQ + row * ALDQ + seg * 32 + j * 8) = v;
    }
    __syncthreads();

    auto a_addr = [&](uint32_t base, int mBase, int k0, int ld) -> uint32_t {
        int t = lane >> 3;
        int r = mBase + ((t & 1) << 3) + (lane & 7);
        int c = k0 + ((t >> 1) << 3);
        return base + (uint32_t)(r * ld + c) * 2;
    };
    auto b_addr = [&](uint32_t base, int nBase, int k0, int ld) -> uint32_t {
        int t = lane >> 3;
        int n = nBase + ((t >> 1) << 3) + (lane & 7);
        int c = k0 + ((t & 1) << 3);
        return base + (uint32_t)(n * ld + c) * 2;
    };

    uint32_t aQ[4][4];
#pragma unroll
    for (int kf = 0; kf < 4; kf++) LDSM_X4(aQ[kf], a_addr(sQb, wid * 16, kf * 16, ALDQ));

    float O[8][4];
#pragma unroll
    for (int i = 0; i < 8; i++)
#pragma unroll
        for (int c = 0; c < 4; c++) O[i][c] = 0.f;
    float m0r = -1e30f, m1r = -1e30f, l0 = 0.f, l1 = 0.f;
    const float scale = 0.17677669529663687f;

    for (int kc = 0; kc < 4; kc++) {
        __syncthreads();
#pragma unroll
        for (int i = 0; i < 4; i++) {
            int c = i * 256 + tid;
            int row = c >> 3, u = c & 7, seg = u >> 2, j = u & 3;
            uint4 v = *reinterpret_cast<const uint4*>(
                qkv + (tok0 + kc * 128 + row) * 1536 + hoff + 512 + seg * 256 + j * 8);
            *reinterpret_cast<uint4*>(sK + row * ALDK + seg * 32 + j * 8) = v;
        }
#pragma unroll
        for (int i = 0; i < 4; i++) {
            int c = i * 256 + tid;
            int s = c >> 3, u = c & 7, seg = u >> 2, j = u & 3;
            uint4 v = *reinterpret_cast<const uint4*>(
                qkv + (tok0 + kc * 128 + s) * 1536 + hoff + 1024 + seg * 256 + j * 8);
            const __nv_bfloat16* pb = reinterpret_cast<const __nv_bfloat16*>(&v);
            int c0 = seg * 32 + j * 8;
#pragma unroll
            for (int jj = 0; jj < 8; jj++) sVt[(c0 + jj) * ALDVT + s] = pb[jj];
        }
        __syncthreads();

        float S[16][4];
#pragma unroll
        for (int nf = 0; nf < 16; nf++)
#pragma unroll
            for (int c = 0; c < 4; c++) S[nf][c] = 0.f;
#pragma unroll
        for (int kf = 0; kf < 4; kf++) {
#pragma unroll
            for (int nf2 = 0; nf2 < 8; nf2++) {
                uint32_t r[4];
                LDSM_X4(r, b_addr(sKb, nf2 * 16, kf * 16, ALDK));
                uint32_t b01[2] = {r[0], r[1]}, b23[2] = {r[2], r[3]};
                MMA_BF16(S[nf2 * 2], aQ[kf], b01);
                MMA_BF16(S[nf2 * 2 + 1], aQ[kf], b23);
            }
        }
        float mx0 = -1e30f, mx1 = -1e30f;
#pragma unroll
        for (int nf = 0; nf < 16; nf++) {
#pragma unroll
            for (int c = 0; c < 4; c++) S[nf][c] *= scale;
            mx0 = fmaxf(mx0, fmaxf(S[nf][0], S[nf][1]));
            mx1 = fmaxf(mx1, fmaxf(S[nf][2], S[nf][3]));
        }
        mx0 = fmaxf(mx0, __shfl_xor_sync(0xffffffffu, mx0, 1));
        mx0 = fmaxf(mx0, __shfl_xor_sync(0xffffffffu, mx0, 2));
        mx1 = fmaxf(mx1, __shfl_xor_sync(0xffffffffu, mx1, 1));
        mx1 = fmaxf(mx1, __shfl_xor_sync(0xffffffffu, mx1, 2));
        float mn0 = fmaxf(m0r, mx0), mn1 = fmaxf(m1r, mx1);
        float al0 = __expf(m0r - mn0), al1 = __expf(m1r - mn1);
        m0r = mn0; m1r = mn1;
        float rs0 = 0.f, rs1 = 0.f;
#pragma unroll
        for (int nf = 0; nf < 16; nf++) {
            S[nf][0] = __expf(S[nf][0] - mn0);
            S[nf][1] = __expf(S[nf][1] - mn0);
            S[nf][2] = __expf(S[nf][2] - mn1);
            S[nf][3] = __expf(S[nf][3] - mn1);
            rs0 += S[nf][0] + S[nf][1];
            rs1 += S[nf][2] + S[nf][3];
        }
        rs0 += __shfl_xor_sync(0xffffffffu, rs0, 1);
        rs0 += __shfl_xor_sync(0xffffffffu, rs0, 2);
        rs1 += __shfl_xor_sync(0xffffffffu, rs1, 1);
        rs1 += __shfl_xor_sync(0xffffffffu, rs1, 2);
        l0 = l0 * al0 + rs0;
        l1 = l1 * al1 + rs1;
#pragma unroll
        for (int i = 0; i < 8; i++) {
            O[i][0] *= al0; O[i][1] *= al0; O[i][2] *= al1; O[i][3] *= al1;
        }
#pragma unroll
        for (int t = 0; t < 8; t++) {
            uint32_t pa[4];
            PACK_BF16X2(pa[0], S[2 * t][0], S[2 * t][1]);
            PACK_BF16X2(pa[1], S[2 * t][2], S[2 * t][3]);
            PACK_BF16X2(pa[2], S[2 * t + 1][0], S[2 * t + 1][1]);
            PACK_BF16X2(pa[3], S[2 * t + 1][2], S[2 * t + 1][3]);
#pragma unroll
            for (int vn2 = 0; vn2 < 4; vn2++) {
                uint32_t r[4];
                LDSM_X4(r, b_addr(sVb, vn2 * 16, t * 16, ALDVT));
                uint32_t b01[2] = {r[0], r[1]}, b23[2] = {r[2], r[3]};
                MMA_BF16(O[vn2 * 2], pa, b01);
                MMA_BF16(O[vn2 * 2 + 1], pa, b23);
            }
        }
    }

    float i0 = 1.f / l0, i1 = 1.f / l1;
    const int r = lane >> 2, cq = (lane & 3) * 2;
#pragma unroll
    for (int onf = 0; onf < 8; onf++) {
        int vc = onf * 8 + cq;
        int off = (vc < 32) ? (hoff + vc) : (256 + hoff + vc - 32);
#pragma unroll
        for (int half = 0; half < 2; half++) {
            size_t token = tok0 + q0 + wid * 16 + r + half * 8;
            float inv = half ? i1 : i0;
            uint32_t p;
            PACK_BF16X2(p, O[onf][half * 2] * inv, O[onf][half * 2 + 1] * inv);
            *reinterpret_cast<uint32_t*>(ap + token * 512 + off) = p;
        }
    }
}

// ---------------- fp32 SGEMM (tiny matrices) ----------------
template<bool BIAS>
__global__ __launch_bounds__(256)
void gemm_nt(const float* __restrict__ A, const float* __restrict__ W,
             const float* __restrict__ bias, float* __restrict__ C,
             int M, int N, int K) {
    __shared__ float As[8][129];
    __shared__ float Ws[8][129];
    const int tid = threadIdx.x;
    const int tx = tid & 15, ty = tid >> 4;
    const int m0 = blockIdx.y * 128, n0 = blockIdx.x * 128;
    const int lm = tid >> 1, lh = tid & 1;

    float acc[8][8];
#pragma unroll
    for (int i = 0; i < 8; i++)
#pragma unroll
        for (int j = 0; j < 8; j++) acc[i][j] = 0.f;

    for (int k0 = 0; k0 < K; k0 += 8) {
        float4 av = make_float4(0.f, 0.f, 0.f, 0.f);
        float4 wv = make_float4(0.f, 0.f, 0.f, 0.f);
        int gm = m0 + lm;
        if (gm < M) av = *reinterpret_cast<const float4*>(A + (long long)gm * K + k0 + lh * 4);
        int gn = n0 + lm;
        if (gn < N) wv = *reinterpret_cast<const float4*>(W + (long long)gn * K + k0 + lh * 4);
        __syncthreads();
        As[lh * 4 + 0][lm] = av.x; As[lh * 4 + 1][lm] = av.y;
        As[lh * 4 + 2][lm] = av.z; As[lh * 4 + 3][lm] = av.w;
        Ws[lh * 4 + 0][lm] = wv.x; Ws[lh * 4 + 1][lm] = wv.y;
        Ws[lh * 4 + 2][lm] = wv.z; Ws[lh * 4 + 3][lm] = wv.w;
        __syncthreads();
#pragma unroll
        for (int kk = 0; kk < 8; kk++) {
            float ra[8], rw[8];
#pragma unroll
            for (int i = 0; i < 8; i++) ra[i] = As[kk][ty + 16 * i];
#pragma unroll
            for (int j = 0; j < 8; j++) rw[j] = Ws[kk][tx + 16 * j];
#pragma unroll
            for (int i = 0; i < 8; i++)
#pragma unroll
                for (int j = 0; j < 8; j++) acc[i][j] += ra[i] * rw[j];
        }
    }
#pragma unroll
    for (int i = 0; i < 8; i++) {
        int gm = m0 + ty + 16 * i;
        if (gm >= M) continue;
#pragma unroll
        for (int j = 0; j < 8; j++) {
            int gn = n0 + tx + 16 * j;
            if (gn >= N) continue;
            float v = acc[i][j];
            if (BIAS) v += bias[gn];
            C[(long long)gm * N + gn] = v;
        }
    }
}

// ---------------- prep kernels ----------------
__global__ void embed_bf_k(const int* __restrict__ tok, const float* __restrict__ emb,
                           __nv_bfloat16* __restrict__ x) {
    long long t = (long long)blockIdx.x * blockDim.x + threadIdx.x;
    if (t >= BLD_) return;
    int token = (int)(t >> 8), d = (int)(t & 255);
    x[t] = __float2bfloat16(emb[(long long)tok[token] * D_ + d]);
}

__global__ void split_k(const float* __restrict__ x, __nv_bfloat16* __restrict__ hi,
                        __nv_bfloat16* __restrict__ lo, long long n) {
    long long t = (long long)blockIdx.x * blockDim.x + threadIdx.x;
    if (t >= n) return;
    float v = x[t];
    __nv_bfloat16 h = __float2bfloat16(v);
    hi[t] = h;
    lo[t] = __float2bfloat16(v - __bfloat162float(h));
}

__global__ void build_wq_bf_k(const float* __restrict__ awr, const float* __restrict__ awi,
                              __nv_bfloat16* __restrict__ w) {
    long long t = (long long)blockIdx.x * blockDim.x + threadIdx.x;
    if (t >= 1536LL * 256) return;
    int n = (int)(t >> 8), k = (int)(t & 255);
    int seg = n >> 8, j = n & 255, proj = seg >> 1;
    float v = ((seg & 1) == 0) ? awr[((long long)proj * 256 + j) * 256 + k]
                               : awi[((long long)proj * 256 + j) * 256 + k];
    w[t] = __float2bfloat16(v);
}

// WZ (256x512): row n: [Wr3[n][:], -Wi3[n][:]]
__global__ void build_wz_bf_k(const float* __restrict__ awr, const float* __restrict__ awi,
                              __nv_bfloat16* __restrict__ w) {
    long long t = (long long)blockIdx.x * blockDim.x + threadIdx.x;
    if (t >= 256LL * 512) return;
    int n = (int)(t >> 9), k = (int)(t & 511);
    float v = (k < 256) ? awr[(768LL + n) * 256 + k] : -awi[(768LL + n) * 256 + (k - 256)];
    w[t] = __float2bfloat16(v);
}

// merged small prep: bqkv (blocks 0-5), bzr (6), en (7), pack_w (8..263)
__global__ void prep_misc_k(const float* __restrict__ abr, const float* __restrict__ abi,
                            const float* __restrict__ gw, const float* __restrict__ vqe,
                            float* __restrict__ bq, float* __restrict__ bz,
                            float* __restrict__ en, float* __restrict__ wev,
                            float* __restrict__ wct) {
    int blk = blockIdx.x, t = threadIdx.x;
    if (blk < 6) {
        int i = blk * 256 + t;
        int seg = i >> 8, j = i & 255, proj = seg >> 1;
        float r = abr[proj * 256 + j], i2 = abi[proj * 256 + j];
        bq[i] = ((seg & 1) == 0) ? (r - i2) : (r + i2);
    } else if (blk == 6) {
        bz[t] = abr[768 + t] - abi[768 + t];
    } else if (blk == 7) {
        if (t < KC_) {
            float a = 0.f;
            for (int d = 0; d < D_; d++) { float e = vqe[t * D_ + d]; a += e * e; }
            en[t] = a;
        }
    } else {
        int i = (blk - 8) * 256 + t;
        int d = i >> 8, j = i & 255;
        wev[i] = gw[d * 3 * D_ + 2 * j];
        wct[i] = gw[d * 3 * D_ + 2 * D_ + j];
    }
}

// ---------------- VQ argmin + loss (shfl-based) ----------------
__global__ void vq_argmin_k(const float* __restrict__ dot, const float* __restrict__ en,
                            const float* __restrict__ Z, const float* __restrict__ E,
                            int* __restrict__ idx_out, float* __restrict__ part) {
    int tkn = blockIdx.x;
    int k = threadIdx.x;                   // 128 threads
    int wid = k >> 5, lane = k & 31;
    __shared__ float wv[4];
    __shared__ int wi[4];
    __shared__ float ws[4];

    float bv = en[k] - 2.f * dot[(long long)tkn * KC_ + k];
    int bi = k;
#pragma unroll
    for (int off = 16; off > 0; off >>= 1) {
        float ov = __shfl_xor_sync(0xffffffffu, bv, off);
        int oi = __shfl_xor_sync(0xffffffffu, bi, off);
        if (ov < bv || (ov == bv && oi < bi)) { bv = ov; bi = oi; }
    }
    if (lane == 0) { wv[wid] = bv; wi[wid] = bi; }
    __syncthreads();
    float fb = wv[0]; int fi = wi[0];
#pragma unroll
    for (int i = 1; i < 4; i++)
        if (wv[i] < fb || (wv[i] == fb && wi[i] < fi)) { fb = wv[i]; fi = wi[i]; }
    if (k == 0) idx_out[tkn] = fi;

    float acc = 0.f;
#pragma unroll
    for (int d = k; d < D_; d += 128) {
        float diff = E[(long long)fi * D_ + d] - Z[(long long)tkn * 256 + d];
        acc += diff * diff;
    }
#pragma unroll
    for (int off = 16; off > 0; off >>= 1) acc += __shfl_xor_sync(0xffffffffu, acc, off);
    if (lane == 0) ws[wid] = acc;
    __syncthreads();
    if (k == 0) part[tkn] = ws[0] + ws[1] + ws[2] + ws[3];
}

__global__ void vq_reduce_k(const float* __restrict__ part, float* __restrict__ out_loss) {
    __shared__ float s[256];
    float a = 0.f;
    for (int i = threadIdx.x; i < BL_; i += 256) a += part[i];
    s[threadIdx.x] = a;
    __syncthreads();
    for (int st = 128; st > 0; st >>= 1) {
        if (threadIdx.x < st) s[threadIdx.x] += s[threadIdx.x + st];
        __syncthreads();
    }
    if (threadIdx.x == 0) out_loss[0] = 2.f * s[0] / (float)BLD_;
}

// ---------------- gate / stack / layernorm+modrelu ----------------
__global__ void gate_k(const float* __restrict__ G, const float* __restrict__ Cg,
                       const int* __restrict__ idx, float* __restrict__ gated) {
    long long t = (long long)blockIdx.x * blockDim.x + threadIdx.x;
    if (t >= BLD_) return;
    int d = (int)(t & 255);
    int tkn = (int)(t >> 8);
    int b = tkn >> 9;
    float x = G[(long long)idx[tkn] * D_ + d] + Cg[b * D_ + d];
    gated[t] = 1.f / (1.f + expf(-x));
}

__global__ void stack_part_k(const float* __restrict__ gated, float* __restrict__ part2) {
    int b = blockIdx.x, p = blockIdx.y, d = threadIdx.x;
    float s = 0.f;
    for (int l = p * 64; l < p * 64 + 64; l++)
        s += gated[((long long)b * L_ + l) * D_ + d];
    part2[((long long)b * 8 + p) * D_ + d] = s;
}

__global__ void stack_fin_k(const float* __restrict__ part2, float* __restrict__ stk,
                            float* __restrict__ out_stk) {
    int b = blockIdx.x, d = threadIdx.x;
    float s = 0.f;
#pragma unroll
    for (int p = 0; p < 8; p++) s += part2[((long long)b * 8 + p) * D_ + d];
    stk[b * D_ + d] = s;
    out_stk[b * D_ + d] = s;
}

__global__ void ln_modrelu_k(const float* __restrict__ gated, const float* __restrict__ stk,
                             const float* __restrict__ lg, const float* __restrict__ lb,
                             const float* __restrict__ ib, const float* __restrict__ mb,
                             __nv_bfloat16* __restrict__ YH, __nv_bfloat16* __restrict__ YL) {
    int tkn = blockIdx.x;
    int b = tkn >> 9;
    int d = threadIdx.x;
    int wid = d >> 5, lane = d & 31;
    __shared__ float ws1[8], ws2[8];
    float x = gated[(long long)tkn * D_ + d] + stk[b * D_ + d];
    float s1 = x, s2 = x * x;
#pragma unroll
    for (int off = 16; off > 0; off >>= 1) {
        s1 += __shfl_xor_sync(0xffffffffu, s1, off);
        s2 += __shfl_xor_sync(0xffffffffu, s2, off);
    }
    if (lane == 0) { ws1[wid] = s1; ws2[wid] = s2; }
    __syncthreads();
    float t1 = 0.f, t2 = 0.f;
#pragma unroll
    for (int i = 0; i < 8; i++) { t1 += ws1[i]; t2 += ws2[i]; }
    float mu = t1 * (1.f / 256.f);
    float var = t2 * (1.f / 256.f) - mu * mu;
    float nr = (x - mu) * rsqrtf(var + 1e-5f) * lg[d] + lb[d];
    float ni = ib[d];
    float mag = sqrtf(nr * nr + ni * ni);
    float sc = fmaxf(mag + mb[d], 0.f) / (mag + 1e-6f);
    float y = nr * sc;
    __nv_bfloat16 h = __float2bfloat16(y);
    YH[(long long)tkn * D_ + d] = h;
    YL[(long long)tkn * D_ + d] = __float2bfloat16(y - __bfloat162float(h));
}

// ---------------- host launch ----------------
extern "C" void kernel_launch(void* const* d_in, const int* in_sizes, int n_in,
                              void* d_out, int out_size) {
    const int*   tokens = (const int*)d_in[0];
    const float* context = (const float*)d_in[1];
    const float* emb = (const float*)d_in[2];
    const float* awr = (const float*)d_in[3];
    const float* awi = (const float*)d_in[4];
    const float* abr = (const float*)d_in[5];
    const float* abi = (const float*)d_in[6];
    const float* vqe = (const float*)d_in[7];
    const float* gw  = (const float*)d_in[8];
    const float* gb  = (const float*)d_in[9];
    const float* lrg = (const float*)d_in[10];
    const float* lrb = (const float*)d_in[11];
    const float* lib = (const float*)d_in[13];
    const float* mrb = (const float*)d_in[14];
    const float* hw  = (const float*)d_in[15];
    const float* hb  = (const float*)d_in[16];
    float* out = (float*)d_out;

    float* S; cudaGetSymbolAddress((void**)&S, d_scratch);
    __nv_bfloat16* BF; cudaGetSymbolAddress((void**)&BF, d_bf);
    int* idxb; cudaGetSymbolAddress((void**)&idxb, d_idxbuf);

    cudaFuncSetAttribute(gemm3<true>,  cudaFuncAttributeMaxDynamicSharedMemorySize, G3_SMEM);
    cudaFuncSetAttribute(gemm3<false>, cudaFuncAttributeMaxDynamicSharedMemorySize, G3_SMEM);
    cudaFuncSetAttribute(gemm1<0>, cudaFuncAttributeMaxDynamicSharedMemorySize, G1_SMEM);
    cudaFuncSetAttribute(gemm1<1>, cudaFuncAttributeMaxDynamicSharedMemorySize, G1_SMEM);
    cudaFuncSetAttribute(attn_mma, cudaFuncAttributeMaxDynamicSharedMemorySize, ATT_SMEM);

    float* Z     = S + OFF_Z;
    float* DOT   = S + OFF_DOT;
    float* GT    = S + OFF_GATED;
    float* G     = S + OFF_G;
    float* Cg    = S + OFF_CG;
    float* wev   = S + OFF_WEV;
    float* wct   = S + OFF_WCT;
    float* stk   = S + OFF_STK;
    float* en    = S + OFF_EN;
    float* part  = S + OFF_PART;
    float* bqkv  = S + OFF_BQKV;
    float* bzr   = S + OFF_BZR;
    float* part2 = S + OFF_PART2;

    __nv_bfloat16* XBF  = BF + BF_X;
    __nv_bfloat16* WQBF = BF + BF_WQ;
    __nv_bfloat16* QKVB = BF + BF_QKV;
    __nv_bfloat16* APB  = BF + BF_AP;
    __nv_bfloat16* WZBF = BF + BF_WZ;
    __nv_bfloat16* ZH   = BF + BF_ZH;  __nv_bfloat16* ZL  = BF + BF_ZL;
    __nv_bfloat16* VQH  = BF + BF_VQH; __nv_bfloat16* VQL = BF + BF_VQL;
    __nv_bfloat16* YH   = BF + BF_YH;  __nv_bfloat16* YL  = BF + BF_YL;
    __nv_bfloat16* HWH  = BF + BF_HWH; __nv_bfloat16* HWL = BF + BF_HWL;

    // prep
    prep_misc_k<<<264, 256>>>(abr, abi, gw, vqe, bqkv, bzr, en, wev, wct);
    build_wq_bf_k<<<(int)((1536LL * 256 + 255) / 256), 256>>>(awr, awi, WQBF);
    build_wz_bf_k<<<(int)((256LL * 512 + 255) / 256), 256>>>(awr, awi, WZBF);
    split_k<<<(int)(((long long)KC_ * D_ + 255) / 256), 256>>>(vqe, VQH, VQL, (long long)KC_ * D_);
    split_k<<<(int)(((long long)V_ * D_ + 255) / 256), 256>>>(hw, HWH, HWL, (long long)V_ * D_);
    embed_bf_k<<<(int)((BLD_ + 255) / 256), 256>>>(tokens, emb, XBF);

    // QKV GEMM (single bf16) -> bf16 packed QKV
    gemm1<0><<<dim3(1536 / 128, BL_ / 128), 256, G1_SMEM>>>(
        XBF, WQBF, bqkv, nullptr, QKVB, nullptr, 1536, 256);

    // flash attention (bf16 HMMA)
    attn_mma<<<B_ * H_ * 4, 256, ATT_SMEM>>>(QKVB, APB);

    // out clinear (single bf16, real part only): Z fp32 + ZH/ZL split
    gemm1<1><<<dim3(256 / 128, BL_ / 128), 256, G1_SMEM>>>(
        APB, WZBF, bzr, Z, ZH, ZL, 256, 512);

    // VQ dot (split, precision-critical for argmin)
    gemm3<false><<<dim3(1, BL_ / 256), 256, G3_SMEM>>>(
        ZH, ZL, VQH, VQL, nullptr, DOT, KC_, 256);
    vq_argmin_k<<<BL_, 128>>>(DOT, en, Z, vqe, idxb, part);
    vq_reduce_k<<<1, 256>>>(part, out + BLV_);

    // gate tables
    gemm_nt<false><<<dim3(2, 1), 256>>>(vqe, wev, nullptr, G, KC_, D_, D_);
    gemm_nt<true><<<dim3(2, 1), 256>>>(context, wct, gb, Cg, B_, D_, D_);

    // gate, stack, layernorm+modrelu
    gate_k<<<(int)((BLD_ + 255) / 256), 256>>>(G, Cg, idxb, GT);
    stack_part_k<<<dim3(B_, 8), 256>>>(GT, part2);
    stack_fin_k<<<B_, D_>>>(part2, stk, out + BLV_ + 1);
    ln_modrelu_k<<<BL_, D_>>>(GT, stk, lrg, lrb, lib, mrb, YH, YL);

    // head GEMM (split, precision-critical): logits
    gemm3<true><<<dim3(V_ / 128, BL_ / 256), 256, G3_SMEM>>>(
        YH, YL, HWH, HWL, hb, out, V_, 256);
}

// round 6
// speedup vs baseline: 6.6759x; 1.3545x over previous
#include <cuda_runtime.h>
#include <cuda_bf16.h>
#include <cuda_fp16.h>
#include <cstdint>
#include <math.h>

// ---------------- problem dims ----------------
constexpr int B_ = 32, L_ = 512, D_ = 256, H_ = 8, V_ = 4096, KC_ = 128;
constexpr int BL_ = B_ * L_;                 // 16384
constexpr long long BLD_ = (long long)BL_ * D_;   // 4194304
constexpr long long BLV_ = (long long)BL_ * V_;   // 67108864

// ---------------- fp32 scratch ----------------
constexpr long long OFF_Z     = 0;                               // BL*256
constexpr long long OFF_DOT   = OFF_Z + (long long)BL_ * 256;    // BL*128
constexpr long long OFF_GATED = OFF_DOT + (long long)BL_ * KC_;  // BLD
constexpr long long OFF_G     = OFF_GATED + BLD_;                // 128*256
constexpr long long OFF_CG    = OFF_G + (long long)KC_ * D_;     // 32*256
constexpr long long OFF_WEV   = OFF_CG + (long long)B_ * D_;
constexpr long long OFF_WCT   = OFF_WEV + (long long)D_ * D_;
constexpr long long OFF_STK   = OFF_WCT + (long long)D_ * D_;
constexpr long long OFF_EN    = OFF_STK + (long long)B_ * D_;
constexpr long long OFF_PART  = OFF_EN + KC_;
constexpr long long OFF_BQKV  = OFF_PART + BL_;
constexpr long long OFF_BZR   = OFF_BQKV + 1536;
constexpr long long OFF_PART2 = OFF_BZR + 256;                   // 32*8*256
constexpr long long SCRATCH_N = OFF_PART2 + 32LL * 8 * 256 + 64;

__device__ float d_scratch[SCRATCH_N];
__device__ int   d_idxbuf[BL_];

// ---------------- bf16 scratch ----------------
constexpr long long BF_X    = 0;                                // BLD
constexpr long long BF_WQ   = BF_X + BLD_;                      // 1536*256
constexpr long long BF_QKV  = BF_WQ + 1536LL * 256;             // BL*1536
constexpr long long BF_AP   = BF_QKV + (long long)BL_ * 1536;   // BL*512
constexpr long long BF_WZ   = BF_AP + (long long)BL_ * 512;     // 256*512
constexpr long long BF_N    = BF_WZ + 256LL * 512 + 64;

__device__ __nv_bfloat16 d_bf[BF_N];

// ---------------- fp16 scratch ----------------
constexpr long long HF_HW  = 0;                                 // V*D
constexpr long long HF_Y   = HF_HW + (long long)V_ * D_;        // BLD
constexpr long long HF_Z   = HF_Y + BLD_;                       // BLD
constexpr long long HF_VQ  = HF_Z + BLD_;                       // KC*D
constexpr long long HF_N   = HF_VQ + (long long)KC_ * D_ + 64;

__device__ __half d_hf[HF_N];

// ==================== PTX helpers ====================
__device__ __forceinline__ uint32_t smem_u32(const void* p) {
    uint32_t a;
    asm("{ .reg .u64 t; cvta.to.shared.u64 t, %1; cvt.u32.u64 %0, t; }" : "=r"(a) : "l"(p));
    return a;
}
#define CP_ASYNC16(dst, src) \
    asm volatile("cp.async.cg.shared.global [%0], [%1], 16;" :: "r"(dst), "l"(src))
#define CP_COMMIT() asm volatile("cp.async.commit_group;" ::: "memory")
#define CP_WAIT(n)  asm volatile("cp.async.wait_group %0;" :: "n"(n) : "memory")
#define LDSM_X4(r, addr) \
    asm volatile("ldmatrix.sync.aligned.m8n8.x4.shared.b16 {%0,%1,%2,%3}, [%4];" \
                 : "=r"((r)[0]), "=r"((r)[1]), "=r"((r)[2]), "=r"((r)[3]) : "r"(addr))
#define MMA_BF16(d, a, b) \
    asm volatile("mma.sync.aligned.m16n8k16.row.col.f32.bf16.bf16.f32 " \
                 "{%0,%1,%2,%3}, {%4,%5,%6,%7}, {%8,%9}, {%0,%1,%2,%3};" \
                 : "+f"((d)[0]), "+f"((d)[1]), "+f"((d)[2]), "+f"((d)[3]) \
                 : "r"((a)[0]), "r"((a)[1]), "r"((a)[2]), "r"((a)[3]), \
                   "r"((b)[0]), "r"((b)[1]))
#define MMA_FP16(d, a, b) \
    asm volatile("mma.sync.aligned.m16n8k16.row.col.f32.f16.f16.f32 " \
                 "{%0,%1,%2,%3}, {%4,%5,%6,%7}, {%8,%9}, {%0,%1,%2,%3};" \
                 : "+f"((d)[0]), "+f"((d)[1]), "+f"((d)[2]), "+f"((d)[3]) \
                 : "r"((a)[0]), "r"((a)[1]), "r"((a)[2]), "r"((a)[3]), \
                   "r"((b)[0]), "r"((b)[1]))
// d.lo = lo, d.hi = hi
#define PACK_BF16X2(d, lo, hi) \
    asm("cvt.rn.bf16x2.f32 %0, %1, %2;" : "=r"(d) : "f"(hi), "f"(lo))
#define PACK_F16X2(d, lo, hi) \
    asm("cvt.rn.f16x2.f32 %0, %1, %2;" : "=r"(d) : "f"(hi), "f"(lo))

constexpr int LDT = 40;                         // padded row stride (16-bit elems)

// ==================== single-fp16 HMMA GEMM, 256x128 CTA tile ====================
// C[M,N] = A[M,K] @ B[N,K]^T (+bias), fp32 accum/out.
// 8 warps as 4M x 2N (warp tile 64x64), K-slab 32, 3-stage cp.async.
constexpr int TS_A = 256 * LDT * 2;             // 20480
constexpr int TS_B = 128 * LDT * 2;             // 10240
constexpr int STAGES = TS_A + TS_B;             // 30720
constexpr int GS_SMEM = 3 * STAGES;             // 92160

template<bool BIAS>
__global__ __launch_bounds__(256, 1)
void gemmS(const __half* __restrict__ A, const __half* __restrict__ B,
           const float* __restrict__ bias, float* __restrict__ C,
           int N, int K) {
    extern __shared__ char smem[];
    const uint32_t sb = smem_u32(smem);
    const int tid = threadIdx.x, wid = tid >> 5, lane = tid & 31;
    const int m0 = blockIdx.y * 256, n0 = blockIdx.x * 128;
    const int mW = (wid & 3) * 64, nW = (wid >> 2) * 64;

    float acc[4][8][4];
#pragma unroll
    for (int i = 0; i < 4; i++)
#pragma unroll
        for (int j = 0; j < 8; j++)
#pragma unroll
            for (int c = 0; c < 4; c++) acc[i][j][c] = 0.f;

    auto load_stage = [&](int buf, int k0) {
        const uint32_t st = sb + buf * STAGES;
#pragma unroll
        for (int it = 0; it < 4; it++) {              // A: 256 rows x 32 cols
            int c = it * 256 + tid;
            int row = c >> 2, cc = c & 3;
            CP_ASYNC16(st + (uint32_t)(row * LDT + cc * 8) * 2,
                       A + (size_t)(m0 + row) * K + k0 + cc * 8);
        }
#pragma unroll
        for (int it = 0; it < 2; it++) {              // B: 128 rows x 32 cols
            int c = it * 256 + tid;
            int row = c >> 2, cc = c & 3;
            CP_ASYNC16(st + TS_A + (uint32_t)(row * LDT + cc * 8) * 2,
                       B + (size_t)(n0 + row) * K + k0 + cc * 8);
        }
        CP_COMMIT();
    };

    auto a_addr = [&](uint32_t base, int mBase, int k0) -> uint32_t {
        int t = lane >> 3;
        int r = mBase + ((t & 1) << 3) + (lane & 7);
        int c = k0 + ((t >> 1) << 3);
        return base + (uint32_t)(r * LDT + c) * 2;
    };
    auto b_addr = [&](uint32_t base, int nBase, int k0) -> uint32_t {
        int t = lane >> 3;
        int n = nBase + ((t >> 1) << 3) + (lane & 7);
        int c = k0 + ((t & 1) << 3);
        return base + (uint32_t)(n * LDT + c) * 2;
    };

    const int S = K >> 5;
    load_stage(0, 0);
    load_stage(1, 32);

    for (int s = 0; s < S; s++) {
        const int buf = s % 3;
        if (s + 2 < S) { load_stage((s + 2) % 3, (s + 2) << 5); CP_WAIT(2); }
        else if (s + 1 < S) { CP_WAIT(1); }
        else { CP_WAIT(0); }
        __syncthreads();

        const uint32_t aS = sb + buf * STAGES;
        const uint32_t bS = aS + TS_A;

#pragma unroll
        for (int kk = 0; kk < 2; kk++) {
            const int k0 = kk * 16;
            uint32_t af[4][4];
#pragma unroll
            for (int mf = 0; mf < 4; mf++) LDSM_X4(af[mf], a_addr(aS, mW + mf * 16, k0));
#pragma unroll
            for (int nf2 = 0; nf2 < 4; nf2++) {
                uint32_t r[4];
                LDSM_X4(r, b_addr(bS, nW + nf2 * 16, k0));
                uint32_t b01[2] = {r[0], r[1]}, b23[2] = {r[2], r[3]};
#pragma unroll
                for (int mf = 0; mf < 4; mf++) {
                    MMA_FP16(acc[mf][nf2 * 2], af[mf], b01);
                    MMA_FP16(acc[mf][nf2 * 2 + 1], af[mf], b23);
                }
            }
        }
        __syncthreads();
    }

    const int lr = lane >> 2, lc = (lane & 3) * 2;
#pragma unroll
    for (int mf = 0; mf < 4; mf++) {
        int row0 = m0 + mW + mf * 16 + lr;
#pragma unroll
        for (int nf = 0; nf < 8; nf++) {
            int col = n0 + nW + nf * 8 + lc;
            float b0 = 0.f, b1 = 0.f;
            if (BIAS) { b0 = bias[col]; b1 = bias[col + 1]; }
            *reinterpret_cast<float2*>(C + (size_t)row0 * N + col) =
                make_float2(acc[mf][nf][0] + b0, acc[mf][nf][1] + b1);
            *reinterpret_cast<float2*>(C + (size_t)(row0 + 8) * N + col) =
                make_float2(acc[mf][nf][2] + b0, acc[mf][nf][3] + b1);
        }
    }
}

// ==================== single-bf16 HMMA GEMM (128x128) ====================
// OUTM 0: bf16 out (+bias) into Ch.  OUTM 1: fp32 Cf + fp16 Ch16 (+bias).
constexpr int TILE_B1 = 128 * LDT * 2;            // 10240
constexpr int STAGE_B1 = 2 * TILE_B1;             // 20480
constexpr int G1_SMEM = 3 * STAGE_B1;             // 61440

template<int OUTM>
__global__ __launch_bounds__(256, 1)
void gemm1(const __nv_bfloat16* __restrict__ A, const __nv_bfloat16* __restrict__ B,
           const float* __restrict__ bias, float* __restrict__ Cf,
           __nv_bfloat16* __restrict__ Ch, __half* __restrict__ Ch16,
           int N, int K) {
    extern __shared__ char smem[];
    const uint32_t sb = smem_u32(smem);
    const int tid = threadIdx.x, wid = tid >> 5, lane = tid & 31;
    const int m0 = blockIdx.y * 128, n0 = blockIdx.x * 128;
    const int warpM = wid & 1, warpN = wid >> 1;
    const int mW = warpM * 64, nW = warpN * 32;

    float acc[4][4][4];
#pragma unroll
    for (int i = 0; i < 4; i++)
#pragma unroll
        for (int j = 0; j < 4; j++)
#pragma unroll
            for (int c = 0; c < 4; c++) acc[i][j][c] = 0.f;

    auto load_stage = [&](int buf, int k0) {
#pragma unroll
        for (int mtx = 0; mtx < 2; mtx++) {
            const __nv_bfloat16* src = (mtx == 0) ? A : B;
            const int rbase = (mtx == 0) ? m0 : n0;
            uint32_t dst = sb + buf * STAGE_B1 + mtx * TILE_B1;
#pragma unroll
            for (int it = 0; it < 2; it++) {
                int c = it * 256 + tid;
                int row = c >> 2, cc = c & 3;
                CP_ASYNC16(dst + (uint32_t)(row * LDT + cc * 8) * 2,
                           src + (size_t)(rbase + row) * K + k0 + cc * 8);
            }
        }
        CP_COMMIT();
    };

    auto a_addr = [&](uint32_t base, int mBase, int k0) -> uint32_t {
        int t = lane >> 3;
        int r = mBase + ((t & 1) << 3) + (lane & 7);
        int c = k0 + ((t >> 1) << 3);
        return base + (uint32_t)(r * LDT + c) * 2;
    };
    auto b_addr = [&](uint32_t base, int nBase, int k0) -> uint32_t {
        int t = lane >> 3;
        int n = nBase + ((t >> 1) << 3) + (lane & 7);
        int c = k0 + ((t & 1) << 3);
        return base + (uint32_t)(n * LDT + c) * 2;
    };

    const int S = K >> 5;
    load_stage(0, 0);
    load_stage(1, 32);

    for (int s = 0; s < S; s++) {
        const int buf = s % 3;
        if (s + 2 < S) { load_stage((s + 2) % 3, (s + 2) << 5); CP_WAIT(2); }
        else if (s + 1 < S) { CP_WAIT(1); }
        else { CP_WAIT(0); }
        __syncthreads();

        const uint32_t aB = sb + buf * STAGE_B1;
        const uint32_t bB = aB + TILE_B1;

#pragma unroll
        for (int kk = 0; kk < 2; kk++) {
            const int k0 = kk * 16;
            uint32_t af[4][4];
#pragma unroll
            for (int mf = 0; mf < 4; mf++) LDSM_X4(af[mf], a_addr(aB, mW + mf * 16, k0));
            uint32_t bf[4][2];
#pragma unroll
            for (int nf2 = 0; nf2 < 2; nf2++) {
                uint32_t r[4];
                LDSM_X4(r, b_addr(bB, nW + nf2 * 16, k0));
                bf[nf2 * 2][0] = r[0]; bf[nf2 * 2][1] = r[1];
                bf[nf2 * 2 + 1][0] = r[2]; bf[nf2 * 2 + 1][1] = r[3];
            }
#pragma unroll
            for (int mf = 0; mf < 4; mf++)
#pragma unroll
                for (int nf = 0; nf < 4; nf++)
                    MMA_BF16(acc[mf][nf], af[mf], bf[nf]);
        }
        __syncthreads();
    }

    const int lr = lane >> 2, lc = (lane & 3) * 2;
#pragma unroll
    for (int mf = 0; mf < 4; mf++) {
        int row0 = m0 + mW + mf * 16 + lr;
#pragma unroll
        for (int nf = 0; nf < 4; nf++) {
            int col = n0 + nW + nf * 8 + lc;
            float b0 = bias ? bias[col] : 0.f;
            float b1 = bias ? bias[col + 1] : 0.f;
#pragma unroll
            for (int half = 0; half < 2; half++) {
                size_t row = (size_t)(row0 + half * 8);
                float v0 = acc[mf][nf][half * 2] + b0;
                float v1 = acc[mf][nf][half * 2 + 1] + b1;
                if (OUTM == 0) {
                    uint32_t p; PACK_BF16X2(p, v0, v1);
                    *reinterpret_cast<uint32_t*>(Ch + row * N + col) = p;
                } else {
                    *reinterpret_cast<float2*>(Cf + row * N + col) = make_float2(v0, v1);
                    uint32_t ph; PACK_F16X2(ph, v0, v1);
                    *reinterpret_cast<uint32_t*>(Ch16 + row * N + col) = ph;
                }
            }
        }
    }
}

// ==================== bf16 HMMA flash attention ====================
constexpr int ALDQ = 72, ALDK = 72, ALDVT = 136;
constexpr int SQ_OFF = 0;
constexpr int SK_OFF = 128 * ALDQ * 2;
constexpr int SV_OFF = SK_OFF + 128 * ALDK * 2;
constexpr int ATT_SMEM = SV_OFF + 64 * ALDVT * 2;   // 54272

__global__ __launch_bounds__(256, 1)
void attn_mma(const __nv_bfloat16* __restrict__ qkv, __nv_bfloat16* __restrict__ ap) {
    extern __shared__ char smem[];
    __nv_bfloat16* sQ = reinterpret_cast<__nv_bfloat16*>(smem + SQ_OFF);
    __nv_bfloat16* sK = reinterpret_cast<__nv_bfloat16*>(smem + SK_OFF);
    __nv_bfloat16* sVt = reinterpret_cast<__nv_bfloat16*>(smem + SV_OFF);
    const uint32_t sQb = smem_u32(sQ), sKb = smem_u32(sK), sVb = smem_u32(sVt);

    const int bid = blockIdx.x;
    const int qt = bid & 3, h = (bid >> 2) & 7, b = bid >> 5;
    const int tid = threadIdx.x, wid = tid >> 5, lane = tid & 31;
    const size_t tok0 = (size_t)b * L_;
    const int q0 = qt * 128;
    const int hoff = h * 32;

#pragma unroll
    for (int i = 0; i < 4; i++) {
        int c = i * 256 + tid;
        int row = c >> 3, u = c & 7, seg = u >> 2, j = u & 3;
        uint4 v = *reinterpret_cast<const uint4*>(
            qkv + (tok0 + q0 + row) * 1536 + hoff + seg * 256 + j * 8);
        *reinterpret_cast<uint4*>(sQ + row * ALDQ + seg * 32 + j * 8) = v;
    }
    __syncthreads();

    auto a_addr = [&](uint32_t base, int mBase, int k0, int ld) -> uint32_t {
        int t = lane >> 3;
        int r = mBase + ((t & 1) << 3) + (lane & 7);
        int c = k0 + ((t >> 1) << 3);
        return base + (uint32_t)(r * ld + c) * 2;
    };
    auto b_addr = [&](uint32_t base, int nBase, int k0, int ld) -> uint32_t {
        int t = lane >> 3;
        int n = nBase + ((t >> 1) << 3) + (lane & 7);
        int c = k0 + ((t & 1) << 3);
        return base + (uint32_t)(n * ld + c) * 2;
    };

    uint32_t aQ[4][4];
#pragma unroll
    for (int kf = 0; kf < 4; kf++) LDSM_X4(aQ[kf], a_addr(sQb, wid * 16, kf * 16, ALDQ));

    float O[8][4];
#pragma unroll
    for (int i = 0; i < 8; i++)
#pragma unroll
        for (int c = 0; c < 4; c++) O[i][c] = 0.f;
    float m0r = -1e30f, m1r = -1e30f, l0 = 0.f, l1 = 0.f;
    const float scale = 0.17677669529663687f;

    for (int kc = 0; kc < 4; kc++) {
        __syncthreads();
#pragma unroll
        for (int i = 0; i < 4; i++) {
            int c = i * 256 + tid;
            int row = c >> 3, u = c & 7, seg = u >> 2, j = u & 3;
            uint4 v = *reinterpret_cast<const uint4*>(
                qkv + (tok0 + kc * 128 + row) * 1536 + hoff + 512 + seg * 256 + j * 8);
            *reinterpret_cast<uint4*>(sK + row * ALDK + seg * 32 + j * 8) = v;
        }
#pragma unroll
        for (int i = 0; i < 4; i++) {
            int c = i * 256 + tid;
            int s = c >> 3, u = c & 7, seg = u >> 2, j = u & 3;
            uint4 v = *reinterpret_cast<const uint4*>(
                qkv + (tok0 + kc * 128 + s) * 1536 + hoff + 1024 + seg * 256 + j * 8);
            const __nv_bfloat16* pb = reinterpret_cast<const __nv_bfloat16*>(&v);
            int c0 = seg * 32 + j * 8;
#pragma unroll
            for (int jj = 0; jj < 8; jj++) sVt[(c0 + jj) * ALDVT + s] = pb[jj];
        }
        __syncthreads();

        float S[16][4];
#pragma unroll
        for (int nf = 0; nf < 16; nf++)
#pragma unroll
            for (int c = 0; c < 4; c++) S[nf][c] = 0.f;
#pragma unroll
        for (int kf = 0; kf < 4; kf++) {
#pragma unroll
            for (int nf2 = 0; nf2 < 8; nf2++) {
                uint32_t r[4];
                LDSM_X4(r, b_addr(sKb, nf2 * 16, kf * 16, ALDK));
                uint32_t b01[2] = {r[0], r[1]}, b23[2] = {r[2], r[3]};
                MMA_BF16(S[nf2 * 2], aQ[kf], b01);
                MMA_BF16(S[nf2 * 2 + 1], aQ[kf], b23);
            }
        }
        float mx0 = -1e30f, mx1 = -1e30f;
#pragma unroll
        for (int nf = 0; nf < 16; nf++) {
#pragma unroll
            for (int c = 0; c < 4; c++) S[nf][c] *= scale;
            mx0 = fmaxf(mx0, fmaxf(S[nf][0], S[nf][1]));
            mx1 = fmaxf(mx1, fmaxf(S[nf][2], S[nf][3]));
        }
        mx0 = fmaxf(mx0, __shfl_xor_sync(0xffffffffu, mx0, 1));
        mx0 = fmaxf(mx0, __shfl_xor_sync(0xffffffffu, mx0, 2));
        mx1 = fmaxf(mx1, __shfl_xor_sync(0xffffffffu, mx1, 1));
        mx1 = fmaxf(mx1, __shfl_xor_sync(0xffffffffu, mx1, 2));
        float mn0 = fmaxf(m0r, mx0), mn1 = fmaxf(m1r, mx1);
        float al0 = __expf(m0r - mn0), al1 = __expf(m1r - mn1);
        m0r = mn0; m1r = mn1;
        float rs0 = 0.f, rs1 = 0.f;
#pragma unroll
        for (int nf = 0; nf < 16; nf++) {
            S[nf][0] = __expf(S[nf][0] - mn0);
            S[nf][1] = __expf(S[nf][1] - mn0);
            S[nf][2] = __expf(S[nf][2] - mn1);
            S[nf][3] = __expf(S[nf][3] - mn1);
            rs0 += S[nf][0] + S[nf][1];
            rs1 += S[nf][2] + S[nf][3];
        }
        rs0 += __shfl_xor_sync(0xffffffffu, rs0, 1);
        rs0 += __shfl_xor_sync(0xffffffffu, rs0, 2);
        rs1 += __shfl_xor_sync(0xffffffffu, rs1, 1);
        rs1 += __shfl_xor_sync(0xffffffffu, rs1, 2);
        l0 = l0 * al0 + rs0;
        l1 = l1 * al1 + rs1;
#pragma unroll
        for (int i = 0; i < 8; i++) {
            O[i][0] *= al0; O[i][1] *= al0; O[i][2] *= al1; O[i][3] *= al1;
        }
#pragma unroll
        for (int t = 0; t < 8; t++) {
            uint32_t pa[4];
            PACK_BF16X2(pa[0], S[2 * t][0], S[2 * t][1]);
            PACK_BF16X2(pa[1], S[2 * t][2], S[2 * t][3]);
            PACK_BF16X2(pa[2], S[2 * t + 1][0], S[2 * t + 1][1]);
            PACK_BF16X2(pa[3], S[2 * t + 1][2], S[2 * t + 1][3]);
#pragma unroll
            for (int vn2 = 0; vn2 < 4; vn2++) {
                uint32_t r[4];
                LDSM_X4(r, b_addr(sVb, vn2 * 16, t * 16, ALDVT));
                uint32_t b01[2] = {r[0], r[1]}, b23[2] = {r[2], r[3]};
                MMA_BF16(O[vn2 * 2], pa, b01);
                MMA_BF16(O[vn2 * 2 + 1], pa, b23);
            }
        }
    }

    float i0 = 1.f / l0, i1 = 1.f / l1;
    const int r = lane >> 2, cq = (lane & 3) * 2;
#pragma unroll
    for (int onf = 0; onf < 8; onf++) {
        int vc = onf * 8 + cq;
        int off = (vc < 32) ? (hoff + vc) : (256 + hoff + vc - 32);
#pragma unroll
        for (int half = 0; half < 2; half++) {
            size_t token = tok0 + q0 + wid * 16 + r + half * 8;
            float inv = half ? i1 : i0;
            uint32_t p;
            PACK_BF16X2(p, O[onf][half * 2] * inv, O[onf][half * 2 + 1] * inv);
            *reinterpret_cast<uint32_t*>(ap + token * 512 + off) = p;
        }
    }
}

// ---------------- fp32 SGEMM (tiny matrices) ----------------
template<bool BIAS>
__global__ __launch_bounds__(256)
void gemm_nt(const float* __restrict__ A, const float* __restrict__ W,
             const float* __restrict__ bias, float* __restrict__ C,
             int M, int N, int K) {
    __shared__ float As[8][129];
    __shared__ float Ws[8][129];
    const int tid = threadIdx.x;
    const int tx = tid & 15, ty = tid >> 4;
    const int m0 = blockIdx.y * 128, n0 = blockIdx.x * 128;
    const int lm = tid >> 1, lh = tid & 1;

    float acc[8][8];
#pragma unroll
    for (int i = 0; i < 8; i++)
#pragma unroll
        for (int j = 0; j < 8; j++) acc[i][j] = 0.f;

    for (int k0 = 0; k0 < K; k0 += 8) {
        float4 av = make_float4(0.f, 0.f, 0.f, 0.f);
        float4 wv = make_float4(0.f, 0.f, 0.f, 0.f);
        int gm = m0 + lm;
        if (gm < M) av = *reinterpret_cast<const float4*>(A + (long long)gm * K + k0 + lh * 4);
        int gn = n0 + lm;
        if (gn < N) wv = *reinterpret_cast<const float4*>(W + (long long)gn * K + k0 + lh * 4);
        __syncthreads();
        As[lh * 4 + 0][lm] = av.x; As[lh * 4 + 1][lm] = av.y;
        As[lh * 4 + 2][lm] = av.z; As[lh * 4 + 3][lm] = av.w;
        Ws[lh * 4 + 0][lm] = wv.x; Ws[lh * 4 + 1][lm] = wv.y;
        Ws[lh * 4 + 2][lm] = wv.z; Ws[lh * 4 + 3][lm] = wv.w;
        __syncthreads();
#pragma unroll
        for (int kk = 0; kk < 8; kk++) {
            float ra[8], rw[8];
#pragma unroll
            for (int i = 0; i < 8; i++) ra[i] = As[kk][ty + 16 * i];
#pragma unroll
            for (int j = 0; j < 8; j++) rw[j] = Ws[kk][tx + 16 * j];
#pragma unroll
            for (int i = 0; i < 8; i++)
#pragma unroll
                for (int j = 0; j < 8; j++) acc[i][j] += ra[i] * rw[j];
        }
    }
#pragma unroll
    for (int i = 0; i < 8; i++) {
        int gm = m0 + ty + 16 * i;
        if (gm >= M) continue;
#pragma unroll
        for (int j = 0; j < 8; j++) {
            int gn = n0 + tx + 16 * j;
            if (gn >= N) continue;
            float v = acc[i][j];
            if (BIAS) v += bias[gn];
            C[(long long)gm * N + gn] = v;
        }
    }
}

// ---------------- merged prep: one launch, block-range dispatch ----------------
// [0,264): misc (bqkv, bzr, en, wev/wct)
// [264,1800): WQ bf16; [1800,2312): WZ bf16; [2312,2440): vqe fp16;
// [2440,6536): hw fp16; [6536,22920): embed bf16
__global__ void prep_all_k(const float* __restrict__ abr, const float* __restrict__ abi,
                           const float* __restrict__ gw, const float* __restrict__ vqe,
                           const float* __restrict__ awr, const float* __restrict__ awi,
                           const float* __restrict__ hw, const int* __restrict__ tok,
                           const float* __restrict__ emb,
                           float* __restrict__ bq, float* __restrict__ bz,
                           float* __restrict__ en, float* __restrict__ wev,
                           float* __restrict__ wct,
                           __nv_bfloat16* __restrict__ wq, __nv_bfloat16* __restrict__ wz,
                           __half* __restrict__ vq16, __half* __restrict__ hw16,
                           __nv_bfloat16* __restrict__ x) {
    int blk = blockIdx.x, t = threadIdx.x;
    if (blk < 264) {
        if (blk < 6) {
            int i = blk * 256 + t;
            int seg = i >> 8, j = i & 255, proj = seg >> 1;
            float r = abr[proj * 256 + j], i2 = abi[proj * 256 + j];
            bq[i] = ((seg & 1) == 0) ? (r - i2) : (r + i2);
        } else if (blk == 6) {
            bz[t] = abr[768 + t] - abi[768 + t];
        } else if (blk == 7) {
            if (t < KC_) {
                float a = 0.f;
                for (int d = 0; d < D_; d++) { float e = vqe[t * D_ + d]; a += e * e; }
                en[t] = a;
            }
        } else {
            int i = (blk - 8) * 256 + t;
            int d = i >> 8, j = i & 255;
            wev[i] = gw[d * 3 * D_ + 2 * j];
            wct[i] = gw[d * 3 * D_ + 2 * D_ + j];
        }
    } else if (blk < 1800) {
        long long i = (long long)(blk - 264) * 256 + t;
        int n = (int)(i >> 8), k = (int)(i & 255);
        int seg = n >> 8, j = n & 255, proj = seg >> 1;
        float v = ((seg & 1) == 0) ? awr[((long long)proj * 256 + j) * 256 + k]
                                   : awi[((long long)proj * 256 + j) * 256 + k];
        wq[i] = __float2bfloat16(v);
    } else if (blk < 2312) {
        long long i = (long long)(blk - 1800) * 256 + t;
        int n = (int)(i >> 9), k = (int)(i & 511);
        float v = (k < 256) ? awr[(768LL + n) * 256 + k] : -awi[(768LL + n) * 256 + (k - 256)];
        wz[i] = __float2bfloat16(v);
    } else if (blk < 2440) {
        long long i = (long long)(blk - 2312) * 256 + t;
        vq16[i] = __float2half(vqe[i]);
    } else if (blk < 6536) {
        long long i = (long long)(blk - 2440) * 256 + t;
        hw16[i] = __float2half(hw[i]);
    } else {
        long long i = (long long)(blk - 6536) * 256 + t;
        int token = (int)(i >> 8), d = (int)(i & 255);
        x[i] = __float2bfloat16(emb[(long long)tok[token] * D_ + d]);
    }
}

// ---------------- VQ argmin + loss (shfl-based) ----------------
__global__ void vq_argmin_k(const float* __restrict__ dot, const float* __restrict__ en,
                            const float* __restrict__ Z, const float* __restrict__ E,
                            int* __restrict__ idx_out, float* __restrict__ part) {
    int tkn = blockIdx.x;
    int k = threadIdx.x;                   // 128 threads
    int wid = k >> 5, lane = k & 31;
    __shared__ float wv[4];
    __shared__ int wi[4];
    __shared__ float ws[4];

    float bv = en[k] - 2.f * dot[(long long)tkn * KC_ + k];
    int bi = k;
#pragma unroll
    for (int off = 16; off > 0; off >>= 1) {
        float ov = __shfl_xor_sync(0xffffffffu, bv, off);
        int oi = __shfl_xor_sync(0xffffffffu, bi, off);
        if (ov < bv || (ov == bv && oi < bi)) { bv = ov; bi = oi; }
    }
    if (lane == 0) { wv[wid] = bv; wi[wid] = bi; }
    __syncthreads();
    float fb = wv[0]; int fi = wi[0];
#pragma unroll
    for (int i = 1; i < 4; i++)
        if (wv[i] < fb || (wv[i] == fb && wi[i] < fi)) { fb = wv[i]; fi = wi[i]; }
    if (k == 0) idx_out[tkn] = fi;

    float acc = 0.f;
#pragma unroll
    for (int d = k; d < D_; d += 128) {
        float diff = E[(long long)fi * D_ + d] - Z[(long long)tkn * 256 + d];
        acc += diff * diff;
    }
#pragma unroll
    for (int off = 16; off > 0; off >>= 1) acc += __shfl_xor_sync(0xffffffffu, acc, off);
    if (lane == 0) ws[wid] = acc;
    __syncthreads();
    if (k == 0) part[tkn] = ws[0] + ws[1] + ws[2] + ws[3];
}

__global__ void vq_reduce_k(const float* __restrict__ part, float* __restrict__ out_loss) {
    __shared__ float s[256];
    float a = 0.f;
    for (int i = threadIdx.x; i < BL_; i += 256) a += part[i];
    s[threadIdx.x] = a;
    __syncthreads();
    for (int st = 128; st > 0; st >>= 1) {
        if (threadIdx.x < st) s[threadIdx.x] += s[threadIdx.x + st];
        __syncthreads();
    }
    if (threadIdx.x == 0) out_loss[0] = 2.f * s[0] / (float)BLD_;
}

// ---------------- gate / stack / layernorm+modrelu ----------------
__global__ void gate_k(const float* __restrict__ G, const float* __restrict__ Cg,
                       const int* __restrict__ idx, float* __restrict__ gated) {
    long long t = (long long)blockIdx.x * blockDim.x + threadIdx.x;
    if (t >= BLD_) return;
    int d = (int)(t & 255);
    int tkn = (int)(t >> 8);
    int b = tkn >> 9;
    float x = G[(long long)idx[tkn] * D_ + d] + Cg[b * D_ + d];
    gated[t] = 1.f / (1.f + expf(-x));
}

__global__ void stack_part_k(const float* __restrict__ gated, float* __restrict__ part2) {
    int b = blockIdx.x, p = blockIdx.y, d = threadIdx.x;
    float s = 0.f;
    for (int l = p * 64; l < p * 64 + 64; l++)
        s += gated[((long long)b * L_ + l) * D_ + d];
    part2[((long long)b * 8 + p) * D_ + d] = s;
}

__global__ void stack_fin_k(const float* __restrict__ part2, float* __restrict__ stk,
                            float* __restrict__ out_stk) {
    int b = blockIdx.x, d = threadIdx.x;
    float s = 0.f;
#pragma unroll
    for (int p = 0; p < 8; p++) s += part2[((long long)b * 8 + p) * D_ + d];
    stk[b * D_ + d] = s;
    out_stk[b * D_ + d] = s;
}

__global__ void ln_modrelu_k(const float* __restrict__ gated, const float* __restrict__ stk,
                             const float* __restrict__ lg, const float* __restrict__ lb,
                             const float* __restrict__ ib, const float* __restrict__ mb,
                             __half* __restrict__ Y16) {
    int tkn = blockIdx.x;
    int b = tkn >> 9;
    int d = threadIdx.x;
    int wid = d >> 5, lane = d & 31;
    __shared__ float ws1[8], ws2[8];
    float x = gated[(long long)tkn * D_ + d] + stk[b * D_ + d];
    float s1 = x, s2 = x * x;
#pragma unroll
    for (int off = 16; off > 0; off >>= 1) {
        s1 += __shfl_xor_sync(0xffffffffu, s1, off);
        s2 += __shfl_xor_sync(0xffffffffu, s2, off);
    }
    if (lane == 0) { ws1[wid] = s1; ws2[wid] = s2; }
    __syncthreads();
    float t1 = 0.f, t2 = 0.f;
#pragma unroll
    for (int i = 0; i < 8; i++) { t1 += ws1[i]; t2 += ws2[i]; }
    float mu = t1 * (1.f / 256.f);
    float var = t2 * (1.f / 256.f) - mu * mu;
    float nr = (x - mu) * rsqrtf(var + 1e-5f) * lg[d] + lb[d];
    float ni = ib[d];
    float mag = sqrtf(nr * nr + ni * ni);
    float sc = fmaxf(mag + mb[d], 0.f) / (mag + 1e-6f);
    Y16[(long long)tkn * D_ + d] = __float2half(nr * sc);
}

// ---------------- host launch ----------------
extern "C" void kernel_launch(void* const* d_in, const int* in_sizes, int n_in,
                              void* d_out, int out_size) {
    const int*   tokens = (const int*)d_in[0];
    const float* context = (const float*)d_in[1];
    const float* emb = (const float*)d_in[2];
    const float* awr = (const float*)d_in[3];
    const float* awi = (const float*)d_in[4];
    const float* abr = (const float*)d_in[5];
    const float* abi = (const float*)d_in[6];
    const float* vqe = (const float*)d_in[7];
    const float* gw  = (const float*)d_in[8];
    const float* gb  = (const float*)d_in[9];
    const float* lrg = (const float*)d_in[10];
    const float* lrb = (const float*)d_in[11];
    const float* lib = (const float*)d_in[13];
    const float* mrb = (const float*)d_in[14];
    const float* hw  = (const float*)d_in[15];
    const float* hb  = (const float*)d_in[16];
    float* out = (float*)d_out;

    float* S; cudaGetSymbolAddress((void**)&S, d_scratch);
    __nv_bfloat16* BF; cudaGetSymbolAddress((void**)&BF, d_bf);
    __half* HF; cudaGetSymbolAddress((void**)&HF, d_hf);
    int* idxb; cudaGetSymbolAddress((void**)&idxb, d_idxbuf);

    cudaFuncSetAttribute(gemmS<true>,  cudaFuncAttributeMaxDynamicSharedMemorySize, GS_SMEM);
    cudaFuncSetAttribute(gemmS<false>, cudaFuncAttributeMaxDynamicSharedMemorySize, GS_SMEM);
    cudaFuncSetAttribute(gemm1<0>, cudaFuncAttributeMaxDynamicSharedMemorySize, G1_SMEM);
    cudaFuncSetAttribute(gemm1<1>, cudaFuncAttributeMaxDynamicSharedMemorySize, G1_SMEM);
    cudaFuncSetAttribute(attn_mma, cudaFuncAttributeMaxDynamicSharedMemorySize, ATT_SMEM);

    float* Z     = S + OFF_Z;
    float* DOT   = S + OFF_DOT;
    float* GT    = S + OFF_GATED;
    float* G     = S + OFF_G;
    float* Cg    = S + OFF_CG;
    float* wev   = S + OFF_WEV;
    float* wct   = S + OFF_WCT;
    float* stk   = S + OFF_STK;
    float* en    = S + OFF_EN;
    float* part  = S + OFF_PART;
    float* bqkv  = S + OFF_BQKV;
    float* bzr   = S + OFF_BZR;
    float* part2 = S + OFF_PART2;

    __nv_bfloat16* XBF  = BF + BF_X;
    __nv_bfloat16* WQBF = BF + BF_WQ;
    __nv_bfloat16* QKVB = BF + BF_QKV;
    __nv_bfloat16* APB  = BF + BF_AP;
    __nv_bfloat16* WZBF = BF + BF_WZ;

    __half* HW16 = HF + HF_HW;
    __half* Y16  = HF + HF_Y;
    __half* Z16  = HF + HF_Z;
    __half* VQ16 = HF + HF_VQ;

    // one merged prep launch
    prep_all_k<<<22920, 256>>>(abr, abi, gw, vqe, awr, awi, hw, tokens, emb,
                               bqkv, bzr, en, wev, wct,
                               WQBF, WZBF, VQ16, HW16, XBF);

    // QKV GEMM (single bf16) -> bf16 packed QKV
    gemm1<0><<<dim3(1536 / 128, BL_ / 128), 256, G1_SMEM>>>(
        XBF, WQBF, bqkv, nullptr, QKVB, nullptr, 1536, 256);

    // flash attention (bf16 HMMA)
    attn_mma<<<B_ * H_ * 4, 256, ATT_SMEM>>>(QKVB, APB);

    // out clinear (single bf16, real part only): Z fp32 + Z16 fp16
    gemm1<1><<<dim3(256 / 128, BL_ / 128), 256, G1_SMEM>>>(
        APB, WZBF, bzr, Z, nullptr, Z16, 256, 512);

    // VQ dot (single fp16): DOT = Z @ vqe^T
    gemmS<false><<<dim3(1, BL_ / 256), 256, GS_SMEM>>>(
        Z16, VQ16, nullptr, DOT, KC_, 256);
    vq_argmin_k<<<BL_, 128>>>(DOT, en, Z, vqe, idxb, part);
    vq_reduce_k<<<1, 256>>>(part, out + BLV_);

    // gate tables
    gemm_nt<false><<<dim3(2, 1), 256>>>(vqe, wev, nullptr, G, KC_, D_, D_);
    gemm_nt<true><<<dim3(2, 1), 256>>>(context, wct, gb, Cg, B_, D_, D_);

    // gate, stack, layernorm+modrelu
    gate_k<<<(int)((BLD_ + 255) / 256), 256>>>(G, Cg, idxb, GT);
    stack_part_k<<<dim3(B_, 8), 256>>>(GT, part2);
    stack_fin_k<<<B_, D_>>>(part2, stk, out + BLV_ + 1);
    ln_modrelu_k<<<BL_, D_>>>(GT, stk, lrg, lrb, lib, mrb, Y16);

    // head GEMM (single fp16): logits = Y @ head_w^T + head_b
    gemmS<true><<<dim3(V_ / 128, BL_ / 256), 256, GS_SMEM>>>(
        Y16, HW16, hb, out, V_, 256);
}

// round 7
// speedup vs baseline: 7.3379x; 1.0992x over previous
#include <cuda_runtime.h>
#include <cuda_bf16.h>
#include <cuda_fp16.h>
#include <cstdint>
#include <math.h>

// ---------------- problem dims ----------------
constexpr int B_ = 32, L_ = 512, D_ = 256, H_ = 8, V_ = 4096, KC_ = 128;
constexpr int BL_ = B_ * L_;                 // 16384
constexpr long long BLD_ = (long long)BL_ * D_;   // 4194304
constexpr long long BLV_ = (long long)BL_ * V_;   // 67108864

// ---------------- fp32 scratch ----------------
constexpr long long OFF_Z     = 0;                               // BL*256
constexpr long long OFF_DOT   = OFF_Z + (long long)BL_ * 256;    // BL*128
constexpr long long OFF_GATED = OFF_DOT + (long long)BL_ * KC_;  // BLD
constexpr long long OFF_G     = OFF_GATED + BLD_;                // 128*256
constexpr long long OFF_CG    = OFF_G + (long long)KC_ * D_;     // 32*256
constexpr long long OFF_WEV   = OFF_CG + (long long)B_ * D_;
constexpr long long OFF_WCT   = OFF_WEV + (long long)D_ * D_;
constexpr long long OFF_STK   = OFF_WCT + (long long)D_ * D_;
constexpr long long OFF_EN    = OFF_STK + (long long)B_ * D_;
constexpr long long OFF_PART  = OFF_EN + KC_;
constexpr long long OFF_BQKV  = OFF_PART + BL_;
constexpr long long OFF_BZR   = OFF_BQKV + 1536;
constexpr long long OFF_PART2 = OFF_BZR + 256;                   // 32*8*256
constexpr long long SCRATCH_N = OFF_PART2 + 32LL * 8 * 256 + 64;

__device__ float d_scratch[SCRATCH_N];
__device__ int   d_idxbuf[BL_];

// ---------------- bf16 scratch ----------------
constexpr long long BF_X    = 0;                                // BLD
constexpr long long BF_WQ   = BF_X + BLD_;                      // 1536*256
constexpr long long BF_QKV  = BF_WQ + 1536LL * 256;             // BL*1536
constexpr long long BF_AP   = BF_QKV + (long long)BL_ * 1536;   // BL*512
constexpr long long BF_WZ   = BF_AP + (long long)BL_ * 512;     // 256*512
constexpr long long BF_N    = BF_WZ + 256LL * 512 + 64;

__device__ __nv_bfloat16 d_bf[BF_N];

// ---------------- fp16 scratch ----------------
constexpr long long HF_HW  = 0;                                 // V*D
constexpr long long HF_Y   = HF_HW + (long long)V_ * D_;        // BLD
constexpr long long HF_Z   = HF_Y + BLD_;                       // BLD
constexpr long long HF_VQ  = HF_Z + BLD_;                       // KC*D
constexpr long long HF_N   = HF_VQ + (long long)KC_ * D_ + 64;

__device__ __half d_hf[HF_N];

// ==================== PTX helpers ====================
__device__ __forceinline__ uint32_t smem_u32(const void* p) {
    uint32_t a;
    asm("{ .reg .u64 t; cvta.to.shared.u64 t, %1; cvt.u32.u64 %0, t; }" : "=r"(a) : "l"(p));
    return a;
}
#define CP_ASYNC16(dst, src) \
    asm volatile("cp.async.cg.shared.global [%0], [%1], 16;" :: "r"(dst), "l"(src))
#define CP_COMMIT() asm volatile("cp.async.commit_group;" ::: "memory")
#define CP_WAIT(n)  asm volatile("cp.async.wait_group %0;" :: "n"(n) : "memory")
#define LDSM_X4(r, addr) \
    asm volatile("ldmatrix.sync.aligned.m8n8.x4.shared.b16 {%0,%1,%2,%3}, [%4];" \
                 : "=r"((r)[0]), "=r"((r)[1]), "=r"((r)[2]), "=r"((r)[3]) : "r"(addr))
#define LDSM_X4_T(r, addr) \
    asm volatile("ldmatrix.sync.aligned.m8n8.x4.trans.shared.b16 {%0,%1,%2,%3}, [%4];" \
                 : "=r"((r)[0]), "=r"((r)[1]), "=r"((r)[2]), "=r"((r)[3]) : "r"(addr))
#define MMA_BF16(d, a, b) \
    asm volatile("mma.sync.aligned.m16n8k16.row.col.f32.bf16.bf16.f32 " \
                 "{%0,%1,%2,%3}, {%4,%5,%6,%7}, {%8,%9}, {%0,%1,%2,%3};" \
                 : "+f"((d)[0]), "+f"((d)[1]), "+f"((d)[2]), "+f"((d)[3]) \
                 : "r"((a)[0]), "r"((a)[1]), "r"((a)[2]), "r"((a)[3]), \
                   "r"((b)[0]), "r"((b)[1]))
#define MMA_FP16(d, a, b) \
    asm volatile("mma.sync.aligned.m16n8k16.row.col.f32.f16.f16.f32 " \
                 "{%0,%1,%2,%3}, {%4,%5,%6,%7}, {%8,%9}, {%0,%1,%2,%3};" \
                 : "+f"((d)[0]), "+f"((d)[1]), "+f"((d)[2]), "+f"((d)[3]) \
                 : "r"((a)[0]), "r"((a)[1]), "r"((a)[2]), "r"((a)[3]), \
                   "r"((b)[0]), "r"((b)[1]))
// d.lo = lo, d.hi = hi
#define PACK_BF16X2(d, lo, hi) \
    asm("cvt.rn.bf16x2.f32 %0, %1, %2;" : "=r"(d) : "f"(hi), "f"(lo))
#define PACK_F16X2(d, lo, hi) \
    asm("cvt.rn.f16x2.f32 %0, %1, %2;" : "=r"(d) : "f"(hi), "f"(lo))

constexpr int LDT = 40;                         // padded row stride (16-bit elems)

// ==================== single-fp16 HMMA GEMM, 256x128 CTA tile ====================
constexpr int TS_A = 256 * LDT * 2;             // 20480
constexpr int TS_B = 128 * LDT * 2;             // 10240
constexpr int STAGES = TS_A + TS_B;             // 30720
constexpr int GS_SMEM = 3 * STAGES;             // 92160

template<bool BIAS>
__global__ __launch_bounds__(256, 1)
void gemmS(const __half* __restrict__ A, const __half* __restrict__ B,
           const float* __restrict__ bias, float* __restrict__ C,
           int N, int K) {
    extern __shared__ char smem[];
    const uint32_t sb = smem_u32(smem);
    const int tid = threadIdx.x, wid = tid >> 5, lane = tid & 31;
    const int m0 = blockIdx.y * 256, n0 = blockIdx.x * 128;
    const int mW = (wid & 3) * 64, nW = (wid >> 2) * 64;

    float acc[4][8][4];
#pragma unroll
    for (int i = 0; i < 4; i++)
#pragma unroll
        for (int j = 0; j < 8; j++)
#pragma unroll
            for (int c = 0; c < 4; c++) acc[i][j][c] = 0.f;

    auto load_stage = [&](int buf, int k0) {
        const uint32_t st = sb + buf * STAGES;
#pragma unroll
        for (int it = 0; it < 4; it++) {
            int c = it * 256 + tid;
            int row = c >> 2, cc = c & 3;
            CP_ASYNC16(st + (uint32_t)(row * LDT + cc * 8) * 2,
                       A + (size_t)(m0 + row) * K + k0 + cc * 8);
        }
#pragma unroll
        for (int it = 0; it < 2; it++) {
            int c = it * 256 + tid;
            int row = c >> 2, cc = c & 3;
            CP_ASYNC16(st + TS_A + (uint32_t)(row * LDT + cc * 8) * 2,
                       B + (size_t)(n0 + row) * K + k0 + cc * 8);
        }
        CP_COMMIT();
    };

    auto a_addr = [&](uint32_t base, int mBase, int k0) -> uint32_t {
        int t = lane >> 3;
        int r = mBase + ((t & 1) << 3) + (lane & 7);
        int c = k0 + ((t >> 1) << 3);
        return base + (uint32_t)(r * LDT + c) * 2;
    };
    auto b_addr = [&](uint32_t base, int nBase, int k0) -> uint32_t {
        int t = lane >> 3;
        int n = nBase + ((t >> 1) << 3) + (lane & 7);
        int c = k0 + ((t & 1) << 3);
        return base + (uint32_t)(n * LDT + c) * 2;
    };

    const int S = K >> 5;
    load_stage(0, 0);
    load_stage(1, 32);

    for (int s = 0; s < S; s++) {
        const int buf = s % 3;
        if (s + 2 < S) { load_stage((s + 2) % 3, (s + 2) << 5); CP_WAIT(2); }
        else if (s + 1 < S) { CP_WAIT(1); }
        else { CP_WAIT(0); }
        __syncthreads();

        const uint32_t aS = sb + buf * STAGES;
        const uint32_t bS = aS + TS_A;

#pragma unroll
        for (int kk = 0; kk < 2; kk++) {
            const int k0 = kk * 16;
            uint32_t af[4][4];
#pragma unroll
            for (int mf = 0; mf < 4; mf++) LDSM_X4(af[mf], a_addr(aS, mW + mf * 16, k0));
#pragma unroll
            for (int nf2 = 0; nf2 < 4; nf2++) {
                uint32_t r[4];
                LDSM_X4(r, b_addr(bS, nW + nf2 * 16, k0));
                uint32_t b01[2] = {r[0], r[1]}, b23[2] = {r[2], r[3]};
#pragma unroll
                for (int mf = 0; mf < 4; mf++) {
                    MMA_FP16(acc[mf][nf2 * 2], af[mf], b01);
                    MMA_FP16(acc[mf][nf2 * 2 + 1], af[mf], b23);
                }
            }
        }
        __syncthreads();
    }

    const int lr = lane >> 2, lc = (lane & 3) * 2;
#pragma unroll
    for (int mf = 0; mf < 4; mf++) {
        int row0 = m0 + mW + mf * 16 + lr;
#pragma unroll
        for (int nf = 0; nf < 8; nf++) {
            int col = n0 + nW + nf * 8 + lc;
            float b0 = 0.f, b1 = 0.f;
            if (BIAS) { b0 = bias[col]; b1 = bias[col + 1]; }
            *reinterpret_cast<float2*>(C + (size_t)row0 * N + col) =
                make_float2(acc[mf][nf][0] + b0, acc[mf][nf][1] + b1);
            *reinterpret_cast<float2*>(C + (size_t)(row0 + 8) * N + col) =
                make_float2(acc[mf][nf][2] + b0, acc[mf][nf][3] + b1);
        }
    }
}

// ==================== single-bf16 HMMA GEMM (128x128, 2 CTA/SM) ====================
constexpr int TILE_B1 = 128 * LDT * 2;            // 10240
constexpr int STAGE_B1 = 2 * TILE_B1;             // 20480
constexpr int G1_SMEM = 3 * STAGE_B1;             // 61440

template<int OUTM>
__global__ __launch_bounds__(256, 2)
void gemm1(const __nv_bfloat16* __restrict__ A, const __nv_bfloat16* __restrict__ B,
           const float* __restrict__ bias, float* __restrict__ Cf,
           __nv_bfloat16* __restrict__ Ch, __half* __restrict__ Ch16,
           int N, int K) {
    extern __shared__ char smem[];
    const uint32_t sb = smem_u32(smem);
    const int tid = threadIdx.x, wid = tid >> 5, lane = tid & 31;
    const int m0 = blockIdx.y * 128, n0 = blockIdx.x * 128;
    const int warpM = wid & 1, warpN = wid >> 1;
    const int mW = warpM * 64, nW = warpN * 32;

    float acc[4][4][4];
#pragma unroll
    for (int i = 0; i < 4; i++)
#pragma unroll
        for (int j = 0; j < 4; j++)
#pragma unroll
            for (int c = 0; c < 4; c++) acc[i][j][c] = 0.f;

    auto load_stage = [&](int buf, int k0) {
#pragma unroll
        for (int mtx = 0; mtx < 2; mtx++) {
            const __nv_bfloat16* src = (mtx == 0) ? A : B;
            const int rbase = (mtx == 0) ? m0 : n0;
            uint32_t dst = sb + buf * STAGE_B1 + mtx * TILE_B1;
#pragma unroll
            for (int it = 0; it < 2; it++) {
                int c = it * 256 + tid;
                int row = c >> 2, cc = c & 3;
                CP_ASYNC16(dst + (uint32_t)(row * LDT + cc * 8) * 2,
                           src + (size_t)(rbase + row) * K + k0 + cc * 8);
            }
        }
        CP_COMMIT();
    };

    auto a_addr = [&](uint32_t base, int mBase, int k0) -> uint32_t {
        int t = lane >> 3;
        int r = mBase + ((t & 1) << 3) + (lane & 7);
        int c = k0 + ((t >> 1) << 3);
        return base + (uint32_t)(r * LDT + c) * 2;
    };
    auto b_addr = [&](uint32_t base, int nBase, int k0) -> uint32_t {
        int t = lane >> 3;
        int n = nBase + ((t >> 1) << 3) + (lane & 7);
        int c = k0 + ((t & 1) << 3);
        return base + (uint32_t)(n * LDT + c) * 2;
    };

    const int S = K >> 5;
    load_stage(0, 0);
    load_stage(1, 32);

    for (int s = 0; s < S; s++) {
        const int buf = s % 3;
        if (s + 2 < S) { load_stage((s + 2) % 3, (s + 2) << 5); CP_WAIT(2); }
        else if (s + 1 < S) { CP_WAIT(1); }
        else { CP_WAIT(0); }
        __syncthreads();

        const uint32_t aB = sb + buf * STAGE_B1;
        const uint32_t bB = aB + TILE_B1;

#pragma unroll
        for (int kk = 0; kk < 2; kk++) {
            const int k0 = kk * 16;
            uint32_t af[4][4];
#pragma unroll
            for (int mf = 0; mf < 4; mf++) LDSM_X4(af[mf], a_addr(aB, mW + mf * 16, k0));
            uint32_t bf[4][2];
#pragma unroll
            for (int nf2 = 0; nf2 < 2; nf2++) {
                uint32_t r[4];
                LDSM_X4(r, b_addr(bB, nW + nf2 * 16, k0));
                bf[nf2 * 2][0] = r[0]; bf[nf2 * 2][1] = r[1];
                bf[nf2 * 2 + 1][0] = r[2]; bf[nf2 * 2 + 1][1] = r[3];
            }
#pragma unroll
            for (int mf = 0; mf < 4; mf++)
#pragma unroll
                for (int nf = 0; nf < 4; nf++)
                    MMA_BF16(acc[mf][nf], af[mf], bf[nf]);
        }
        __syncthreads();
    }

    const int lr = lane >> 2, lc = (lane & 3) * 2;
#pragma unroll
    for (int mf = 0; mf < 4; mf++) {
        int row0 = m0 + mW + mf * 16 + lr;
#pragma unroll
        for (int nf = 0; nf < 4; nf++) {
            int col = n0 + nW + nf * 8 + lc;
            float b0 = bias ? bias[col] : 0.f;
            float b1 = bias ? bias[col + 1] : 0.f;
#pragma unroll
            for (int half = 0; half < 2; half++) {
                size_t row = (size_t)(row0 + half * 8);
                float v0 = acc[mf][nf][half * 2] + b0;
                float v1 = acc[mf][nf][half * 2 + 1] + b1;
                if (OUTM == 0) {
                    uint32_t p; PACK_BF16X2(p, v0, v1);
                    *reinterpret_cast<uint32_t*>(Ch + row * N + col) = p;
                } else {
                    *reinterpret_cast<float2*>(Cf + row * N + col) = make_float2(v0, v1);
                    uint32_t ph; PACK_F16X2(ph, v0, v1);
                    *reinterpret_cast<uint32_t*>(Ch16 + row * N + col) = ph;
                }
            }
        }
    }
}

// ==================== bf16 HMMA flash attention (V via ldmatrix.trans) ====================
constexpr int ALDQ = 72, ALDK = 72, ALDV = 72;
constexpr int SQ_OFF = 0;
constexpr int SK_OFF = 128 * ALDQ * 2;
constexpr int SV_OFF = SK_OFF + 128 * ALDK * 2;
constexpr int ATT_SMEM = SV_OFF + 128 * ALDV * 2;   // 55296

__global__ __launch_bounds__(256, 1)
void attn_mma(const __nv_bfloat16* __restrict__ qkv, __nv_bfloat16* __restrict__ ap) {
    extern __shared__ char smem[];
    __nv_bfloat16* sQ = reinterpret_cast<__nv_bfloat16*>(smem + SQ_OFF);
    __nv_bfloat16* sK = reinterpret_cast<__nv_bfloat16*>(smem + SK_OFF);
    __nv_bfloat16* sV = reinterpret_cast<__nv_bfloat16*>(smem + SV_OFF);
    const uint32_t sQb = smem_u32(sQ), sKb = smem_u32(sK), sVb = smem_u32(sV);

    const int bid = blockIdx.x;
    const int qt = bid & 3, h = (bid >> 2) & 7, b = bid >> 5;
    const int tid = threadIdx.x, wid = tid >> 5, lane = tid & 31;
    const size_t tok0 = (size_t)b * L_;
    const int q0 = qt * 128;
    const int hoff = h * 32;

#pragma unroll
    for (int i = 0; i < 4; i++) {
        int c = i * 256 + tid;
        int row = c >> 3, u = c & 7, seg = u >> 2, j = u & 3;
        uint4 v = *reinterpret_cast<const uint4*>(
            qkv + (tok0 + q0 + row) * 1536 + hoff + seg * 256 + j * 8);
        *reinterpret_cast<uint4*>(sQ + row * ALDQ + seg * 32 + j * 8) = v;
    }
    __syncthreads();

    // fragment addr: rows mBase.., k-cols k0.. (works for A frags and trans-V frags)
    auto a_addr = [&](uint32_t base, int mBase, int k0, int ld) -> uint32_t {
        int t = lane >> 3;
        int r = mBase + ((t & 1) << 3) + (lane & 7);
        int c = k0 + ((t >> 1) << 3);
        return base + (uint32_t)(r * ld + c) * 2;
    };
    auto b_addr = [&](uint32_t base, int nBase, int k0, int ld) -> uint32_t {
        int t = lane >> 3;
        int n = nBase + ((t >> 1) << 3) + (lane & 7);
        int c = k0 + ((t & 1) << 3);
        return base + (uint32_t)(n * ld + c) * 2;
    };

    uint32_t aQ[4][4];
#pragma unroll
    for (int kf = 0; kf < 4; kf++) LDSM_X4(aQ[kf], a_addr(sQb, wid * 16, kf * 16, ALDQ));

    float O[8][4];
#pragma unroll
    for (int i = 0; i < 8; i++)
#pragma unroll
        for (int c = 0; c < 4; c++) O[i][c] = 0.f;
    float m0r = -1e30f, m1r = -1e30f, l0 = 0.f, l1 = 0.f;
    const float scale = 0.17677669529663687f;

    for (int kc = 0; kc < 4; kc++) {
        __syncthreads();
#pragma unroll
        for (int i = 0; i < 4; i++) {
            int c = i * 256 + tid;
            int row = c >> 3, u = c & 7, seg = u >> 2, j = u & 3;
            uint4 v = *reinterpret_cast<const uint4*>(
                qkv + (tok0 + kc * 128 + row) * 1536 + hoff + 512 + seg * 256 + j * 8);
            *reinterpret_cast<uint4*>(sK + row * ALDK + seg * 32 + j * 8) = v;
        }
#pragma unroll
        for (int i = 0; i < 4; i++) {       // V row-major [key][64]
            int c = i * 256 + tid;
            int row = c >> 3, u = c & 7, seg = u >> 2, j = u & 3;
            uint4 v = *reinterpret_cast<const uint4*>(
                qkv + (tok0 + kc * 128 + row) * 1536 + hoff + 1024 + seg * 256 + j * 8);
            *reinterpret_cast<uint4*>(sV + row * ALDV + seg * 32 + j * 8) = v;
        }
        __syncthreads();

        float S[16][4];
#pragma unroll
        for (int nf = 0; nf < 16; nf++)
#pragma unroll
            for (int c = 0; c < 4; c++) S[nf][c] = 0.f;
#pragma unroll
        for (int kf = 0; kf < 4; kf++) {
#pragma unroll
            for (int nf2 = 0; nf2 < 8; nf2++) {
                uint32_t r[4];
                LDSM_X4(r, b_addr(sKb, nf2 * 16, kf * 16, ALDK));
                uint32_t b01[2] = {r[0], r[1]}, b23[2] = {r[2], r[3]};
                MMA_BF16(S[nf2 * 2], aQ[kf], b01);
                MMA_BF16(S[nf2 * 2 + 1], aQ[kf], b23);
            }
        }
        float mx0 = -1e30f, mx1 = -1e30f;
#pragma unroll
        for (int nf = 0; nf < 16; nf++) {
#pragma unroll
            for (int c = 0; c < 4; c++) S[nf][c] *= scale;
            mx0 = fmaxf(mx0, fmaxf(S[nf][0], S[nf][1]));
            mx1 = fmaxf(mx1, fmaxf(S[nf][2], S[nf][3]));
        }
        mx0 = fmaxf(mx0, __shfl_xor_sync(0xffffffffu, mx0, 1));
        mx0 = fmaxf(mx0, __shfl_xor_sync(0xffffffffu, mx0, 2));
        mx1 = fmaxf(mx1, __shfl_xor_sync(0xffffffffu, mx1, 1));
        mx1 = fmaxf(mx1, __shfl_xor_sync(0xffffffffu, mx1, 2));
        float mn0 = fmaxf(m0r, mx0), mn1 = fmaxf(m1r, mx1);
        float al0 = __expf(m0r - mn0), al1 = __expf(m1r - mn1);
        m0r = mn0; m1r = mn1;
        float rs0 = 0.f, rs1 = 0.f;
#pragma unroll
        for (int nf = 0; nf < 16; nf++) {
            S[nf][0] = __expf(S[nf][0] - mn0);
            S[nf][1] = __expf(S[nf][1] - mn0);
            S[nf][2] = __expf(S[nf][2] - mn1);
            S[nf][3] = __expf(S[nf][3] - mn1);
            rs0 += S[nf][0] + S[nf][1];
            rs1 += S[nf][2] + S[nf][3];
        }
        rs0 += __shfl_xor_sync(0xffffffffu, rs0, 1);
        rs0 += __shfl_xor_sync(0xffffffffu, rs0, 2);
        rs1 += __shfl_xor_sync(0xffffffffu, rs1, 1);
        rs1 += __shfl_xor_sync(0xffffffffu, rs1, 2);
        l0 = l0 * al0 + rs0;
        l1 = l1 * al1 + rs1;
#pragma unroll
        for (int i = 0; i < 8; i++) {
            O[i][0] *= al0; O[i][1] *= al0; O[i][2] *= al1; O[i][3] *= al1;
        }
        // PV: B-fragments from row-major V via ldmatrix.trans
#pragma unroll
        for (int t8 = 0; t8 < 8; t8++) {
            uint32_t pa[4];
            PACK_BF16X2(pa[0], S[2 * t8][0], S[2 * t8][1]);
            PACK_BF16X2(pa[1], S[2 * t8][2], S[2 * t8][3]);
            PACK_BF16X2(pa[2], S[2 * t8 + 1][0], S[2 * t8 + 1][1]);
            PACK_BF16X2(pa[3], S[2 * t8 + 1][2], S[2 * t8 + 1][3]);
#pragma unroll
            for (int vn2 = 0; vn2 < 4; vn2++) {
                uint32_t r[4];
                LDSM_X4_T(r, a_addr(sVb, t8 * 16, vn2 * 16, ALDV));
                uint32_t b01[2] = {r[0], r[1]}, b23[2] = {r[2], r[3]};
                MMA_BF16(O[vn2 * 2], pa, b01);
                MMA_BF16(O[vn2 * 2 + 1], pa, b23);
            }
        }
    }

    float i0 = 1.f / l0, i1 = 1.f / l1;
    const int r = lane >> 2, cq = (lane & 3) * 2;
#pragma unroll
    for (int onf = 0; onf < 8; onf++) {
        int vc = onf * 8 + cq;
        int off = (vc < 32) ? (hoff + vc) : (256 + hoff + vc - 32);
#pragma unroll
        for (int half = 0; half < 2; half++) {
            size_t token = tok0 + q0 + wid * 16 + r + half * 8;
            float inv = half ? i1 : i0;
            uint32_t p;
            PACK_BF16X2(p, O[onf][half * 2] * inv, O[onf][half * 2 + 1] * inv);
            *reinterpret_cast<uint32_t*>(ap + token * 512 + off) = p;
        }
    }
}

// ---------------- fp32 SGEMM (tiny matrices) ----------------
template<bool BIAS>
__global__ __launch_bounds__(256)
void gemm_nt(const float* __restrict__ A, const float* __restrict__ W,
             const float* __restrict__ bias, float* __restrict__ C,
             int M, int N, int K) {
    __shared__ float As[8][129];
    __shared__ float Ws[8][129];
    const int tid = threadIdx.x;
    const int tx = tid & 15, ty = tid >> 4;
    const int m0 = blockIdx.y * 128, n0 = blockIdx.x * 128;
    const int lm = tid >> 1, lh = tid & 1;

    float acc[8][8];
#pragma unroll
    for (int i = 0; i < 8; i++)
#pragma unroll
        for (int j = 0; j < 8; j++) acc[i][j] = 0.f;

    for (int k0 = 0; k0 < K; k0 += 8) {
        float4 av = make_float4(0.f, 0.f, 0.f, 0.f);
        float4 wv = make_float4(0.f, 0.f, 0.f, 0.f);
        int gm = m0 + lm;
        if (gm < M) av = *reinterpret_cast<const float4*>(A + (long long)gm * K + k0 + lh * 4);
        int gn = n0 + lm;
        if (gn < N) wv = *reinterpret_cast<const float4*>(W + (long long)gn * K + k0 + lh * 4);
        __syncthreads();
        As[lh * 4 + 0][lm] = av.x; As[lh * 4 + 1][lm] = av.y;
        As[lh * 4 + 2][lm] = av.z; As[lh * 4 + 3][lm] = av.w;
        Ws[lh * 4 + 0][lm] = wv.x; Ws[lh * 4 + 1][lm] = wv.y;
        Ws[lh * 4 + 2][lm] = wv.z; Ws[lh * 4 + 3][lm] = wv.w;
        __syncthreads();
#pragma unroll
        for (int kk = 0; kk < 8; kk++) {
            float ra[8], rw[8];
#pragma unroll
            for (int i = 0; i < 8; i++) ra[i] = As[kk][ty + 16 * i];
#pragma unroll
            for (int j = 0; j < 8; j++) rw[j] = Ws[kk][tx + 16 * j];
#pragma unroll
            for (int i = 0; i < 8; i++)
#pragma unroll
                for (int j = 0; j < 8; j++) acc[i][j] += ra[i] * rw[j];
        }
    }
#pragma unroll
    for (int i = 0; i < 8; i++) {
        int gm = m0 + ty + 16 * i;
        if (gm >= M) continue;
#pragma unroll
        for (int j = 0; j < 8; j++) {
            int gn = n0 + tx + 16 * j;
            if (gn >= N) continue;
            float v = acc[i][j];
            if (BIAS) v += bias[gn];
            C[(long long)gm * N + gn] = v;
        }
    }
}

// ---------------- merged prep ----------------
__global__ void prep_all_k(const float* __restrict__ abr, const float* __restrict__ abi,
                           const float* __restrict__ gw, const float* __restrict__ vqe,
                           const float* __restrict__ awr, const float* __restrict__ awi,
                           const float* __restrict__ hw, const int* __restrict__ tok,
                           const float* __restrict__ emb,
                           float* __restrict__ bq, float* __restrict__ bz,
                           float* __restrict__ en, float* __restrict__ wev,
                           float* __restrict__ wct,
                           __nv_bfloat16* __restrict__ wq, __nv_bfloat16* __restrict__ wz,
                           __half* __restrict__ vq16, __half* __restrict__ hw16,
                           __nv_bfloat16* __restrict__ x) {
    int blk = blockIdx.x, t = threadIdx.x;
    if (blk < 264) {
        if (blk < 6) {
            int i = blk * 256 + t;
            int seg = i >> 8, j = i & 255, proj = seg >> 1;
            float r = abr[proj * 256 + j], i2 = abi[proj * 256 + j];
            bq[i] = ((seg & 1) == 0) ? (r - i2) : (r + i2);
        } else if (blk == 6) {
            bz[t] = abr[768 + t] - abi[768 + t];
        } else if (blk == 7) {
            if (t < KC_) {
                float a = 0.f;
                for (int d = 0; d < D_; d++) { float e = vqe[t * D_ + d]; a += e * e; }
                en[t] = a;
            }
        } else {
            int i = (blk - 8) * 256 + t;
            int d = i >> 8, j = i & 255;
            wev[i] = gw[d * 3 * D_ + 2 * j];
            wct[i] = gw[d * 3 * D_ + 2 * D_ + j];
        }
    } else if (blk < 1800) {
        long long i = (long long)(blk - 264) * 256 + t;
        int n = (int)(i >> 8), k = (int)(i & 255);
        int seg = n >> 8, j = n & 255, proj = seg >> 1;
        float v = ((seg & 1) == 0) ? awr[((long long)proj * 256 + j) * 256 + k]
                                   : awi[((long long)proj * 256 + j) * 256 + k];
        wq[i] = __float2bfloat16(v);
    } else if (blk < 2312) {
        long long i = (long long)(blk - 1800) * 256 + t;
        int n = (int)(i >> 9), k = (int)(i & 511);
        float v = (k < 256) ? awr[(768LL + n) * 256 + k] : -awi[(768LL + n) * 256 + (k - 256)];
        wz[i] = __float2bfloat16(v);
    } else if (blk < 2440) {
        long long i = (long long)(blk - 2312) * 256 + t;
        vq16[i] = __float2half(vqe[i]);
    } else if (blk < 6536) {
        long long i = (long long)(blk - 2440) * 256 + t;
        hw16[i] = __float2half(hw[i]);
    } else {
        long long i = (long long)(blk - 6536) * 256 + t;
        int token = (int)(i >> 8), d = (int)(i & 255);
        x[i] = __float2bfloat16(emb[(long long)tok[token] * D_ + d]);
    }
}

// ---------------- VQ argmin + loss ----------------
__global__ void vq_argmin_k(const float* __restrict__ dot, const float* __restrict__ en,
                            const float* __restrict__ Z, const float* __restrict__ E,
                            int* __restrict__ idx_out, float* __restrict__ part) {
    int tkn = blockIdx.x;
    int k = threadIdx.x;
    int wid = k >> 5, lane = k & 31;
    __shared__ float wv[4];
    __shared__ int wi[4];
    __shared__ float ws[4];

    float bv = en[k] - 2.f * dot[(long long)tkn * KC_ + k];
    int bi = k;
#pragma unroll
    for (int off = 16; off > 0; off >>= 1) {
        float ov = __shfl_xor_sync(0xffffffffu, bv, off);
        int oi = __shfl_xor_sync(0xffffffffu, bi, off);
        if (ov < bv || (ov == bv && oi < bi)) { bv = ov; bi = oi; }
    }
    if (lane == 0) { wv[wid] = bv; wi[wid] = bi; }
    __syncthreads();
    float fb = wv[0]; int fi = wi[0];
#pragma unroll
    for (int i = 1; i < 4; i++)
        if (wv[i] < fb || (wv[i] == fb && wi[i] < fi)) { fb = wv[i]; fi = wi[i]; }
    if (k == 0) idx_out[tkn] = fi;

    float acc = 0.f;
#pragma unroll
    for (int d = k; d < D_; d += 128) {
        float diff = E[(long long)fi * D_ + d] - Z[(long long)tkn * 256 + d];
        acc += diff * diff;
    }
#pragma unroll
    for (int off = 16; off > 0; off >>= 1) acc += __shfl_xor_sync(0xffffffffu, acc, off);
    if (lane == 0) ws[wid] = acc;
    __syncthreads();
    if (k == 0) part[tkn] = ws[0] + ws[1] + ws[2] + ws[3];
}

__global__ void vq_reduce_k(const float* __restrict__ part, float* __restrict__ out_loss) {
    __shared__ float s[256];
    float a = 0.f;
    for (int i = threadIdx.x; i < BL_; i += 256) a += part[i];
    s[threadIdx.x] = a;
    __syncthreads();
    for (int st = 128; st > 0; st >>= 1) {
        if (threadIdx.x < st) s[threadIdx.x] += s[threadIdx.x + st];
        __syncthreads();
    }
    if (threadIdx.x == 0) out_loss[0] = 2.f * s[0] / (float)BLD_;
}

// ---------------- fused gate + stack partial ----------------
// grid (B, 8), 256 thr; block (b,p): tokens [p*64, p*64+64), all d.
__global__ void gate_stack_k(const float* __restrict__ G, const float* __restrict__ Cg,
                             const int* __restrict__ idx, float* __restrict__ gated,
                             float* __restrict__ part2) {
    int b = blockIdx.x, p = blockIdx.y, d = threadIdx.x;
    float cg = Cg[b * D_ + d];
    float s = 0.f;
    int tbase = b * L_ + p * 64;
#pragma unroll 4
    for (int l = 0; l < 64; l++) {
        int tok = tbase + l;
        float x = G[(long long)idx[tok] * D_ + d] + cg;
        float g = 1.f / (1.f + __expf(-x));
        gated[(long long)tok * D_ + d] = g;
        s += g;
    }
    part2[((long long)b * 8 + p) * D_ + d] = s;
}

__global__ void stack_fin_k(const float* __restrict__ part2, float* __restrict__ stk,
                            float* __restrict__ out_stk) {
    int b = blockIdx.x, d = threadIdx.x;
    float s = 0.f;
#pragma unroll
    for (int p = 0; p < 8; p++) s += part2[((long long)b * 8 + p) * D_ + d];
    stk[b * D_ + d] = s;
    out_stk[b * D_ + d] = s;
}

__global__ void ln_modrelu_k(const float* __restrict__ gated, const float* __restrict__ stk,
                             const float* __restrict__ lg, const float* __restrict__ lb,
                             const float* __restrict__ ib, const float* __restrict__ mb,
                             __half* __restrict__ Y16) {
    int tkn = blockIdx.x;
    int b = tkn >> 9;
    int d = threadIdx.x;
    int wid = d >> 5, lane = d & 31;
    __shared__ float ws1[8], ws2[8];
    float x = gated[(long long)tkn * D_ + d] + stk[b * D_ + d];
    float s1 = x, s2 = x * x;
#pragma unroll
    for (int off = 16; off > 0; off >>= 1) {
        s1 += __shfl_xor_sync(0xffffffffu, s1, off);
        s2 += __shfl_xor_sync(0xffffffffu, s2, off);
    }
    if (lane == 0) { ws1[wid] = s1; ws2[wid] = s2; }
    __syncthreads();
    float t1 = 0.f, t2 = 0.f;
#pragma unroll
    for (int i = 0; i < 8; i++) { t1 += ws1[i]; t2 += ws2[i]; }
    float mu = t1 * (1.f / 256.f);
    float var = t2 * (1.f / 256.f) - mu * mu;
    float nr = (x - mu) * rsqrtf(var + 1e-5f) * lg[d] + lb[d];
    float ni = ib[d];
    float mag = sqrtf(nr * nr + ni * ni);
    float sc = fmaxf(mag + mb[d], 0.f) / (mag + 1e-6f);
    Y16[(long long)tkn * D_ + d] = __float2half(nr * sc);
}

// ---------------- host launch ----------------
extern "C" void kernel_launch(void* const* d_in, const int* in_sizes, int n_in,
                              void* d_out, int out_size) {
    const int*   tokens = (const int*)d_in[0];
    const float* context = (const float*)d_in[1];
    const float* emb = (const float*)d_in[2];
    const float* awr = (const float*)d_in[3];
    const float* awi = (const float*)d_in[4];
    const float* abr = (const float*)d_in[5];
    const float* abi = (const float*)d_in[6];
    const float* vqe = (const float*)d_in[7];
    const float* gw  = (const float*)d_in[8];
    const float* gb  = (const float*)d_in[9];
    const float* lrg = (const float*)d_in[10];
    const float* lrb = (const float*)d_in[11];
    const float* lib = (const float*)d_in[13];
    const float* mrb = (const float*)d_in[14];
    const float* hw  = (const float*)d_in[15];
    const float* hb  = (const float*)d_in[16];
    float* out = (float*)d_out;

    float* S; cudaGetSymbolAddress((void**)&S, d_scratch);
    __nv_bfloat16* BF; cudaGetSymbolAddress((void**)&BF, d_bf);
    __half* HF; cudaGetSymbolAddress((void**)&HF, d_hf);
    int* idxb; cudaGetSymbolAddress((void**)&idxb, d_idxbuf);

    cudaFuncSetAttribute(gemmS<true>,  cudaFuncAttributeMaxDynamicSharedMemorySize, GS_SMEM);
    cudaFuncSetAttribute(gemmS<false>, cudaFuncAttributeMaxDynamicSharedMemorySize, GS_SMEM);
    cudaFuncSetAttribute(gemm1<0>, cudaFuncAttributeMaxDynamicSharedMemorySize, G1_SMEM);
    cudaFuncSetAttribute(gemm1<1>, cudaFuncAttributeMaxDynamicSharedMemorySize, G1_SMEM);
    cudaFuncSetAttribute(attn_mma, cudaFuncAttributeMaxDynamicSharedMemorySize, ATT_SMEM);

    float* Z     = S + OFF_Z;
    float* DOT   = S + OFF_DOT;
    float* GT    = S + OFF_GATED;
    float* G     = S + OFF_G;
    float* Cg    = S + OFF_CG;
    float* wev   = S + OFF_WEV;
    float* wct   = S + OFF_WCT;
    float* stk   = S + OFF_STK;
    float* en    = S + OFF_EN;
    float* part  = S + OFF_PART;
    float* bqkv  = S + OFF_BQKV;
    float* bzr   = S + OFF_BZR;
    float* part2 = S + OFF_PART2;

    __nv_bfloat16* XBF  = BF + BF_X;
    __nv_bfloat16* WQBF = BF + BF_WQ;
    __nv_bfloat16* QKVB = BF + BF_QKV;
    __nv_bfloat16* APB  = BF + BF_AP;
    __nv_bfloat16* WZBF = BF + BF_WZ;

    __half* HW16 = HF + HF_HW;
    __half* Y16  = HF + HF_Y;
    __half* Z16  = HF + HF_Z;
    __half* VQ16 = HF + HF_VQ;

    prep_all_k<<<22920, 256>>>(abr, abi, gw, vqe, awr, awi, hw, tokens, emb,
                               bqkv, bzr, en, wev, wct,
                               WQBF, WZBF, VQ16, HW16, XBF);

    // QKV GEMM -> bf16 packed QKV
    gemm1<0><<<dim3(1536 / 128, BL_ / 128), 256, G1_SMEM>>>(
        XBF, WQBF, bqkv, nullptr, QKVB, nullptr, 1536, 256);

    // flash attention
    attn_mma<<<B_ * H_ * 4, 256, ATT_SMEM>>>(QKVB, APB);

    // out clinear: Z fp32 + Z16 fp16
    gemm1<1><<<dim3(256 / 128, BL_ / 128), 256, G1_SMEM>>>(
        APB, WZBF, bzr, Z, nullptr, Z16, 256, 512);

    // VQ dot + argmin + loss
    gemmS<false><<<dim3(1, BL_ / 256), 256, GS_SMEM>>>(
        Z16, VQ16, nullptr, DOT, KC_, 256);
    vq_argmin_k<<<BL_, 128>>>(DOT, en, Z, vqe, idxb, part);
    vq_reduce_k<<<1, 256>>>(part, out + BLV_);

    // gate tables
    gemm_nt<false><<<dim3(2, 1), 256>>>(vqe, wev, nullptr, G, KC_, D_, D_);
    gemm_nt<true><<<dim3(2, 1), 256>>>(context, wct, gb, Cg, B_, D_, D_);

    // fused gate+stack, final reduce, layernorm+modrelu
    gate_stack_k<<<dim3(B_, 8), 256>>>(G, Cg, idxb, GT, part2);
    stack_fin_k<<<B_, D_>>>(part2, stk, out + BLV_ + 1);
    ln_modrelu_k<<<BL_, D_>>>(GT, stk, lrg, lrb, lib, mrb, Y16);

    // head GEMM (fp16): logits
    gemmS<true><<<dim3(V_ / 128, BL_ / 256), 256, GS_SMEM>>>(
        Y16, HW16, hb, out, V_, 256);
}

// round 8
// speedup vs baseline: 7.3647x; 1.0037x over previous
#include <cuda_runtime.h>
#include <cuda_bf16.h>
#include <cuda_fp16.h>
#include <cstdint>
#include <math.h>

// ---------------- problem dims ----------------
constexpr int B_ = 32, L_ = 512, D_ = 256, H_ = 8, V_ = 4096, KC_ = 128;
constexpr int BL_ = B_ * L_;                 // 16384
constexpr long long BLD_ = (long long)BL_ * D_;   // 4194304
constexpr long long BLV_ = (long long)BL_ * V_;   // 67108864

// ---------------- fp32 scratch ----------------
constexpr long long OFF_DOT   = 0;                               // BL*128
constexpr long long OFF_GATED = OFF_DOT + (long long)BL_ * KC_;  // BLD
constexpr long long OFF_G     = OFF_GATED + BLD_;                // 128*256
constexpr long long OFF_CG    = OFF_G + (long long)KC_ * D_;     // 32*256
constexpr long long OFF_WEV   = OFF_CG + (long long)B_ * D_;
constexpr long long OFF_WCT   = OFF_WEV + (long long)D_ * D_;
constexpr long long OFF_STK   = OFF_WCT + (long long)D_ * D_;
constexpr long long OFF_EN    = OFF_STK + (long long)B_ * D_;
constexpr long long OFF_PART  = OFF_EN + KC_;
constexpr long long OFF_BQKV  = OFF_PART + BL_;
constexpr long long OFF_BZR   = OFF_BQKV + 1536;
constexpr long long OFF_PART2 = OFF_BZR + 256;                   // 32*8*256
constexpr long long SCRATCH_N = OFF_PART2 + 32LL * 8 * 256 + 64;

__device__ float d_scratch[SCRATCH_N];
__device__ int   d_idxbuf[BL_];

// ---------------- bf16 scratch ----------------
constexpr long long BF_X    = 0;                                // BLD
constexpr long long BF_WQ   = BF_X + BLD_;                      // 1536*256
constexpr long long BF_QKV  = BF_WQ + 1536LL * 256;             // BL*1536
constexpr long long BF_AP   = BF_QKV + (long long)BL_ * 1536;   // BL*512
constexpr long long BF_WZ   = BF_AP + (long long)BL_ * 512;     // 256*512
constexpr long long BF_N    = BF_WZ + 256LL * 512 + 64;

__device__ __nv_bfloat16 d_bf[BF_N];

// ---------------- fp16 scratch ----------------
constexpr long long HF_HW  = 0;                                 // V*D
constexpr long long HF_Y   = HF_HW + (long long)V_ * D_;        // BLD
constexpr long long HF_Z   = HF_Y + BLD_;                       // BLD
constexpr long long HF_VQ  = HF_Z + BLD_;                       // KC*D
constexpr long long HF_N   = HF_VQ + (long long)KC_ * D_ + 64;

__device__ __half d_hf[HF_N];

// ==================== PTX helpers ====================
__device__ __forceinline__ uint32_t smem_u32(const void* p) {
    uint32_t a;
    asm("{ .reg .u64 t; cvta.to.shared.u64 t, %1; cvt.u32.u64 %0, t; }" : "=r"(a) : "l"(p));
    return a;
}
#define CP_ASYNC16(dst, src) \
    asm volatile("cp.async.cg.shared.global [%0], [%1], 16;" :: "r"(dst), "l"(src))
#define CP_COMMIT() asm volatile("cp.async.commit_group;" ::: "memory")
#define CP_WAIT(n)  asm volatile("cp.async.wait_group %0;" :: "n"(n) : "memory")
#define LDSM_X4(r, addr) \
    asm volatile("ldmatrix.sync.aligned.m8n8.x4.shared.b16 {%0,%1,%2,%3}, [%4];" \
                 : "=r"((r)[0]), "=r"((r)[1]), "=r"((r)[2]), "=r"((r)[3]) : "r"(addr))
#define LDSM_X4_T(r, addr) \
    asm volatile("ldmatrix.sync.aligned.m8n8.x4.trans.shared.b16 {%0,%1,%2,%3}, [%4];" \
                 : "=r"((r)[0]), "=r"((r)[1]), "=r"((r)[2]), "=r"((r)[3]) : "r"(addr))
#define MMA_BF16(d, a, b) \
    asm volatile("mma.sync.aligned.m16n8k16.row.col.f32.bf16.bf16.f32 " \
                 "{%0,%1,%2,%3}, {%4,%5,%6,%7}, {%8,%9}, {%0,%1,%2,%3};" \
                 : "+f"((d)[0]), "+f"((d)[1]), "+f"((d)[2]), "+f"((d)[3]) \
                 : "r"((a)[0]), "r"((a)[1]), "r"((a)[2]), "r"((a)[3]), \
                   "r"((b)[0]), "r"((b)[1]))
#define MMA_FP16(d, a, b) \
    asm volatile("mma.sync.aligned.m16n8k16.row.col.f32.f16.f16.f32 " \
                 "{%0,%1,%2,%3}, {%4,%5,%6,%7}, {%8,%9}, {%0,%1,%2,%3};" \
                 : "+f"((d)[0]), "+f"((d)[1]), "+f"((d)[2]), "+f"((d)[3]) \
                 : "r"((a)[0]), "r"((a)[1]), "r"((a)[2]), "r"((a)[3]), \
                   "r"((b)[0]), "r"((b)[1]))
// d.lo = lo, d.hi = hi
#define PACK_BF16X2(d, lo, hi) \
    asm("cvt.rn.bf16x2.f32 %0, %1, %2;" : "=r"(d) : "f"(hi), "f"(lo))
#define PACK_F16X2(d, lo, hi) \
    asm("cvt.rn.f16x2.f32 %0, %1, %2;" : "=r"(d) : "f"(hi), "f"(lo))

constexpr int LDT = 40;                         // padded row stride (16-bit elems)

// ==================== single-fp16 HMMA GEMM, 256x128 CTA tile ====================
constexpr int TS_A = 256 * LDT * 2;             // 20480
constexpr int TS_B = 128 * LDT * 2;             // 10240
constexpr int STAGES = TS_A + TS_B;             // 30720
constexpr int GS_SMEM = 3 * STAGES;             // 92160

template<bool BIAS>
__global__ __launch_bounds__(256, 1)
void gemmS(const __half* __restrict__ A, const __half* __restrict__ B,
           const float* __restrict__ bias, float* __restrict__ C,
           int N, int K) {
    extern __shared__ char smem[];
    const uint32_t sb = smem_u32(smem);
    const int tid = threadIdx.x, wid = tid >> 5, lane = tid & 31;
    const int m0 = blockIdx.y * 256, n0 = blockIdx.x * 128;
    const int mW = (wid & 3) * 64, nW = (wid >> 2) * 64;

    float acc[4][8][4];
#pragma unroll
    for (int i = 0; i < 4; i++)
#pragma unroll
        for (int j = 0; j < 8; j++)
#pragma unroll
            for (int c = 0; c < 4; c++) acc[i][j][c] = 0.f;

    auto load_stage = [&](int buf, int k0) {
        const uint32_t st = sb + buf * STAGES;
#pragma unroll
        for (int it = 0; it < 4; it++) {
            int c = it * 256 + tid;
            int row = c >> 2, cc = c & 3;
            CP_ASYNC16(st + (uint32_t)(row * LDT + cc * 8) * 2,
                       A + (size_t)(m0 + row) * K + k0 + cc * 8);
        }
#pragma unroll
        for (int it = 0; it < 2; it++) {
            int c = it * 256 + tid;
            int row = c >> 2, cc = c & 3;
            CP_ASYNC16(st + TS_A + (uint32_t)(row * LDT + cc * 8) * 2,
                       B + (size_t)(n0 + row) * K + k0 + cc * 8);
        }
        CP_COMMIT();
    };

    auto a_addr = [&](uint32_t base, int mBase, int k0) -> uint32_t {
        int t = lane >> 3;
        int r = mBase + ((t & 1) << 3) + (lane & 7);
        int c = k0 + ((t >> 1) << 3);
        return base + (uint32_t)(r * LDT + c) * 2;
    };
    auto b_addr = [&](uint32_t base, int nBase, int k0) -> uint32_t {
        int t = lane >> 3;
        int n = nBase + ((t >> 1) << 3) + (lane & 7);
        int c = k0 + ((t & 1) << 3);
        return base + (uint32_t)(n * LDT + c) * 2;
    };

    const int S = K >> 5;
    load_stage(0, 0);
    load_stage(1, 32);

    for (int s = 0; s < S; s++) {
        const int buf = s % 3;
        if (s + 1 < S) { CP_WAIT(1); } else { CP_WAIT(0); }
        __syncthreads();
        if (s + 2 < S) load_stage((s + 2) % 3, (s + 2) << 5);

        const uint32_t aS = sb + buf * STAGES;
        const uint32_t bS = aS + TS_A;

        // prefetch ALL A fragments for both kk halves up front
        uint32_t af[2][4][4];
#pragma unroll
        for (int kk = 0; kk < 2; kk++)
#pragma unroll
            for (int mf = 0; mf < 4; mf++)
                LDSM_X4(af[kk][mf], a_addr(aS, mW + mf * 16, kk * 16));

#pragma unroll
        for (int kk = 0; kk < 2; kk++) {
            const int k0 = kk * 16;
#pragma unroll
            for (int nf2 = 0; nf2 < 4; nf2++) {
                uint32_t r[4];
                LDSM_X4(r, b_addr(bS, nW + nf2 * 16, k0));
                uint32_t b01[2] = {r[0], r[1]}, b23[2] = {r[2], r[3]};
#pragma unroll
                for (int mf = 0; mf < 4; mf++) {
                    MMA_FP16(acc[mf][nf2 * 2], af[kk][mf], b01);
                    MMA_FP16(acc[mf][nf2 * 2 + 1], af[kk][mf], b23);
                }
            }
        }
    }
    __syncthreads();

    const int lr = lane >> 2, lc = (lane & 3) * 2;
#pragma unroll
    for (int mf = 0; mf < 4; mf++) {
        int row0 = m0 + mW + mf * 16 + lr;
#pragma unroll
        for (int nf = 0; nf < 8; nf++) {
            int col = n0 + nW + nf * 8 + lc;
            float b0 = 0.f, b1 = 0.f;
            if (BIAS) { b0 = bias[col]; b1 = bias[col + 1]; }
            *reinterpret_cast<float2*>(C + (size_t)row0 * N + col) =
                make_float2(acc[mf][nf][0] + b0, acc[mf][nf][1] + b1);
            *reinterpret_cast<float2*>(C + (size_t)(row0 + 8) * N + col) =
                make_float2(acc[mf][nf][2] + b0, acc[mf][nf][3] + b1);
        }
    }
}

// ==================== single-bf16 HMMA GEMM (128x128, 2 CTA/SM) ====================
// OUTM 0: bf16 out (+bias) into Ch.  OUTM 1: fp16 out (+bias) into Ch16.
constexpr int TILE_B1 = 128 * LDT * 2;            // 10240
constexpr int STAGE_B1 = 2 * TILE_B1;             // 20480
constexpr int G1_SMEM = 3 * STAGE_B1;             // 61440

template<int OUTM>
__global__ __launch_bounds__(256, 2)
void gemm1(const __nv_bfloat16* __restrict__ A, const __nv_bfloat16* __restrict__ B,
           const float* __restrict__ bias, __nv_bfloat16* __restrict__ Ch,
           __half* __restrict__ Ch16, int N, int K) {
    extern __shared__ char smem[];
    const uint32_t sb = smem_u32(smem);
    const int tid = threadIdx.x, wid = tid >> 5, lane = tid & 31;
    const int m0 = blockIdx.y * 128, n0 = blockIdx.x * 128;
    const int warpM = wid & 1, warpN = wid >> 1;
    const int mW = warpM * 64, nW = warpN * 32;

    float acc[4][4][4];
#pragma unroll
    for (int i = 0; i < 4; i++)
#pragma unroll
        for (int j = 0; j < 4; j++)
#pragma unroll
            for (int c = 0; c < 4; c++) acc[i][j][c] = 0.f;

    auto load_stage = [&](int buf, int k0) {
#pragma unroll
        for (int mtx = 0; mtx < 2; mtx++) {
            const __nv_bfloat16* src = (mtx == 0) ? A : B;
            const int rbase = (mtx == 0) ? m0 : n0;
            uint32_t dst = sb + buf * STAGE_B1 + mtx * TILE_B1;
#pragma unroll
            for (int it = 0; it < 2; it++) {
                int c = it * 256 + tid;
                int row = c >> 2, cc = c & 3;
                CP_ASYNC16(dst + (uint32_t)(row * LDT + cc * 8) * 2,
                           src + (size_t)(rbase + row) * K + k0 + cc * 8);
            }
        }
        CP_COMMIT();
    };

    auto a_addr = [&](uint32_t base, int mBase, int k0) -> uint32_t {
        int t = lane >> 3;
        int r = mBase + ((t & 1) << 3) + (lane & 7);
        int c = k0 + ((t >> 1) << 3);
        return base + (uint32_t)(r * LDT + c) * 2;
    };
    auto b_addr = [&](uint32_t base, int nBase, int k0) -> uint32_t {
        int t = lane >> 3;
        int n = nBase + ((t >> 1) << 3) + (lane & 7);
        int c = k0 + ((t & 1) << 3);
        return base + (uint32_t)(n * LDT + c) * 2;
    };

    const int S = K >> 5;
    load_stage(0, 0);
    load_stage(1, 32);

    for (int s = 0; s < S; s++) {
        const int buf = s % 3;
        if (s + 1 < S) { CP_WAIT(1); } else { CP_WAIT(0); }
        __syncthreads();
        if (s + 2 < S) load_stage((s + 2) % 3, (s + 2) << 5);

        const uint32_t aB = sb + buf * STAGE_B1;
        const uint32_t bB = aB + TILE_B1;

        uint32_t af[2][4][4];
#pragma unroll
        for (int kk = 0; kk < 2; kk++)
#pragma unroll
            for (int mf = 0; mf < 4; mf++)
                LDSM_X4(af[kk][mf], a_addr(aB, mW + mf * 16, kk * 16));

#pragma unroll
        for (int kk = 0; kk < 2; kk++) {
            const int k0 = kk * 16;
#pragma unroll
            for (int nf2 = 0; nf2 < 2; nf2++) {
                uint32_t r[4];
                LDSM_X4(r, b_addr(bB, nW + nf2 * 16, k0));
                uint32_t b01[2] = {r[0], r[1]}, b23[2] = {r[2], r[3]};
#pragma unroll
                for (int mf = 0; mf < 4; mf++) {
                    MMA_BF16(acc[mf][nf2 * 2], af[kk][mf], b01);
                    MMA_BF16(acc[mf][nf2 * 2 + 1], af[kk][mf], b23);
                }
            }
        }
    }
    __syncthreads();

    const int lr = lane >> 2, lc = (lane & 3) * 2;
#pragma unroll
    for (int mf = 0; mf < 4; mf++) {
        int row0 = m0 + mW + mf * 16 + lr;
#pragma unroll
        for (int nf = 0; nf < 4; nf++) {
            int col = n0 + nW + nf * 8 + lc;
            float b0 = bias ? bias[col] : 0.f;
            float b1 = bias ? bias[col + 1] : 0.f;
#pragma unroll
            for (int half = 0; half < 2; half++) {
                size_t row = (size_t)(row0 + half * 8);
                float v0 = acc[mf][nf][half * 2] + b0;
                float v1 = acc[mf][nf][half * 2 + 1] + b1;
                if (OUTM == 0) {
                    uint32_t p; PACK_BF16X2(p, v0, v1);
                    *reinterpret_cast<uint32_t*>(Ch + row * N + col) = p;
                } else {
                    uint32_t ph; PACK_F16X2(ph, v0, v1);
                    *reinterpret_cast<uint32_t*>(Ch16 + row * N + col) = ph;
                }
            }
        }
    }
}

// ==================== bf16 HMMA flash attention (V via ldmatrix.trans) ====================
constexpr int ALDQ = 72, ALDK = 72, ALDV = 72;
constexpr int SQ_OFF = 0;
constexpr int SK_OFF = 128 * ALDQ * 2;
constexpr int SV_OFF = SK_OFF + 128 * ALDK * 2;
constexpr int ATT_SMEM = SV_OFF + 128 * ALDV * 2;   // 55296

__global__ __launch_bounds__(256, 1)
void attn_mma(const __nv_bfloat16* __restrict__ qkv, __nv_bfloat16* __restrict__ ap) {
    extern __shared__ char smem[];
    __nv_bfloat16* sQ = reinterpret_cast<__nv_bfloat16*>(smem + SQ_OFF);
    __nv_bfloat16* sK = reinterpret_cast<__nv_bfloat16*>(smem + SK_OFF);
    __nv_bfloat16* sV = reinterpret_cast<__nv_bfloat16*>(smem + SV_OFF);
    const uint32_t sQb = smem_u32(sQ), sKb = smem_u32(sK), sVb = smem_u32(sV);

    const int bid = blockIdx.x;
    const int qt = bid & 3, h = (bid >> 2) & 7, b = bid >> 5;
    const int tid = threadIdx.x, wid = tid >> 5, lane = tid & 31;
    const size_t tok0 = (size_t)b * L_;
    const int q0 = qt * 128;
    const int hoff = h * 32;

#pragma unroll
    for (int i = 0; i < 4; i++) {
        int c = i * 256 + tid;
        int row = c >> 3, u = c & 7, seg = u >> 2, j = u & 3;
        uint4 v = *reinterpret_cast<const uint4*>(
            qkv + (tok0 + q0 + row) * 1536 + hoff + seg * 256 + j * 8);
        *reinterpret_cast<uint4*>(sQ + row * ALDQ + seg * 32 + j * 8) = v;
    }
    __syncthreads();

    auto a_addr = [&](uint32_t base, int mBase, int k0, int ld) -> uint32_t {
        int t = lane >> 3;
        int r = mBase + ((t & 1) << 3) + (lane & 7);
        int c = k0 + ((t >> 1) << 3);
        return base + (uint32_t)(r * ld + c) * 2;
    };
    auto b_addr = [&](uint32_t base, int nBase, int k0, int ld) -> uint32_t {
        int t = lane >> 3;
        int n = nBase + ((t >> 1) << 3) + (lane & 7);
        int c = k0 + ((t & 1) << 3);
        return base + (uint32_t)(n * ld + c) * 2;
    };

    uint32_t aQ[4][4];
#pragma unroll
    for (int kf = 0; kf < 4; kf++) LDSM_X4(aQ[kf], a_addr(sQb, wid * 16, kf * 16, ALDQ));

    float O[8][4];
#pragma unroll
    for (int i = 0; i < 8; i++)
#pragma unroll
        for (int c = 0; c < 4; c++) O[i][c] = 0.f;
    float m0r = -1e30f, m1r = -1e30f, l0 = 0.f, l1 = 0.f;
    const float scale = 0.17677669529663687f;

    for (int kc = 0; kc < 4; kc++) {
        __syncthreads();
#pragma unroll
        for (int i = 0; i < 4; i++) {
            int c = i * 256 + tid;
            int row = c >> 3, u = c & 7, seg = u >> 2, j = u & 3;
            uint4 v = *reinterpret_cast<const uint4*>(
                qkv + (tok0 + kc * 128 + row) * 1536 + hoff + 512 + seg * 256 + j * 8);
            *reinterpret_cast<uint4*>(sK + row * ALDK + seg * 32 + j * 8) = v;
        }
#pragma unroll
        for (int i = 0; i < 4; i++) {
            int c = i * 256 + tid;
            int row = c >> 3, u = c & 7, seg = u >> 2, j = u & 3;
            uint4 v = *reinterpret_cast<const uint4*>(
                qkv + (tok0 + kc * 128 + row) * 1536 + hoff + 1024 + seg * 256 + j * 8);
            *reinterpret_cast<uint4*>(sV + row * ALDV + seg * 32 + j * 8) = v;
        }
        __syncthreads();

        float S[16][4];
#pragma unroll
        for (int nf = 0; nf < 16; nf++)
#pragma unroll
            for (int c = 0; c < 4; c++) S[nf][c] = 0.f;
#pragma unroll
        for (int kf = 0; kf < 4; kf++) {
#pragma unroll
            for (int nf2 = 0; nf2 < 8; nf2++) {
                uint32_t r[4];
                LDSM_X4(r, b_addr(sKb, nf2 * 16, kf * 16, ALDK));
                uint32_t b01[2] = {r[0], r[1]}, b23[2] = {r[2], r[3]};
                MMA_BF16(S[nf2 * 2], aQ[kf], b01);
                MMA_BF16(S[nf2 * 2 + 1], aQ[kf], b23);
            }
        }
        float mx0 = -1e30f, mx1 = -1e30f;
#pragma unroll
        for (int nf = 0; nf < 16; nf++) {
#pragma unroll
            for (int c = 0; c < 4; c++) S[nf][c] *= scale;
            mx0 = fmaxf(mx0, fmaxf(S[nf][0], S[nf][1]));
            mx1 = fmaxf(mx1, fmaxf(S[nf][2], S[nf][3]));
        }
        mx0 = fmaxf(mx0, __shfl_xor_sync(0xffffffffu, mx0, 1));
        mx0 = fmaxf(mx0, __shfl_xor_sync(0xffffffffu, mx0, 2));
        mx1 = fmaxf(mx1, __shfl_xor_sync(0xffffffffu, mx1, 1));
        mx1 = fmaxf(mx1, __shfl_xor_sync(0xffffffffu, mx1, 2));
        float mn0 = fmaxf(m0r, mx0), mn1 = fmaxf(m1r, mx1);
        float al0 = __expf(m0r - mn0), al1 = __expf(m1r - mn1);
        m0r = mn0; m1r = mn1;
        float rs0 = 0.f, rs1 = 0.f;
#pragma unroll
        for (int nf = 0; nf < 16; nf++) {
            S[nf][0] = __expf(S[nf][0] - mn0);
            S[nf][1] = __expf(S[nf][1] - mn0);
            S[nf][2] = __expf(S[nf][2] - mn1);
            S[nf][3] = __expf(S[nf][3] - mn1);
            rs0 += S[nf][0] + S[nf][1];
            rs1 += S[nf][2] + S[nf][3];
        }
        rs0 += __shfl_xor_sync(0xffffffffu, rs0, 1);
        rs0 += __shfl_xor_sync(0xffffffffu, rs0, 2);
        rs1 += __shfl_xor_sync(0xffffffffu, rs1, 1);
        rs1 += __shfl_xor_sync(0xffffffffu, rs1, 2);
        l0 = l0 * al0 + rs0;
        l1 = l1 * al1 + rs1;
#pragma unroll
        for (int i = 0; i < 8; i++) {
            O[i][0] *= al0; O[i][1] *= al0; O[i][2] *= al1; O[i][3] *= al1;
        }
#pragma unroll
        for (int t8 = 0; t8 < 8; t8++) {
            uint32_t pa[4];
            PACK_BF16X2(pa[0], S[2 * t8][0], S[2 * t8][1]);
            PACK_BF16X2(pa[1], S[2 * t8][2], S[2 * t8][3]);
            PACK_BF16X2(pa[2], S[2 * t8 + 1][0], S[2 * t8 + 1][1]);
            PACK_BF16X2(pa[3], S[2 * t8 + 1][2], S[2 * t8 + 1][3]);
#pragma unroll
            for (int vn2 = 0; vn2 < 4; vn2++) {
                uint32_t r[4];
                LDSM_X4_T(r, a_addr(sVb, t8 * 16, vn2 * 16, ALDV));
                uint32_t b01[2] = {r[0], r[1]}, b23[2] = {r[2], r[3]};
                MMA_BF16(O[vn2 * 2], pa, b01);
                MMA_BF16(O[vn2 * 2 + 1], pa, b23);
            }
        }
    }

    float i0 = 1.f / l0, i1 = 1.f / l1;
    const int r = lane >> 2, cq = (lane & 3) * 2;
#pragma unroll
    for (int onf = 0; onf < 8; onf++) {
        int vc = onf * 8 + cq;
        int off = (vc < 32) ? (hoff + vc) : (256 + hoff + vc - 32);
#pragma unroll
        for (int half = 0; half < 2; half++) {
            size_t token = tok0 + q0 + wid * 16 + r + half * 8;
            float inv = half ? i1 : i0;
            uint32_t p;
            PACK_BF16X2(p, O[onf][half * 2] * inv, O[onf][half * 2 + 1] * inv);
            *reinterpret_cast<uint32_t*>(ap + token * 512 + off) = p;
        }
    }
}

// ---------------- fp32 SGEMM (tiny matrices) ----------------
template<bool BIAS>
__global__ __launch_bounds__(256)
void gemm_nt(const float* __restrict__ A, const float* __restrict__ W,
             const float* __restrict__ bias, float* __restrict__ C,
             int M, int N, int K) {
    __shared__ float As[8][129];
    __shared__ float Ws[8][129];
    const int tid = threadIdx.x;
    const int tx = tid & 15, ty = tid >> 4;
    const int m0 = blockIdx.y * 128, n0 = blockIdx.x * 128;
    const int lm = tid >> 1, lh = tid & 1;

    float acc[8][8];
#pragma unroll
    for (int i = 0; i < 8; i++)
#pragma unroll
        for (int j = 0; j < 8; j++) acc[i][j] = 0.f;

    for (int k0 = 0; k0 < K; k0 += 8) {
        float4 av = make_float4(0.f, 0.f, 0.f, 0.f);
        float4 wv = make_float4(0.f, 0.f, 0.f, 0.f);
        int gm = m0 + lm;
        if (gm < M) av = *reinterpret_cast<const float4*>(A + (long long)gm * K + k0 + lh * 4);
        int gn = n0 + lm;
        if (gn < N) wv = *reinterpret_cast<const float4*>(W + (long long)gn * K + k0 + lh * 4);
        __syncthreads();
        As[lh * 4 + 0][lm] = av.x; As[lh * 4 + 1][lm] = av.y;
        As[lh * 4 + 2][lm] = av.z; As[lh * 4 + 3][lm] = av.w;
        Ws[lh * 4 + 0][lm] = wv.x; Ws[lh * 4 + 1][lm] = wv.y;
        Ws[lh * 4 + 2][lm] = wv.z; Ws[lh * 4 + 3][lm] = wv.w;
        __syncthreads();
#pragma unroll
        for (int kk = 0; kk < 8; kk++) {
            float ra[8], rw[8];
#pragma unroll
            for (int i = 0; i < 8; i++) ra[i] = As[kk][ty + 16 * i];
#pragma unroll
            for (int j = 0; j < 8; j++) rw[j] = Ws[kk][tx + 16 * j];
#pragma unroll
            for (int i = 0; i < 8; i++)
#pragma unroll
                for (int j = 0; j < 8; j++) acc[i][j] += ra[i] * rw[j];
        }
    }
#pragma unroll
    for (int i = 0; i < 8; i++) {
        int gm = m0 + ty + 16 * i;
        if (gm >= M) continue;
#pragma unroll
        for (int j = 0; j < 8; j++) {
            int gn = n0 + tx + 16 * j;
            if (gn >= N) continue;
            float v = acc[i][j];
            if (BIAS) v += bias[gn];
            C[(long long)gm * N + gn] = v;
        }
    }
}

// ---------------- merged prep ----------------
__global__ void prep_all_k(const float* __restrict__ abr, const float* __restrict__ abi,
                           const float* __restrict__ gw, const float* __restrict__ vqe,
                           const float* __restrict__ awr, const float* __restrict__ awi,
                           const float* __restrict__ hw, const int* __restrict__ tok,
                           const float* __restrict__ emb,
                           float* __restrict__ bq, float* __restrict__ bz,
                           float* __restrict__ en, float* __restrict__ wev,
                           float* __restrict__ wct,
                           __nv_bfloat16* __restrict__ wq, __nv_bfloat16* __restrict__ wz,
                           __half* __restrict__ vq16, __half* __restrict__ hw16,
                           __nv_bfloat16* __restrict__ x) {
    int blk = blockIdx.x, t = threadIdx.x;
    if (blk < 264) {
        if (blk < 6) {
            int i = blk * 256 + t;
            int seg = i >> 8, j = i & 255, proj = seg >> 1;
            float r = abr[proj * 256 + j], i2 = abi[proj * 256 + j];
            bq[i] = ((seg & 1) == 0) ? (r - i2) : (r + i2);
        } else if (blk == 6) {
            bz[t] = abr[768 + t] - abi[768 + t];
        } else if (blk == 7) {
            if (t < KC_) {
                float a = 0.f;
                for (int d = 0; d < D_; d++) { float e = vqe[t * D_ + d]; a += e * e; }
                en[t] = a;
            }
        } else {
            int i = (blk - 8) * 256 + t;
            int d = i >> 8, j = i & 255;
            wev[i] = gw[d * 3 * D_ + 2 * j];
            wct[i] = gw[d * 3 * D_ + 2 * D_ + j];
        }
    } else if (blk < 1800) {
        long long i = (long long)(blk - 264) * 256 + t;
        int n = (int)(i >> 8), k = (int)(i & 255);
        int seg = n >> 8, j = n & 255, proj = seg >> 1;
        float v = ((seg & 1) == 0) ? awr[((long long)proj * 256 + j) * 256 + k]
                                   : awi[((long long)proj * 256 + j) * 256 + k];
        wq[i] = __float2bfloat16(v);
    } else if (blk < 2312) {
        long long i = (long long)(blk - 1800) * 256 + t;
        int n = (int)(i >> 9), k = (int)(i & 511);
        float v = (k < 256) ? awr[(768LL + n) * 256 + k] : -awi[(768LL + n) * 256 + (k - 256)];
        wz[i] = __float2bfloat16(v);
    } else if (blk < 2440) {
        long long i = (long long)(blk - 2312) * 256 + t;
        vq16[i] = __float2half(vqe[i]);
    } else if (blk < 6536) {
        long long i = (long long)(blk - 2440) * 256 + t;
        hw16[i] = __float2half(hw[i]);
    } else {
        long long i = (long long)(blk - 6536) * 256 + t;
        int token = (int)(i >> 8), d = (int)(i & 255);
        x[i] = __float2bfloat16(emb[(long long)tok[token] * D_ + d]);
    }
}

// ---------------- VQ argmin + loss (Z in fp16) ----------------
__global__ void vq_argmin_k(const float* __restrict__ dot, const float* __restrict__ en,
                            const __half* __restrict__ Z16, const float* __restrict__ E,
                            int* __restrict__ idx_out, float* __restrict__ part) {
    int tkn = blockIdx.x;
    int k = threadIdx.x;
    int wid = k >> 5, lane = k & 31;
    __shared__ float wv[4];
    __shared__ int wi[4];
    __shared__ float ws[4];

    float bv = en[k] - 2.f * dot[(long long)tkn * KC_ + k];
    int bi = k;
#pragma unroll
    for (int off = 16; off > 0; off >>= 1) {
        float ov = __shfl_xor_sync(0xffffffffu, bv, off);
        int oi = __shfl_xor_sync(0xffffffffu, bi, off);
        if (ov < bv || (ov == bv && oi < bi)) { bv = ov; bi = oi; }
    }
    if (lane == 0) { wv[wid] = bv; wi[wid] = bi; }
    __syncthreads();
    float fb = wv[0]; int fi = wi[0];
#pragma unroll
    for (int i = 1; i < 4; i++)
        if (wv[i] < fb || (wv[i] == fb && wi[i] < fi)) { fb = wv[i]; fi = wi[i]; }
    if (k == 0) idx_out[tkn] = fi;

    float acc = 0.f;
#pragma unroll
    for (int d = k; d < D_; d += 128) {
        float diff = E[(long long)fi * D_ + d] - __half2float(Z16[(long long)tkn * 256 + d]);
        acc += diff * diff;
    }
#pragma unroll
    for (int off = 16; off > 0; off >>= 1) acc += __shfl_xor_sync(0xffffffffu, acc, off);
    if (lane == 0) ws[wid] = acc;
    __syncthreads();
    if (k == 0) part[tkn] = ws[0] + ws[1] + ws[2] + ws[3];
}

__global__ void vq_reduce_k(const float* __restrict__ part, float* __restrict__ out_loss) {
    __shared__ float s[256];
    float a = 0.f;
    for (int i = threadIdx.x; i < BL_; i += 256) a += part[i];
    s[threadIdx.x] = a;
    __syncthreads();
    for (int st = 128; st > 0; st >>= 1) {
        if (threadIdx.x < st) s[threadIdx.x] += s[threadIdx.x + st];
        __syncthreads();
    }
    if (threadIdx.x == 0) out_loss[0] = 2.f * s[0] / (float)BLD_;
}

// ---------------- fused gate + stack partial ----------------
__global__ void gate_stack_k(const float* __restrict__ G, const float* __restrict__ Cg,
                             const int* __restrict__ idx, float* __restrict__ gated,
                             float* __restrict__ part2) {
    int b = blockIdx.x, p = blockIdx.y, d = threadIdx.x;
    float cg = Cg[b * D_ + d];
    float s = 0.f;
    int tbase = b * L_ + p * 64;
#pragma unroll 4
    for (int l = 0; l < 64; l++) {
        int tok = tbase + l;
        float x = G[(long long)idx[tok] * D_ + d] + cg;
        float g = 1.f / (1.f + __expf(-x));
        gated[(long long)tok * D_ + d] = g;
        s += g;
    }
    part2[((long long)b * 8 + p) * D_ + d] = s;
}

__global__ void stack_fin_k(const float* __restrict__ part2, float* __restrict__ stk,
                            float* __restrict__ out_stk) {
    int b = blockIdx.x, d = threadIdx.x;
    float s = 0.f;
#pragma unroll
    for (int p = 0; p < 8; p++) s += part2[((long long)b * 8 + p) * D_ + d];
    stk[b * D_ + d] = s;
    out_stk[b * D_ + d] = s;
}

__global__ void ln_modrelu_k(const float* __restrict__ gated, const float* __restrict__ stk,
                             const float* __restrict__ lg, const float* __restrict__ lb,
                             const float* __restrict__ ib, const float* __restrict__ mb,
                             __half* __restrict__ Y16) {
    int tkn = blockIdx.x;
    int b = tkn >> 9;
    int d = threadIdx.x;
    int wid = d >> 5, lane = d & 31;
    __shared__ float ws1[8], ws2[8];
    float x = gated[(long long)tkn * D_ + d] + stk[b * D_ + d];
    float s1 = x, s2 = x * x;
#pragma unroll
    for (int off = 16; off > 0; off >>= 1) {
        s1 += __shfl_xor_sync(0xffffffffu, s1, off);
        s2 += __shfl_xor_sync(0xffffffffu, s2, off);
    }
    if (lane == 0) { ws1[wid] = s1; ws2[wid] = s2; }
    __syncthreads();
    float t1 = 0.f, t2 = 0.f;
#pragma unroll
    for (int i = 0; i < 8; i++) { t1 += ws1[i]; t2 += ws2[i]; }
    float mu = t1 * (1.f / 256.f);
    float var = t2 * (1.f / 256.f) - mu * mu;
    float nr = (x - mu) * rsqrtf(var + 1e-5f) * lg[d] + lb[d];
    float ni = ib[d];
    float mag = sqrtf(nr * nr + ni * ni);
    float sc = fmaxf(mag + mb[d], 0.f) / (mag + 1e-6f);
    Y16[(long long)tkn * D_ + d] = __float2half(nr * sc);
}

// ---------------- host launch ----------------
extern "C" void kernel_launch(void* const* d_in, const int* in_sizes, int n_in,
                              void* d_out, int out_size) {
    const int*   tokens = (const int*)d_in[0];
    const float* context = (const float*)d_in[1];
    const float* emb = (const float*)d_in[2];
    const float* awr = (const float*)d_in[3];
    const float* awi = (const float*)d_in[4];
    const float* abr = (const float*)d_in[5];
    const float* abi = (const float*)d_in[6];
    const float* vqe = (const float*)d_in[7];
    const float* gw  = (const float*)d_in[8];
    const float* gb  = (const float*)d_in[9];
    const float* lrg = (const float*)d_in[10];
    const float* lrb = (const float*)d_in[11];
    const float* lib = (const float*)d_in[13];
    const float* mrb = (const float*)d_in[14];
    const float* hw  = (const float*)d_in[15];
    const float* hb  = (const float*)d_in[16];
    float* out = (float*)d_out;

    float* S; cudaGetSymbolAddress((void**)&S, d_scratch);
    __nv_bfloat16* BF; cudaGetSymbolAddress((void**)&BF, d_bf);
    __half* HF; cudaGetSymbolAddress((void**)&HF, d_hf);
    int* idxb; cudaGetSymbolAddress((void**)&idxb, d_idxbuf);

    cudaFuncSetAttribute(gemmS<true>,  cudaFuncAttributeMaxDynamicSharedMemorySize, GS_SMEM);
    cudaFuncSetAttribute(gemmS<false>, cudaFuncAttributeMaxDynamicSharedMemorySize, GS_SMEM);
    cudaFuncSetAttribute(gemm1<0>, cudaFuncAttributeMaxDynamicSharedMemorySize, G1_SMEM);
    cudaFuncSetAttribute(gemm1<1>, cudaFuncAttributeMaxDynamicSharedMemorySize, G1_SMEM);
    cudaFuncSetAttribute(attn_mma, cudaFuncAttributeMaxDynamicSharedMemorySize, ATT_SMEM);

    float* DOT   = S + OFF_DOT;
    float* GT    = S + OFF_GATED;
    float* G     = S + OFF_G;
    float* Cg    = S + OFF_CG;
    float* wev   = S + OFF_WEV;
    float* wct   = S + OFF_WCT;
    float* stk   = S + OFF_STK;
    float* en    = S + OFF_EN;
    float* part  = S + OFF_PART;
    float* bqkv  = S + OFF_BQKV;
    float* bzr   = S + OFF_BZR;
    float* part2 = S + OFF_PART2;

    __nv_bfloat16* XBF  = BF + BF_X;
    __nv_bfloat16* WQBF = BF + BF_WQ;
    __nv_bfloat16* QKVB = BF + BF_QKV;
    __nv_bfloat16* APB  = BF + BF_AP;
    __nv_bfloat16* WZBF = BF + BF_WZ;

    __half* HW16 = HF + HF_HW;
    __half* Y16  = HF + HF_Y;
    __half* Z16  = HF + HF_Z;
    __half* VQ16 = HF + HF_VQ;

    prep_all_k<<<22920, 256>>>(abr, abi, gw, vqe, awr, awi, hw, tokens, emb,
                               bqkv, bzr, en, wev, wct,
                               WQBF, WZBF, VQ16, HW16, XBF);

    // QKV GEMM -> bf16 packed QKV
    gemm1<0><<<dim3(1536 / 128, BL_ / 128), 256, G1_SMEM>>>(
        XBF, WQBF, bqkv, QKVB, nullptr, 1536, 256);

    // flash attention
    attn_mma<<<B_ * H_ * 4, 256, ATT_SMEM>>>(QKVB, APB);

    // out clinear -> Z16 fp16 only
    gemm1<1><<<dim3(256 / 128, BL_ / 128), 256, G1_SMEM>>>(
        APB, WZBF, bzr, nullptr, Z16, 256, 512);

    // VQ dot + argmin + loss
    gemmS<false><<<dim3(1, BL_ / 256), 256, GS_SMEM>>>(
        Z16, VQ16, nullptr, DOT, KC_, 256);
    vq_argmin_k<<<BL_, 128>>>(DOT, en, Z16, vqe, idxb, part);
    vq_reduce_k<<<1, 256>>>(part, out + BLV_);

    // gate tables
    gemm_nt<false><<<dim3(2, 1), 256>>>(vqe, wev, nullptr, G, KC_, D_, D_);
    gemm_nt<true><<<dim3(2, 1), 256>>>(context, wct, gb, Cg, B_, D_, D_);

    // fused gate+stack, final reduce, layernorm+modrelu
    gate_stack_k<<<dim3(B_, 8), 256>>>(G, Cg, idxb, GT, part2);
    stack_fin_k<<<B_, D_>>>(part2, stk, out + BLV_ + 1);
    ln_modrelu_k<<<BL_, D_>>>(GT, stk, lrg, lrb, lib, mrb, Y16);

    // head GEMM (fp16): logits
    gemmS<true><<<dim3(V_ / 128, BL_ / 256), 256, GS_SMEM>>>(
        Y16, HW16, hb, out, V_, 256);
}